// round 4
// baseline (speedup 1.0000x reference)
#include <cuda_runtime.h>
#include <cuda_bf16.h>
#include <math.h>
#include <stdint.h>

#define HIDDEN 1536
#define NHEADS 12
#define HDIM 128
#define MLPH 6144
#define TXT 256
#define LX 4352
#define NC 20
#define LC 4116
#define NROWS 4372          // LX + NC
#define W1OUT 10752         // 3*HIDDEN + MLPH
#define CCW 7680            // HIDDEN + MLPH

typedef __nv_bfloat16 bf16;

// ---------------- scratch (static device globals; no runtime allocation) ---
static __device__ float g_mod[3 * HIDDEN];
static __device__ bf16  g_xmh[(size_t)NROWS * HIDDEN];
static __device__ bf16  g_xml[(size_t)NROWS * HIDDEN];
static __device__ bf16  g_w1h[(size_t)W1OUT * HIDDEN];
static __device__ bf16  g_w1l[(size_t)W1OUT * HIDDEN];
static __device__ bf16  g_w2h[(size_t)HIDDEN * CCW];
static __device__ bf16  g_w2l[(size_t)HIDDEN * CCW];
static __device__ float g_h[(size_t)NROWS * W1OUT];
static __device__ bf16  g_q1h[(size_t)NHEADS * LX * HDIM];
static __device__ bf16  g_q1l[(size_t)NHEADS * LX * HDIM];
static __device__ bf16  g_k1h[(size_t)NHEADS * LX * HDIM];
static __device__ bf16  g_k1l[(size_t)NHEADS * LX * HDIM];
static __device__ bf16  g_vt1h[(size_t)NHEADS * HDIM * LX];
static __device__ bf16  g_vt1l[(size_t)NHEADS * HDIM * LX];
static __device__ float g_q2[(size_t)NHEADS * NC * HDIM];
static __device__ float g_k2[(size_t)NHEADS * LC * HDIM];
static __device__ float g_vt2[(size_t)NHEADS * HDIM * LC];
static __device__ float g_s1[(size_t)NHEADS * LX * LX];   // logits; split in place
static __device__ float g_s2[(size_t)NHEADS * NC * LC];
static __device__ bf16  g_cch[(size_t)NROWS * CCW];
static __device__ bf16  g_ccl[(size_t)NROWS * CCW];
static __device__ float g_out[(size_t)NROWS * HIDDEN];

// ---------------- reductions ----------------------------------------------
__device__ __forceinline__ float warp_sum(float v) {
    #pragma unroll
    for (int o = 16; o > 0; o >>= 1) v += __shfl_xor_sync(0xffffffffu, v, o);
    return v;
}
__device__ __forceinline__ float warp_max(float v) {
    #pragma unroll
    for (int o = 16; o > 0; o >>= 1) v = fmaxf(v, __shfl_xor_sync(0xffffffffu, v, o));
    return v;
}
template <int NT>
__device__ __forceinline__ float block_sum(float v, float* sbuf) {
    v = warp_sum(v);
    int lane = threadIdx.x & 31, w = threadIdx.x >> 5;
    if (lane == 0) sbuf[w] = v;
    __syncthreads();
    if (threadIdx.x < 32) {
        float x = (threadIdx.x < NT / 32) ? sbuf[threadIdx.x] : 0.f;
        x = warp_sum(x);
        if (threadIdx.x == 0) sbuf[0] = x;
    }
    __syncthreads();
    float r = sbuf[0];
    __syncthreads();
    return r;
}
template <int NT>
__device__ __forceinline__ float block_max(float v, float* sbuf) {
    v = warp_max(v);
    int lane = threadIdx.x & 31, w = threadIdx.x >> 5;
    if (lane == 0) sbuf[w] = v;
    __syncthreads();
    if (threadIdx.x < 32) {
        float x = (threadIdx.x < NT / 32) ? sbuf[threadIdx.x] : -1e30f;
        x = warp_max(x);
        if (threadIdx.x == 0) sbuf[0] = x;
    }
    __syncthreads();
    float r = sbuf[0];
    __syncthreads();
    return r;
}

// ---------------- split helpers --------------------------------------------
__device__ __forceinline__ void split1(float v, bf16& h, bf16& l) {
    h = __float2bfloat16(v);
    l = __float2bfloat16(v - __bfloat162float(h));
}
__device__ __forceinline__ void split4(float4 v, uint2& h, uint2& l) {
    bf16 h0, h1, h2, h3, l0, l1, l2, l3;
    split1(v.x, h0, l0); split1(v.y, h1, l1);
    split1(v.z, h2, l2); split1(v.w, h3, l3);
    __nv_bfloat162 ph0(h0, h1), ph1(h2, h3), pl0(l0, l1), pl1(l2, l3);
    h.x = *reinterpret_cast<uint32_t*>(&ph0);
    h.y = *reinterpret_cast<uint32_t*>(&ph1);
    l.x = *reinterpret_cast<uint32_t*>(&pl0);
    l.y = *reinterpret_cast<uint32_t*>(&pl1);
}

// ======================= HMMA helpers ======================================
__device__ __forceinline__ uint32_t smem_u32(const void* p) {
    uint32_t a;
    asm("{ .reg .u64 t; cvta.to.shared.u64 t, %1; cvt.u32.u64 %0, t; }"
        : "=r"(a) : "l"(p));
    return a;
}
__device__ __forceinline__ void ldsm4(uint32_t* r, uint32_t addr) {
    asm volatile("ldmatrix.sync.aligned.m8n8.x4.shared.b16 {%0,%1,%2,%3}, [%4];"
                 : "=r"(r[0]), "=r"(r[1]), "=r"(r[2]), "=r"(r[3]) : "r"(addr));
}
__device__ __forceinline__ void mma_bf16(float* c, const uint32_t* a,
                                         uint32_t b0, uint32_t b1) {
    asm volatile(
        "mma.sync.aligned.m16n8k16.row.col.f32.bf16.bf16.f32 "
        "{%0,%1,%2,%3}, {%4,%5,%6,%7}, {%8,%9}, {%0,%1,%2,%3};"
        : "+f"(c[0]), "+f"(c[1]), "+f"(c[2]), "+f"(c[3])
        : "r"(a[0]), "r"(a[1]), "r"(a[2]), "r"(a[3]), "r"(b0), "r"(b1));
}
__device__ __forceinline__ void cp_async16(uint32_t dst, const void* src, int sz) {
    asm volatile("cp.async.cg.shared.global [%0], [%1], 16, %2;"
                 :: "r"(dst), "l"(src), "r"(sz) : "memory");
}
__device__ __forceinline__ void cp_commit() {
    asm volatile("cp.async.commit_group;" ::: "memory");
}
__device__ __forceinline__ void cp_wait2() {
    asm volatile("cp.async.wait_group 2;" ::: "memory");
}

// smem: per stage 4 tiles (Ah, Al, Bh, Bl): 128 rows x 32 bf16, row stride 80 B
#define SPB      80
#define T_BYTES  (128 * SPB)          // 10240
#define STAGE_B  (4 * T_BYTES)        // 40960
#define NSTAGE   4
#define HG_SMEM  (NSTAGE * STAGE_B)   // 163840

// ======== split-bf16 HMMA GEMM: C = alpha * A@B^T + bias ===================
// Operands pre-split into bf16 hi/lo planes. A:[M,K] lda, B:[N,K] ldb.
// outmode 0: C fp32 (ldc).  outmode 1: Ch/Cl bf16 planes (ldc).
// Requires K%32==0, N%128==0; M ragged OK. Batched via blockIdx.z strides.
__global__ void __launch_bounds__(256, 1) gemm_bf(
    const bf16* __restrict__ Ah, const bf16* __restrict__ Al, int lda, long long sA,
    const bf16* __restrict__ Bh, const bf16* __restrict__ Bl, int ldb, long long sB,
    float* __restrict__ C, bf16* __restrict__ Ch, bf16* __restrict__ Cl,
    int ldc, long long sC,
    int M, int N, int K, float alpha, const float* __restrict__ bias, int outmode)
{
    extern __shared__ char smem[];
    uint32_t sbase = smem_u32(smem);
    int tid = threadIdx.x, wid = tid >> 5, lane = tid & 31;
    int bz = blockIdx.z;
    Ah += (size_t)sA * bz; Al += (size_t)sA * bz;
    Bh += (size_t)sB * bz; Bl += (size_t)sB * bz;
    if (outmode == 0) C += (size_t)sC * bz;
    else { Ch += (size_t)sC * bz; Cl += (size_t)sC * bz; }
    int m0 = blockIdx.y * 128, n0 = blockIdx.x * 128;

    int warp_m = wid & 3;          // 4 warps along M (32 rows each)
    int warp_n = wid >> 2;         // 2 warps along N (64 cols each)
    int lrow = lane & 15, lhalf = lane >> 4;

    uint32_t a_off[2], b_off[4];
    #pragma unroll
    for (int i = 0; i < 2; ++i)
        a_off[i] = (uint32_t)((warp_m * 32 + i * 16 + lrow) * SPB + lhalf * 16);
    #pragma unroll
    for (int g = 0; g < 4; ++g)
        b_off[g] = (uint32_t)((warp_n * 64 + g * 16 + lrow) * SPB + lhalf * 16);

    float acc[2][8][4];
    #pragma unroll
    for (int i = 0; i < 2; ++i)
        #pragma unroll
        for (int j = 0; j < 8; ++j)
            #pragma unroll
            for (int t = 0; t < 4; ++t) acc[i][j][t] = 0.f;

    int nch = K >> 5;

    // cp.async producer: thread handles 8x 16B units (2048 units/stage)
    auto issue = [&](int c) {
        if (c < nch) {
            int kc = c << 5;
            uint32_t sb = sbase + (uint32_t)(c % NSTAGE) * STAGE_B;
            #pragma unroll
            for (int u8 = 0; u8 < 8; ++u8) {
                int u = tid + 256 * u8;
                int tile = u >> 9;              // compile-time per u8 pair
                int r = (u >> 2) & 127;
                int c16 = u & 3;
                uint32_t dst = sb + (uint32_t)(tile * T_BYTES + r * SPB + c16 * 16);
                if (tile == 0) {
                    int sz = (m0 + r < M) ? 16 : 0;
                    cp_async16(dst, Ah + (size_t)(m0 + r) * lda + kc + c16 * 8, sz);
                } else if (tile == 1) {
                    int sz = (m0 + r < M) ? 16 : 0;
                    cp_async16(dst, Al + (size_t)(m0 + r) * lda + kc + c16 * 8, sz);
                } else if (tile == 2) {
                    cp_async16(dst, Bh + (size_t)(n0 + r) * ldb + kc + c16 * 8, 16);
                } else {
                    cp_async16(dst, Bl + (size_t)(n0 + r) * ldb + kc + c16 * 8, 16);
                }
            }
        }
        cp_commit();
    };

    issue(0); issue(1); issue(2);

    for (int c = 0; c < nch; ++c) {
        cp_wait2();
        __syncthreads();
        issue(c + NSTAGE - 1);
        uint32_t sb = sbase + (uint32_t)(c % NSTAGE) * STAGE_B;
        #pragma unroll
        for (int k16 = 0; k16 < 2; ++k16) {
            uint32_t koff = (uint32_t)(k16 * 32);
            uint32_t ah[2][4], al[2][4], bh[4][4], bl[4][4];
            #pragma unroll
            for (int i = 0; i < 2; ++i) {
                ldsm4(ah[i], sb + 0 * T_BYTES + a_off[i] + koff);
                ldsm4(al[i], sb + 1 * T_BYTES + a_off[i] + koff);
            }
            #pragma unroll
            for (int g = 0; g < 4; ++g) {
                ldsm4(bh[g], sb + 2 * T_BYTES + b_off[g] + koff);
                ldsm4(bl[g], sb + 3 * T_BYTES + b_off[g] + koff);
            }
            // 3 passes of 16 independent MMAs (hi*hi, lo*hi, hi*lo)
            #pragma unroll
            for (int i = 0; i < 2; ++i)
                #pragma unroll
                for (int j = 0; j < 8; ++j) {
                    int g = j >> 1, sI = j & 1;
                    mma_bf16(acc[i][j], ah[i], bh[g][sI], bh[g][sI + 2]);
                }
            #pragma unroll
            for (int i = 0; i < 2; ++i)
                #pragma unroll
                for (int j = 0; j < 8; ++j) {
                    int g = j >> 1, sI = j & 1;
                    mma_bf16(acc[i][j], al[i], bh[g][sI], bh[g][sI + 2]);
                }
            #pragma unroll
            for (int i = 0; i < 2; ++i)
                #pragma unroll
                for (int j = 0; j < 8; ++j) {
                    int g = j >> 1, sI = j & 1;
                    mma_bf16(acc[i][j], ah[i], bl[g][sI], bl[g][sI + 2]);
                }
        }
    }

    // ---- epilogue ----
    int trow = lane >> 2, tc2 = (lane & 3) * 2;
    #pragma unroll
    for (int i = 0; i < 2; ++i) {
        int mbase = m0 + warp_m * 32 + i * 16 + trow;
        #pragma unroll
        for (int half = 0; half < 2; ++half) {
            int m = mbase + half * 8;
            if (m >= M) continue;
            #pragma unroll
            for (int j = 0; j < 8; ++j) {
                int n = n0 + warp_n * 64 + j * 8 + tc2;
                float vx = alpha * acc[i][j][half * 2 + 0];
                float vy = alpha * acc[i][j][half * 2 + 1];
                if (bias) { vx += bias[n]; vy += bias[n + 1]; }
                if (outmode == 0) {
                    float2 v = make_float2(vx, vy);
                    *reinterpret_cast<float2*>(C + (size_t)m * ldc + n) = v;
                } else {
                    bf16 hx, lx, hy, ly;
                    split1(vx, hx, lx); split1(vy, hy, ly);
                    __nv_bfloat162 hv(hx, hy), lv(lx, ly);
                    *reinterpret_cast<__nv_bfloat162*>(Ch + (size_t)m * ldc + n) = hv;
                    *reinterpret_cast<__nv_bfloat162*>(Cl + (size_t)m * ldc + n) = lv;
                }
            }
        }
    }
}

// ---------------- SIMT GEMM for tiny block-2 attention ---------------------
// splitout: 0 -> C fp32; 1 -> Ch/Cl bf16 planes
__global__ void __launch_bounds__(256) sgemm_abt(
    const float* __restrict__ A, int lda, long long sA,
    const float* __restrict__ B, int ldb, long long sB,
    float* __restrict__ C, bf16* __restrict__ Ch, bf16* __restrict__ Cl,
    int ldc, long long sC,
    int M, int N, int K, float alpha, int splitout)
{
    __shared__ float As[8][128];
    __shared__ float Bs[8][128];
    int bz = blockIdx.z;
    A += (size_t)sA * bz;
    B += (size_t)sB * bz;
    if (splitout) { Ch += (size_t)sC * bz; Cl += (size_t)sC * bz; }
    else C += (size_t)sC * bz;
    int m0 = blockIdx.y * 128;
    int n0 = blockIdx.x * 128;
    int tid = threadIdx.x;
    int tx = tid & 15, ty = tid >> 4;
    int lrow = tid >> 1;
    int lcol = (tid & 1) * 4;

    float acc[8][8];
    #pragma unroll
    for (int i = 0; i < 8; i++)
        #pragma unroll
        for (int j = 0; j < 8; j++) acc[i][j] = 0.f;

    for (int k0 = 0; k0 < K; k0 += 8) {
        float4 av = make_float4(0.f, 0.f, 0.f, 0.f);
        float4 bv = make_float4(0.f, 0.f, 0.f, 0.f);
        if (m0 + lrow < M && k0 + lcol < K)
            av = *reinterpret_cast<const float4*>(A + (size_t)(m0 + lrow) * lda + k0 + lcol);
        if (n0 + lrow < N && k0 + lcol < K)
            bv = *reinterpret_cast<const float4*>(B + (size_t)(n0 + lrow) * ldb + k0 + lcol);
        As[lcol + 0][lrow] = av.x; As[lcol + 1][lrow] = av.y;
        As[lcol + 2][lrow] = av.z; As[lcol + 3][lrow] = av.w;
        Bs[lcol + 0][lrow] = bv.x; Bs[lcol + 1][lrow] = bv.y;
        Bs[lcol + 2][lrow] = bv.z; Bs[lcol + 3][lrow] = bv.w;
        __syncthreads();
        #pragma unroll
        for (int k = 0; k < 8; k++) {
            float ra[8], rb[8];
            #pragma unroll
            for (int i = 0; i < 8; i++) ra[i] = As[k][ty + 16 * i];
            #pragma unroll
            for (int j = 0; j < 8; j++) rb[j] = Bs[k][tx + 16 * j];
            #pragma unroll
            for (int i = 0; i < 8; i++)
                #pragma unroll
                for (int j = 0; j < 8; j++)
                    acc[i][j] = fmaf(ra[i], rb[j], acc[i][j]);
        }
        __syncthreads();
    }

    #pragma unroll
    for (int i = 0; i < 8; i++) {
        int m = m0 + ty + 16 * i;
        if (m >= M) continue;
        #pragma unroll
        for (int j = 0; j < 8; j++) {
            int n = n0 + tx + 16 * j;
            if (n >= N) continue;
            float v = alpha * acc[i][j];
            if (splitout) {
                bf16 h, l;
                split1(v, h, l);
                Ch[(size_t)m * ldc + n] = h;
                Cl[(size_t)m * ldc + n] = l;
            } else {
                C[(size_t)m * ldc + n] = v;
            }
        }
    }
}

// ---------------- split-convert fp32 -> bf16 hi/lo planes ------------------
__global__ void __launch_bounds__(256) convert_split(
    const float4* __restrict__ src, uint2* __restrict__ h, uint2* __restrict__ l,
    int n4)
{
    int idx = blockIdx.x * 256 + threadIdx.x;
    if (idx >= n4) return;
    uint2 hh, ll;
    split4(src[idx], hh, ll);
    h[idx] = hh;
    l[idx] = ll;
}

// ---------------- modulation: m = silu(vec) @ mod_w^T + mod_b --------------
__global__ void __launch_bounds__(128) mod_kernel(
    const float* __restrict__ vec, const float* __restrict__ mod_w,
    const float* __restrict__ mod_b)
{
    int n = blockIdx.x * 4 + (threadIdx.x >> 5);
    if (n >= 3 * HIDDEN) return;
    int lane = threadIdx.x & 31;
    const float* wrow = mod_w + (size_t)n * HIDDEN;
    float acc = 0.f;
    for (int k = lane; k < HIDDEN; k += 32) {
        float xv = vec[k];
        float s = xv / (1.f + __expf(-xv));
        acc = fmaf(s, wrow[k], acc);
    }
    acc = warp_sum(acc);
    if (lane == 0) g_mod[n] = acc + mod_b[n];
}

// ---------------- layernorm + modulate -> split planes ---------------------
__global__ void __launch_bounds__(256) ln_mod_kernel(
    const float* __restrict__ x, const float* __restrict__ concepts)
{
    __shared__ float sbuf[8];
    int row = blockIdx.x;
    const float* src = (row < LX) ? (x + (size_t)row * HIDDEN)
                                  : (concepts + (size_t)(row - LX) * HIDDEN);
    int tid = threadIdx.x;
    float v[6];
    float s = 0.f;
    #pragma unroll
    for (int i = 0; i < 6; i++) { v[i] = src[tid + 256 * i]; s += v[i]; }
    s = block_sum<256>(s, sbuf);
    float mu = s * (1.0f / 1536.0f);
    float s2 = 0.f;
    #pragma unroll
    for (int i = 0; i < 6; i++) { float d = v[i] - mu; s2 = fmaf(d, d, s2); }
    s2 = block_sum<256>(s2, sbuf);
    float rstd = rsqrtf(s2 * (1.0f / 1536.0f) + 1e-6f);
    #pragma unroll
    for (int i = 0; i < 6; i++) {
        int j = tid + 256 * i;
        float val = (1.f + g_mod[HIDDEN + j]) * ((v[i] - mu) * rstd) + g_mod[j];
        bf16 h, l;
        split1(val, h, l);
        g_xmh[(size_t)row * HIDDEN + j] = h;
        g_xml[(size_t)row * HIDDEN + j] = l;
    }
}

// ---------------- RoPE helper (pair exchange via shfl) ---------------------
__device__ __forceinline__ float rope_pair(float a, const float* __restrict__ petab,
                                           int tok, int d)
{
    float b = __shfl_xor_sync(0xffffffffu, a, 1);
    int i = d >> 1;
    const float* p = petab + ((size_t)tok * 64 + i) * 4;
    if ((d & 1) == 0) return fmaf(p[0], a, p[1] * b);
    else              return fmaf(p[2], b, p[3] * a);
}

// ---------------- attention prep for x tokens ------------------------------
__global__ void __launch_bounds__(128) attn_prep1(
    const float* __restrict__ pe, const float* __restrict__ cpe,
    const float* __restrict__ q_scale, const float* __restrict__ k_scale)
{
    __shared__ float sbuf[4];
    int t = blockIdx.x, h = blockIdx.y, d = threadIdx.x;
    const float* hrow = g_h + (size_t)t * W1OUT;
    float q = hrow[h * HDIM + d];
    float k = hrow[HIDDEN + h * HDIM + d];
    float v = hrow[2 * HIDDEN + h * HDIM + d];
    float msq = block_sum<128>(q * q, sbuf) * (1.f / 128.f);
    float msk = block_sum<128>(k * k, sbuf) * (1.f / 128.f);
    float qn = q * rsqrtf(msq + 1e-6f) * q_scale[d];
    float kn = k * rsqrtf(msk + 1e-6f) * k_scale[d];
    float qr = rope_pair(qn, pe, t, d);
    float kr = rope_pair(kn, pe, t, d);
    bf16 hh, ll;
    size_t qi = ((size_t)h * LX + t) * HDIM + d;
    split1(qr, hh, ll); g_q1h[qi] = hh; g_q1l[qi] = ll;
    split1(kr, hh, ll); g_k1h[qi] = hh; g_k1l[qi] = ll;
    size_t vi = ((size_t)h * HDIM + d) * LX + t;
    split1(v, hh, ll); g_vt1h[vi] = hh; g_vt1l[vi] = ll;
    if (t >= TXT) {
        int j = NC + (t - TXT);
        g_k2[((size_t)h * LC + j) * HDIM + d] = rope_pair(kn, cpe, j, d);
        g_vt2[((size_t)h * HDIM + d) * LC + j] = v;
    }
}

// ---------------- attention prep for concept tokens ------------------------
__global__ void __launch_bounds__(128) attn_prep2(
    const float* __restrict__ cpe,
    const float* __restrict__ q_scale, const float* __restrict__ k_scale)
{
    __shared__ float sbuf[4];
    int i = blockIdx.x, h = blockIdx.y, d = threadIdx.x;
    const float* hrow = g_h + (size_t)(LX + i) * W1OUT;
    float q = hrow[h * HDIM + d];
    float k = hrow[HIDDEN + h * HDIM + d];
    float v = hrow[2 * HIDDEN + h * HDIM + d];
    float msq = block_sum<128>(q * q, sbuf) * (1.f / 128.f);
    float msk = block_sum<128>(k * k, sbuf) * (1.f / 128.f);
    float qn = q * rsqrtf(msq + 1e-6f) * q_scale[d];
    float kn = k * rsqrtf(msk + 1e-6f) * k_scale[d];
    g_q2[((size_t)h * NC + i) * HDIM + d] = rope_pair(qn, cpe, i, d);
    g_k2[((size_t)h * LC + i) * HDIM + d] = rope_pair(kn, cpe, i, d);
    g_vt2[((size_t)h * HDIM + d) * LC + i] = v;
}

// ---------------- row softmax; optional in-place split to bf16 planes ------
// do_split: writes hi plane at bf16[0..ncol), lo plane at bf16[ncol..2*ncol)
// over the same fp32 row storage (4 bytes/elem total, rows independent).
__global__ void __launch_bounds__(256) softmax_rows(float* __restrict__ S, int ncol,
                                                    int do_split)
{
    __shared__ float sbuf[8];
    float* row = S + (size_t)blockIdx.x * ncol;
    int tid = threadIdx.x;
    float v[17];
    float mx = -1e30f;
    #pragma unroll
    for (int i = 0; i < 17; i++) {
        int c = tid + 256 * i;
        v[i] = (c < ncol) ? row[c] : -1e30f;
        mx = fmaxf(mx, v[i]);
    }
    mx = block_max<256>(mx, sbuf);
    float s = 0.f;
    #pragma unroll
    for (int i = 0; i < 17; i++) { v[i] = __expf(v[i] - mx); s += v[i]; }
    s = block_sum<256>(s, sbuf);   // barrier: all reads complete before writes
    float inv = 1.f / s;
    if (do_split) {
        bf16* rowb = reinterpret_cast<bf16*>(row);
        #pragma unroll
        for (int i = 0; i < 17; i++) {
            int c = tid + 256 * i;
            if (c < ncol) {
                bf16 h, l;
                split1(v[i] * inv, h, l);
                rowb[c] = h;
                rowb[ncol + c] = l;
            }
        }
    } else {
        #pragma unroll
        for (int i = 0; i < 17; i++) {
            int c = tid + 256 * i;
            if (c < ncol) row[c] = v[i] * inv;
        }
    }
}

// ---------------- gelu(tanh) on mlp part into cc planes --------------------
__global__ void __launch_bounds__(256) gelu_kernel()
{
    size_t idx = (size_t)blockIdx.x * 256 + threadIdx.x;
    if (idx >= (size_t)NROWS * MLPH) return;
    size_t r = idx / MLPH;
    int c = (int)(idx % MLPH);
    float xv = g_h[r * W1OUT + 3 * HIDDEN + c];
    float inner = 0.7978845608028654f * fmaf(0.044715f * xv * xv, xv, xv);
    float gv = 0.5f * xv * (1.f + tanhf(inner));
    bf16 h, l;
    split1(gv, h, l);
    g_cch[r * CCW + HIDDEN + c] = h;
    g_ccl[r * CCW + HIDDEN + c] = l;
}

// ---------------- residual: out = base + gate * block_out ------------------
__global__ void __launch_bounds__(256) final_kernel(
    const float* __restrict__ x, const float* __restrict__ concepts,
    float* __restrict__ out)
{
    size_t idx = (size_t)blockIdx.x * 256 + threadIdx.x;
    if (idx >= (size_t)NROWS * HIDDEN) return;
    int c = (int)(idx % HIDDEN);
    size_t r = idx / HIDDEN;
    float base = (r < LX) ? x[idx] : concepts[idx - (size_t)LX * HIDDEN];
    out[idx] = fmaf(g_mod[2 * HIDDEN + c], g_out[idx], base);
}

// ---------------------------------------------------------------------------
extern "C" void kernel_launch(void* const* d_in, const int* in_sizes, int n_in,
                              void* d_out, int out_size)
{
    const float* x        = (const float*)d_in[0];
    const float* concepts = (const float*)d_in[1];
    const float* vec      = (const float*)d_in[2];
    const float* pe       = (const float*)d_in[3];
    const float* cpe      = (const float*)d_in[4];
    const float* w1       = (const float*)d_in[5];
    const float* b1       = (const float*)d_in[6];
    const float* w2       = (const float*)d_in[7];
    const float* b2       = (const float*)d_in[8];
    const float* q_scale  = (const float*)d_in[9];
    const float* k_scale  = (const float*)d_in[10];
    const float* mod_w    = (const float*)d_in[11];
    const float* mod_b    = (const float*)d_in[12];
    float* out = (float*)d_out;

    void* p;
    cudaGetSymbolAddress(&p, g_xmh);  bf16* xmh = (bf16*)p;
    cudaGetSymbolAddress(&p, g_xml);  bf16* xml = (bf16*)p;
    cudaGetSymbolAddress(&p, g_w1h);  bf16* w1h = (bf16*)p;
    cudaGetSymbolAddress(&p, g_w1l);  bf16* w1l = (bf16*)p;
    cudaGetSymbolAddress(&p, g_w2h);  bf16* w2h = (bf16*)p;
    cudaGetSymbolAddress(&p, g_w2l);  bf16* w2l = (bf16*)p;
    cudaGetSymbolAddress(&p, g_h);    float* hbuf = (float*)p;
    cudaGetSymbolAddress(&p, g_q1h);  bf16* q1h = (bf16*)p;
    cudaGetSymbolAddress(&p, g_q1l);  bf16* q1l = (bf16*)p;
    cudaGetSymbolAddress(&p, g_k1h);  bf16* k1h = (bf16*)p;
    cudaGetSymbolAddress(&p, g_k1l);  bf16* k1l = (bf16*)p;
    cudaGetSymbolAddress(&p, g_vt1h); bf16* vt1h = (bf16*)p;
    cudaGetSymbolAddress(&p, g_vt1l); bf16* vt1l = (bf16*)p;
    cudaGetSymbolAddress(&p, g_q2);   float* q2b  = (float*)p;
    cudaGetSymbolAddress(&p, g_k2);   float* k2b  = (float*)p;
    cudaGetSymbolAddress(&p, g_vt2);  float* vt2b = (float*)p;
    cudaGetSymbolAddress(&p, g_s1);   float* s1b  = (float*)p;
    cudaGetSymbolAddress(&p, g_s2);   float* s2b  = (float*)p;
    cudaGetSymbolAddress(&p, g_cch);  bf16* cch = (bf16*)p;
    cudaGetSymbolAddress(&p, g_ccl);  bf16* ccl = (bf16*)p;
    cudaGetSymbolAddress(&p, g_out);  float* outb = (float*)p;

    cudaFuncSetAttribute(gemm_bf, cudaFuncAttributeMaxDynamicSharedMemorySize,
                         HG_SMEM);

    const float scl = 0.08838834764831845f;  // 1/sqrt(128)

    // modulation vector (shift | scale | gate)
    mod_kernel<<<(3 * HIDDEN + 3) / 4, 128>>>(vec, mod_w, mod_b);
    // weight splitting (hi/lo bf16 planes)
    {
        int n4 = (W1OUT * HIDDEN) / 4;
        convert_split<<<(n4 + 255) / 256, 256>>>(
            (const float4*)w1, (uint2*)w1h, (uint2*)w1l, n4);
        n4 = (HIDDEN * CCW) / 4;
        convert_split<<<(n4 + 255) / 256, 256>>>(
            (const float4*)w2, (uint2*)w2h, (uint2*)w2l, n4);
    }
    // layernorm + modulate -> xm planes
    ln_mod_kernel<<<NROWS, 256>>>(x, concepts);
    // GEMM1: h = xm @ w1^T + b1
    gemm_bf<<<dim3(W1OUT / 128, (NROWS + 127) / 128, 1), 256, HG_SMEM>>>(
        xmh, xml, HIDDEN, 0, w1h, w1l, HIDDEN, 0,
        hbuf, nullptr, nullptr, W1OUT, 0,
        NROWS, W1OUT, HIDDEN, 1.f, b1, 0);
    // rmsnorm + rope -> q/k/vt planes (+ block2 fp32 arrays)
    attn_prep1<<<dim3(LX, NHEADS), 128>>>(pe, cpe, q_scale, k_scale);
    attn_prep2<<<dim3(NC, NHEADS), 128>>>(cpe, q_scale, k_scale);
    // block1 QK^T -> fp32 logits
    gemm_bf<<<dim3(LX / 128, LX / 128, NHEADS), 256, HG_SMEM>>>(
        q1h, q1l, HDIM, (long long)LX * HDIM, k1h, k1l, HDIM, (long long)LX * HDIM,
        s1b, nullptr, nullptr, LX, (long long)LX * LX,
        LX, LX, HDIM, scl, nullptr, 0);
    // softmax + in-place split to bf16 hi/lo planes
    softmax_rows<<<NHEADS * LX, 256>>>(s1b, LX, 1);
    // block1 PV: A = split S (in-place planes), B = vt planes -> cc planes
    gemm_bf<<<dim3(1, LX / 128, NHEADS), 256, HG_SMEM>>>(
        (const bf16*)s1b, (const bf16*)s1b + LX, 2 * LX, (long long)2 * LX * LX,
        vt1h, vt1l, LX, (long long)HDIM * LX,
        nullptr, cch, ccl, CCW, 128,
        LX, HDIM, LX, 1.f, nullptr, 1);
    // block2 attention (20 queries over 4116 keys) — SIMT path
    sgemm_abt<<<dim3((LC + 127) / 128, 1, NHEADS), 256>>>(
        q2b, HDIM, (long long)NC * HDIM, k2b, HDIM, (long long)LC * HDIM,
        s2b, nullptr, nullptr, LC, (long long)NC * LC,
        NC, LC, HDIM, scl, 0);
    softmax_rows<<<NHEADS * NC, 256>>>(s2b, LC, 0);
    sgemm_abt<<<dim3(1, 1, NHEADS), 256>>>(
        s2b, LC, (long long)NC * LC, vt2b, LC, (long long)HDIM * LC,
        nullptr, cch + (size_t)LX * CCW, ccl + (size_t)LX * CCW, CCW, 128,
        NC, HDIM, LC, 1.f, 1);
    // gelu on mlp half -> cc planes
    gelu_kernel<<<(unsigned)(((size_t)NROWS * MLPH + 255) / 256), 256>>>();
    // GEMM2: out = cc @ w2^T + b2
    gemm_bf<<<dim3(HIDDEN / 128, (NROWS + 127) / 128, 1), 256, HG_SMEM>>>(
        cch, ccl, CCW, 0, w2h, w2l, CCW, 0,
        outb, nullptr, nullptr, HIDDEN, 0,
        NROWS, HIDDEN, CCW, 1.f, b2, 0);
    // residual + gate
    final_kernel<<<(unsigned)(((size_t)NROWS * HIDDEN + 255) / 256), 256>>>(
        x, concepts, out);
}

// round 5
// speedup vs baseline: 1.1542x; 1.1542x over previous
#include <cuda_runtime.h>
#include <cuda_bf16.h>
#include <math.h>
#include <stdint.h>

#define HIDDEN 1536
#define NHEADS 12
#define HDIM 128
#define MLPH 6144
#define TXT 256
#define LX 4352
#define NC 20
#define LC 4116
#define NROWS 4372          // LX + NC
#define W1OUT 10752         // 3*HIDDEN + MLPH
#define CCW 7680            // HIDDEN + MLPH

typedef __nv_bfloat16 bf16;

// ---------------- scratch (static device globals; no runtime allocation) ---
static __device__ float g_mod[3 * HIDDEN];
static __device__ bf16  g_xmh[(size_t)NROWS * HIDDEN];
static __device__ bf16  g_xml[(size_t)NROWS * HIDDEN];
static __device__ bf16  g_w1h[(size_t)W1OUT * HIDDEN];
static __device__ bf16  g_w1l[(size_t)W1OUT * HIDDEN];
static __device__ bf16  g_w2h[(size_t)HIDDEN * CCW];
static __device__ bf16  g_w2l[(size_t)HIDDEN * CCW];
static __device__ float g_h[(size_t)NROWS * W1OUT];
static __device__ bf16  g_q1h[(size_t)NHEADS * LX * HDIM];
static __device__ bf16  g_q1l[(size_t)NHEADS * LX * HDIM];
static __device__ bf16  g_k1h[(size_t)NHEADS * LX * HDIM];
static __device__ bf16  g_k1l[(size_t)NHEADS * LX * HDIM];
static __device__ bf16  g_v1h[(size_t)NHEADS * LX * HDIM];
static __device__ bf16  g_v1l[(size_t)NHEADS * LX * HDIM];
static __device__ float g_q2[(size_t)NHEADS * NC * HDIM];
static __device__ float g_k2[(size_t)NHEADS * LC * HDIM];
static __device__ float g_vt2[(size_t)NHEADS * HDIM * LC];
static __device__ float g_s2[(size_t)NHEADS * NC * LC];
static __device__ bf16  g_cch[(size_t)NROWS * CCW];
static __device__ bf16  g_ccl[(size_t)NROWS * CCW];
static __device__ float g_out[(size_t)NROWS * HIDDEN];

// ---------------- reductions ----------------------------------------------
__device__ __forceinline__ float warp_sum(float v) {
    #pragma unroll
    for (int o = 16; o > 0; o >>= 1) v += __shfl_xor_sync(0xffffffffu, v, o);
    return v;
}
__device__ __forceinline__ float warp_max(float v) {
    #pragma unroll
    for (int o = 16; o > 0; o >>= 1) v = fmaxf(v, __shfl_xor_sync(0xffffffffu, v, o));
    return v;
}
template <int NT>
__device__ __forceinline__ float block_sum(float v, float* sbuf) {
    v = warp_sum(v);
    int lane = threadIdx.x & 31, w = threadIdx.x >> 5;
    if (lane == 0) sbuf[w] = v;
    __syncthreads();
    if (threadIdx.x < 32) {
        float x = (threadIdx.x < NT / 32) ? sbuf[threadIdx.x] : 0.f;
        x = warp_sum(x);
        if (threadIdx.x == 0) sbuf[0] = x;
    }
    __syncthreads();
    float r = sbuf[0];
    __syncthreads();
    return r;
}
template <int NT>
__device__ __forceinline__ float block_max(float v, float* sbuf) {
    v = warp_max(v);
    int lane = threadIdx.x & 31, w = threadIdx.x >> 5;
    if (lane == 0) sbuf[w] = v;
    __syncthreads();
    if (threadIdx.x < 32) {
        float x = (threadIdx.x < NT / 32) ? sbuf[threadIdx.x] : -1e30f;
        x = warp_max(x);
        if (threadIdx.x == 0) sbuf[0] = x;
    }
    __syncthreads();
    float r = sbuf[0];
    __syncthreads();
    return r;
}

// ---------------- split helpers --------------------------------------------
__device__ __forceinline__ void split1(float v, bf16& h, bf16& l) {
    h = __float2bfloat16(v);
    l = __float2bfloat16(v - __bfloat162float(h));
}
__device__ __forceinline__ void split2(float x, float y, uint32_t& h, uint32_t& l) {
    bf16 hx, lx, hy, ly;
    split1(x, hx, lx); split1(y, hy, ly);
    __nv_bfloat162 hh(hx, hy), ll(lx, ly);
    h = *reinterpret_cast<uint32_t*>(&hh);
    l = *reinterpret_cast<uint32_t*>(&ll);
}
__device__ __forceinline__ void split4(float4 v, uint2& h, uint2& l) {
    split2(v.x, v.y, h.x, l.x);
    split2(v.z, v.w, h.y, l.y);
}

// ======================= HMMA helpers ======================================
__device__ __forceinline__ uint32_t smem_u32(const void* p) {
    uint32_t a;
    asm("{ .reg .u64 t; cvta.to.shared.u64 t, %1; cvt.u32.u64 %0, t; }"
        : "=r"(a) : "l"(p));
    return a;
}
__device__ __forceinline__ void ldsm4(uint32_t* r, uint32_t addr) {
    asm volatile("ldmatrix.sync.aligned.m8n8.x4.shared.b16 {%0,%1,%2,%3}, [%4];"
                 : "=r"(r[0]), "=r"(r[1]), "=r"(r[2]), "=r"(r[3]) : "r"(addr));
}
__device__ __forceinline__ void ldsm4t(uint32_t* r, uint32_t addr) {
    asm volatile("ldmatrix.sync.aligned.m8n8.x4.trans.shared.b16 {%0,%1,%2,%3}, [%4];"
                 : "=r"(r[0]), "=r"(r[1]), "=r"(r[2]), "=r"(r[3]) : "r"(addr));
}
__device__ __forceinline__ void mma_bf16(float* c, const uint32_t* a,
                                         uint32_t b0, uint32_t b1) {
    asm volatile(
        "mma.sync.aligned.m16n8k16.row.col.f32.bf16.bf16.f32 "
        "{%0,%1,%2,%3}, {%4,%5,%6,%7}, {%8,%9}, {%0,%1,%2,%3};"
        : "+f"(c[0]), "+f"(c[1]), "+f"(c[2]), "+f"(c[3])
        : "r"(a[0]), "r"(a[1]), "r"(a[2]), "r"(a[3]), "r"(b0), "r"(b1));
}
__device__ __forceinline__ void cp_async16(uint32_t dst, const void* src, int sz) {
    asm volatile("cp.async.cg.shared.global [%0], [%1], 16, %2;"
                 :: "r"(dst), "l"(src), "r"(sz) : "memory");
}
__device__ __forceinline__ void cp_commit() {
    asm volatile("cp.async.commit_group;" ::: "memory");
}
__device__ __forceinline__ void cp_wait0() {
    asm volatile("cp.async.wait_group 0;" ::: "memory");
}
__device__ __forceinline__ void cp_wait1() {
    asm volatile("cp.async.wait_group 1;" ::: "memory");
}
__device__ __forceinline__ void cp_wait2() {
    asm volatile("cp.async.wait_group 2;" ::: "memory");
}

// smem: per stage 4 tiles (Ah, Al, Bh, Bl): 128 rows x 32 bf16, row stride 80 B
#define SPB      80
#define T_BYTES  (128 * SPB)          // 10240
#define STAGE_B  (4 * T_BYTES)        // 40960
#define NSTAGE   4
#define HG_SMEM  (NSTAGE * STAGE_B)   // 163840

// ======== split-bf16 HMMA GEMM: C = alpha * A@B^T + bias ===================
__global__ void __launch_bounds__(256, 1) gemm_bf(
    const bf16* __restrict__ Ah, const bf16* __restrict__ Al, int lda, long long sA,
    const bf16* __restrict__ Bh, const bf16* __restrict__ Bl, int ldb, long long sB,
    float* __restrict__ C, int ldc, long long sC,
    int M, int N, int K, float alpha, const float* __restrict__ bias)
{
    extern __shared__ char smem[];
    uint32_t sbase = smem_u32(smem);
    int tid = threadIdx.x, wid = tid >> 5, lane = tid & 31;
    int bz = blockIdx.z;
    Ah += (size_t)sA * bz; Al += (size_t)sA * bz;
    Bh += (size_t)sB * bz; Bl += (size_t)sB * bz;
    C += (size_t)sC * bz;
    int m0 = blockIdx.y * 128, n0 = blockIdx.x * 128;

    int warp_m = wid & 3;
    int warp_n = wid >> 2;
    int lrow = lane & 15, lhalf = lane >> 4;

    uint32_t a_off[2], b_off[4];
    #pragma unroll
    for (int i = 0; i < 2; ++i)
        a_off[i] = (uint32_t)((warp_m * 32 + i * 16 + lrow) * SPB + lhalf * 16);
    #pragma unroll
    for (int g = 0; g < 4; ++g)
        b_off[g] = (uint32_t)((warp_n * 64 + g * 16 + lrow) * SPB + lhalf * 16);

    float acc[2][8][4];
    #pragma unroll
    for (int i = 0; i < 2; ++i)
        #pragma unroll
        for (int j = 0; j < 8; ++j)
            #pragma unroll
            for (int t = 0; t < 4; ++t) acc[i][j][t] = 0.f;

    int nch = K >> 5;

    auto issue = [&](int c) {
        if (c < nch) {
            int kc = c << 5;
            uint32_t sb = sbase + (uint32_t)(c % NSTAGE) * STAGE_B;
            #pragma unroll
            for (int u8 = 0; u8 < 8; ++u8) {
                int u = tid + 256 * u8;
                int tile = u >> 9;
                int r = (u >> 2) & 127;
                int c16 = u & 3;
                uint32_t dst = sb + (uint32_t)(tile * T_BYTES + r * SPB + c16 * 16);
                if (tile == 0) {
                    int sz = (m0 + r < M) ? 16 : 0;
                    cp_async16(dst, Ah + (size_t)(m0 + r) * lda + kc + c16 * 8, sz);
                } else if (tile == 1) {
                    int sz = (m0 + r < M) ? 16 : 0;
                    cp_async16(dst, Al + (size_t)(m0 + r) * lda + kc + c16 * 8, sz);
                } else if (tile == 2) {
                    cp_async16(dst, Bh + (size_t)(n0 + r) * ldb + kc + c16 * 8, 16);
                } else {
                    cp_async16(dst, Bl + (size_t)(n0 + r) * ldb + kc + c16 * 8, 16);
                }
            }
        }
        cp_commit();
    };

    issue(0); issue(1); issue(2);

    for (int c = 0; c < nch; ++c) {
        cp_wait2();
        __syncthreads();
        issue(c + NSTAGE - 1);
        uint32_t sb = sbase + (uint32_t)(c % NSTAGE) * STAGE_B;
        #pragma unroll
        for (int k16 = 0; k16 < 2; ++k16) {
            uint32_t koff = (uint32_t)(k16 * 32);
            uint32_t ah[2][4], al[2][4], bh[4][4], bl[4][4];
            #pragma unroll
            for (int i = 0; i < 2; ++i) {
                ldsm4(ah[i], sb + 0 * T_BYTES + a_off[i] + koff);
                ldsm4(al[i], sb + 1 * T_BYTES + a_off[i] + koff);
            }
            #pragma unroll
            for (int g = 0; g < 4; ++g) {
                ldsm4(bh[g], sb + 2 * T_BYTES + b_off[g] + koff);
                ldsm4(bl[g], sb + 3 * T_BYTES + b_off[g] + koff);
            }
            #pragma unroll
            for (int i = 0; i < 2; ++i)
                #pragma unroll
                for (int j = 0; j < 8; ++j) {
                    int g = j >> 1, sI = j & 1;
                    mma_bf16(acc[i][j], ah[i], bh[g][sI], bh[g][sI + 2]);
                }
            #pragma unroll
            for (int i = 0; i < 2; ++i)
                #pragma unroll
                for (int j = 0; j < 8; ++j) {
                    int g = j >> 1, sI = j & 1;
                    mma_bf16(acc[i][j], al[i], bh[g][sI], bh[g][sI + 2]);
                }
            #pragma unroll
            for (int i = 0; i < 2; ++i)
                #pragma unroll
                for (int j = 0; j < 8; ++j) {
                    int g = j >> 1, sI = j & 1;
                    mma_bf16(acc[i][j], ah[i], bl[g][sI], bl[g][sI + 2]);
                }
        }
    }

    int trow = lane >> 2, tc2 = (lane & 3) * 2;
    #pragma unroll
    for (int i = 0; i < 2; ++i) {
        int mbase = m0 + warp_m * 32 + i * 16 + trow;
        #pragma unroll
        for (int half = 0; half < 2; ++half) {
            int m = mbase + half * 8;
            if (m >= M) continue;
            #pragma unroll
            for (int j = 0; j < 8; ++j) {
                int n = n0 + warp_n * 64 + j * 8 + tc2;
                float vx = alpha * acc[i][j][half * 2 + 0];
                float vy = alpha * acc[i][j][half * 2 + 1];
                if (bias) { vx += bias[n]; vy += bias[n + 1]; }
                *reinterpret_cast<float2*>(C + (size_t)m * ldc + n) =
                    make_float2(vx, vy);
            }
        }
    }
}

// ================= flash attention for block 1 =============================
// Q tile 128 rows (8 warps x 16), KV streamed in 64-row tiles, split-bf16
// 3-product for both QK^T and PV. O written (split) into cc planes.
#define BK 64
#define FSTR 272                       // 128*2 + 16 pad
#define FQ_PLANE (128 * FSTR)          // 34816
#define FK_PLANE (BK * FSTR)           // 17408
#define FS_OFF   (2 * FQ_PLANE)        // 69632
#define FSTAGE   (4 * FK_PLANE)        // 69632
#define FLASH_SMEM (FS_OFF + 2 * FSTAGE)  // 208896
#define NKT (LX / BK)                  // 68

__global__ void __launch_bounds__(256, 1) flash1(
    const bf16* __restrict__ Qh, const bf16* __restrict__ Ql,
    const bf16* __restrict__ Kh, const bf16* __restrict__ Kl,
    const bf16* __restrict__ Vh, const bf16* __restrict__ Vl,
    bf16* __restrict__ Och, bf16* __restrict__ Ocl)
{
    extern __shared__ char smem[];
    uint32_t sbase = smem_u32(smem);
    int tid = threadIdx.x, wid = tid >> 5, lane = tid & 31;
    int head = blockIdx.y;
    int q0 = blockIdx.x * 128;
    size_t hb = (size_t)head * LX * HDIM;
    const bf16* qp0 = Qh + hb + (size_t)q0 * HDIM;
    const bf16* qp1 = Ql + hb + (size_t)q0 * HDIM;
    const bf16* kp[4] = { Kh + hb, Kl + hb, Vh + hb, Vl + hb };

    // Q -> smem (commit group 0)
    #pragma unroll
    for (int u8 = 0; u8 < 16; ++u8) {
        int u = tid + 256 * u8;
        int pl = u >> 11, r = (u >> 4) & 127, c = u & 15;
        const bf16* src = (pl ? qp1 : qp0) + (size_t)r * HDIM + c * 8;
        cp_async16(sbase + (uint32_t)(pl * FQ_PLANE + r * FSTR + c * 16), src, 16);
    }
    cp_commit();

    auto issueKV = [&](int it) {
        int kv0 = it * BK;
        #pragma unroll
        for (int u8 = 0; u8 < 16; ++u8) {
            int u = tid + 256 * u8;
            int pl = u >> 10, r = (u >> 4) & 63, c = u & 15;
            cp_async16(sbase + (uint32_t)(FS_OFF + (it & 1) * FSTAGE +
                                          pl * FK_PLANE + r * FSTR + c * 16),
                       kp[pl] + (size_t)(kv0 + r) * HDIM + c * 8, 16);
        }
        cp_commit();
    };
    issueKV(0);
    issueKV(1);

    uint32_t a_addr = sbase + (uint32_t)((wid * 16 + (lane & 15)) * FSTR +
                                         (lane >> 4) * 16);
    uint32_t bk_rel = (uint32_t)((lane & 15) * FSTR + (lane >> 4) * 16);
    uint32_t bv_rel = (uint32_t)(((((lane >> 3) & 1) * 8) + (lane & 7)) * FSTR +
                                 ((lane >> 4) & 1) * 16);

    float accO[16][4];
    #pragma unroll
    for (int j = 0; j < 16; ++j)
        #pragma unroll
        for (int t = 0; t < 4; ++t) accO[j][t] = 0.f;
    float mrow0 = -1e30f, mrow1 = -1e30f, lsum0 = 0.f, lsum1 = 0.f;
    const float scl = 0.08838834764831845f;  // 1/sqrt(128)

    for (int it = 0; it < NKT; ++it) {
        if (it < NKT - 1) cp_wait1(); else cp_wait0();
        __syncthreads();
        uint32_t kb = sbase + FS_OFF + (uint32_t)(it & 1) * FSTAGE;

        // ---- S = Q K^T (this 64-col slab), split-bf16 3-product ----
        float s[8][4];
        #pragma unroll
        for (int j = 0; j < 8; ++j)
            #pragma unroll
            for (int t = 0; t < 4; ++t) s[j][t] = 0.f;
        #pragma unroll
        for (int ks = 0; ks < 8; ++ks) {
            uint32_t aqh[4], aql[4];
            ldsm4(aqh, a_addr + ks * 32);
            ldsm4(aql, a_addr + FQ_PLANE + ks * 32);
            uint32_t bh[4][4], bl[4][4];
            #pragma unroll
            for (int g = 0; g < 4; ++g) {
                ldsm4(bh[g], kb + bk_rel + g * (16 * FSTR) + ks * 32);
                ldsm4(bl[g], kb + FK_PLANE + bk_rel + g * (16 * FSTR) + ks * 32);
            }
            #pragma unroll
            for (int j = 0; j < 8; ++j)
                mma_bf16(s[j], aqh, bh[j >> 1][j & 1], bh[j >> 1][(j & 1) + 2]);
            #pragma unroll
            for (int j = 0; j < 8; ++j)
                mma_bf16(s[j], aql, bh[j >> 1][j & 1], bh[j >> 1][(j & 1) + 2]);
            #pragma unroll
            for (int j = 0; j < 8; ++j)
                mma_bf16(s[j], aqh, bl[j >> 1][j & 1], bl[j >> 1][(j & 1) + 2]);
        }

        // ---- online softmax ----
        float m0 = -1e30f, m1 = -1e30f;
        #pragma unroll
        for (int j = 0; j < 8; ++j) {
            s[j][0] *= scl; s[j][1] *= scl; s[j][2] *= scl; s[j][3] *= scl;
            m0 = fmaxf(m0, fmaxf(s[j][0], s[j][1]));
            m1 = fmaxf(m1, fmaxf(s[j][2], s[j][3]));
        }
        m0 = fmaxf(m0, __shfl_xor_sync(0xffffffffu, m0, 1));
        m0 = fmaxf(m0, __shfl_xor_sync(0xffffffffu, m0, 2));
        m1 = fmaxf(m1, __shfl_xor_sync(0xffffffffu, m1, 1));
        m1 = fmaxf(m1, __shfl_xor_sync(0xffffffffu, m1, 2));
        float mn0 = fmaxf(mrow0, m0), mn1 = fmaxf(mrow1, m1);
        float al0 = __expf(mrow0 - mn0), al1 = __expf(mrow1 - mn1);
        mrow0 = mn0; mrow1 = mn1;

        uint32_t ph[8][2], plo[8][2];
        float ps0 = 0.f, ps1 = 0.f;
        #pragma unroll
        for (int j = 0; j < 8; ++j) {
            float p00 = __expf(s[j][0] - mn0), p01 = __expf(s[j][1] - mn0);
            float p10 = __expf(s[j][2] - mn1), p11 = __expf(s[j][3] - mn1);
            ps0 += p00 + p01; ps1 += p10 + p11;
            split2(p00, p01, ph[j][0], plo[j][0]);
            split2(p10, p11, ph[j][1], plo[j][1]);
        }
        lsum0 = lsum0 * al0 + ps0;
        lsum1 = lsum1 * al1 + ps1;
        #pragma unroll
        for (int j = 0; j < 16; ++j) {
            accO[j][0] *= al0; accO[j][1] *= al0;
            accO[j][2] *= al1; accO[j][3] *= al1;
        }

        // ---- O += P V (split-bf16 3-product, P from regs, V via ldsm.trans)
        uint32_t vb = kb + 2 * FK_PLANE;
        #pragma unroll
        for (int s4 = 0; s4 < 4; ++s4) {
            uint32_t Ahf[4] = { ph[2 * s4][0], ph[2 * s4][1],
                                ph[2 * s4 + 1][0], ph[2 * s4 + 1][1] };
            uint32_t Alf[4] = { plo[2 * s4][0], plo[2 * s4][1],
                                plo[2 * s4 + 1][0], plo[2 * s4 + 1][1] };
            #pragma unroll
            for (int g = 0; g < 8; ++g) {
                uint32_t bvh[4], bvl[4];
                ldsm4t(bvh, vb + bv_rel + s4 * (16 * FSTR) + g * 32);
                ldsm4t(bvl, vb + FK_PLANE + bv_rel + s4 * (16 * FSTR) + g * 32);
                mma_bf16(accO[2 * g],     Ahf, bvh[0], bvh[1]);
                mma_bf16(accO[2 * g + 1], Ahf, bvh[2], bvh[3]);
                mma_bf16(accO[2 * g],     Alf, bvh[0], bvh[1]);
                mma_bf16(accO[2 * g + 1], Alf, bvh[2], bvh[3]);
                mma_bf16(accO[2 * g],     Ahf, bvl[0], bvl[1]);
                mma_bf16(accO[2 * g + 1], Ahf, bvl[2], bvl[3]);
            }
        }
        __syncthreads();
        if (it + 2 < NKT) issueKV(it + 2);
    }

    // ---- epilogue: normalize, split, write into cc planes ----
    lsum0 += __shfl_xor_sync(0xffffffffu, lsum0, 1);
    lsum0 += __shfl_xor_sync(0xffffffffu, lsum0, 2);
    lsum1 += __shfl_xor_sync(0xffffffffu, lsum1, 1);
    lsum1 += __shfl_xor_sync(0xffffffffu, lsum1, 2);
    float inv0 = 1.f / lsum0, inv1 = 1.f / lsum1;
    int r0 = q0 + wid * 16 + (lane >> 2);
    int cbase = head * HDIM + (lane & 3) * 2;
    #pragma unroll
    for (int j = 0; j < 16; ++j) {
        int c = cbase + j * 8;
        uint32_t h, l;
        split2(accO[j][0] * inv0, accO[j][1] * inv0, h, l);
        *reinterpret_cast<uint32_t*>(Och + (size_t)r0 * CCW + c) = h;
        *reinterpret_cast<uint32_t*>(Ocl + (size_t)r0 * CCW + c) = l;
        split2(accO[j][2] * inv1, accO[j][3] * inv1, h, l);
        *reinterpret_cast<uint32_t*>(Och + (size_t)(r0 + 8) * CCW + c) = h;
        *reinterpret_cast<uint32_t*>(Ocl + (size_t)(r0 + 8) * CCW + c) = l;
    }
}

// ---------------- SIMT GEMM for tiny block-2 attention ---------------------
__global__ void __launch_bounds__(256) sgemm_abt(
    const float* __restrict__ A, int lda, long long sA,
    const float* __restrict__ B, int ldb, long long sB,
    float* __restrict__ C, bf16* __restrict__ Ch, bf16* __restrict__ Cl,
    int ldc, long long sC,
    int M, int N, int K, float alpha, int splitout)
{
    __shared__ float As[8][128];
    __shared__ float Bs[8][128];
    int bz = blockIdx.z;
    A += (size_t)sA * bz;
    B += (size_t)sB * bz;
    if (splitout) { Ch += (size_t)sC * bz; Cl += (size_t)sC * bz; }
    else C += (size_t)sC * bz;
    int m0 = blockIdx.y * 128;
    int n0 = blockIdx.x * 128;
    int tid = threadIdx.x;
    int tx = tid & 15, ty = tid >> 4;
    int lrow = tid >> 1;
    int lcol = (tid & 1) * 4;

    float acc[8][8];
    #pragma unroll
    for (int i = 0; i < 8; i++)
        #pragma unroll
        for (int j = 0; j < 8; j++) acc[i][j] = 0.f;

    for (int k0 = 0; k0 < K; k0 += 8) {
        float4 av = make_float4(0.f, 0.f, 0.f, 0.f);
        float4 bv = make_float4(0.f, 0.f, 0.f, 0.f);
        if (m0 + lrow < M && k0 + lcol < K)
            av = *reinterpret_cast<const float4*>(A + (size_t)(m0 + lrow) * lda + k0 + lcol);
        if (n0 + lrow < N && k0 + lcol < K)
            bv = *reinterpret_cast<const float4*>(B + (size_t)(n0 + lrow) * ldb + k0 + lcol);
        As[lcol + 0][lrow] = av.x; As[lcol + 1][lrow] = av.y;
        As[lcol + 2][lrow] = av.z; As[lcol + 3][lrow] = av.w;
        Bs[lcol + 0][lrow] = bv.x; Bs[lcol + 1][lrow] = bv.y;
        Bs[lcol + 2][lrow] = bv.z; Bs[lcol + 3][lrow] = bv.w;
        __syncthreads();
        #pragma unroll
        for (int k = 0; k < 8; k++) {
            float ra[8], rb[8];
            #pragma unroll
            for (int i = 0; i < 8; i++) ra[i] = As[k][ty + 16 * i];
            #pragma unroll
            for (int j = 0; j < 8; j++) rb[j] = Bs[k][tx + 16 * j];
            #pragma unroll
            for (int i = 0; i < 8; i++)
                #pragma unroll
                for (int j = 0; j < 8; j++)
                    acc[i][j] = fmaf(ra[i], rb[j], acc[i][j]);
        }
        __syncthreads();
    }

    #pragma unroll
    for (int i = 0; i < 8; i++) {
        int m = m0 + ty + 16 * i;
        if (m >= M) continue;
        #pragma unroll
        for (int j = 0; j < 8; j++) {
            int n = n0 + tx + 16 * j;
            if (n >= N) continue;
            float v = alpha * acc[i][j];
            if (splitout) {
                bf16 h, l;
                split1(v, h, l);
                Ch[(size_t)m * ldc + n] = h;
                Cl[(size_t)m * ldc + n] = l;
            } else {
                C[(size_t)m * ldc + n] = v;
            }
        }
    }
}

// ---------------- split-convert fp32 -> bf16 hi/lo planes ------------------
__global__ void __launch_bounds__(256) convert_split(
    const float4* __restrict__ src, uint2* __restrict__ h, uint2* __restrict__ l,
    int n4)
{
    int idx = blockIdx.x * 256 + threadIdx.x;
    if (idx >= n4) return;
    uint2 hh, ll;
    split4(src[idx], hh, ll);
    h[idx] = hh;
    l[idx] = ll;
}

// ---------------- modulation: m = silu(vec) @ mod_w^T + mod_b --------------
__global__ void __launch_bounds__(128) mod_kernel(
    const float* __restrict__ vec, const float* __restrict__ mod_w,
    const float* __restrict__ mod_b)
{
    int n = blockIdx.x * 4 + (threadIdx.x >> 5);
    if (n >= 3 * HIDDEN) return;
    int lane = threadIdx.x & 31;
    const float* wrow = mod_w + (size_t)n * HIDDEN;
    float acc = 0.f;
    for (int k = lane; k < HIDDEN; k += 32) {
        float xv = vec[k];
        float s = xv / (1.f + __expf(-xv));
        acc = fmaf(s, wrow[k], acc);
    }
    acc = warp_sum(acc);
    if (lane == 0) g_mod[n] = acc + mod_b[n];
}

// ---------------- layernorm + modulate -> split planes ---------------------
__global__ void __launch_bounds__(256) ln_mod_kernel(
    const float* __restrict__ x, const float* __restrict__ concepts)
{
    __shared__ float sbuf[8];
    int row = blockIdx.x;
    const float* src = (row < LX) ? (x + (size_t)row * HIDDEN)
                                  : (concepts + (size_t)(row - LX) * HIDDEN);
    int tid = threadIdx.x;
    float v[6];
    float s = 0.f;
    #pragma unroll
    for (int i = 0; i < 6; i++) { v[i] = src[tid + 256 * i]; s += v[i]; }
    s = block_sum<256>(s, sbuf);
    float mu = s * (1.0f / 1536.0f);
    float s2 = 0.f;
    #pragma unroll
    for (int i = 0; i < 6; i++) { float d = v[i] - mu; s2 = fmaf(d, d, s2); }
    s2 = block_sum<256>(s2, sbuf);
    float rstd = rsqrtf(s2 * (1.0f / 1536.0f) + 1e-6f);
    #pragma unroll
    for (int i = 0; i < 6; i++) {
        int j = tid + 256 * i;
        float val = (1.f + g_mod[HIDDEN + j]) * ((v[i] - mu) * rstd) + g_mod[j];
        bf16 h, l;
        split1(val, h, l);
        g_xmh[(size_t)row * HIDDEN + j] = h;
        g_xml[(size_t)row * HIDDEN + j] = l;
    }
}

// ---------------- RoPE helper (pair exchange via shfl) ---------------------
__device__ __forceinline__ float rope_pair(float a, const float* __restrict__ petab,
                                           int tok, int d)
{
    float b = __shfl_xor_sync(0xffffffffu, a, 1);
    int i = d >> 1;
    const float* p = petab + ((size_t)tok * 64 + i) * 4;
    if ((d & 1) == 0) return fmaf(p[0], a, p[1] * b);
    else              return fmaf(p[2], b, p[3] * a);
}

// ---------------- attention prep for x tokens ------------------------------
__global__ void __launch_bounds__(128) attn_prep1(
    const float* __restrict__ pe, const float* __restrict__ cpe,
    const float* __restrict__ q_scale, const float* __restrict__ k_scale)
{
    __shared__ float sbuf[4];
    int t = blockIdx.x, h = blockIdx.y, d = threadIdx.x;
    const float* hrow = g_h + (size_t)t * W1OUT;
    float q = hrow[h * HDIM + d];
    float k = hrow[HIDDEN + h * HDIM + d];
    float v = hrow[2 * HIDDEN + h * HDIM + d];
    float msq = block_sum<128>(q * q, sbuf) * (1.f / 128.f);
    float msk = block_sum<128>(k * k, sbuf) * (1.f / 128.f);
    float qn = q * rsqrtf(msq + 1e-6f) * q_scale[d];
    float kn = k * rsqrtf(msk + 1e-6f) * k_scale[d];
    float qr = rope_pair(qn, pe, t, d);
    float kr = rope_pair(kn, pe, t, d);
    bf16 hh, ll;
    size_t qi = ((size_t)h * LX + t) * HDIM + d;
    split1(qr, hh, ll); g_q1h[qi] = hh; g_q1l[qi] = ll;
    split1(kr, hh, ll); g_k1h[qi] = hh; g_k1l[qi] = ll;
    split1(v,  hh, ll); g_v1h[qi] = hh; g_v1l[qi] = ll;
    if (t >= TXT) {
        int j = NC + (t - TXT);
        g_k2[((size_t)h * LC + j) * HDIM + d] = rope_pair(kn, cpe, j, d);
        g_vt2[((size_t)h * HDIM + d) * LC + j] = v;
    }
}

// ---------------- attention prep for concept tokens ------------------------
__global__ void __launch_bounds__(128) attn_prep2(
    const float* __restrict__ cpe,
    const float* __restrict__ q_scale, const float* __restrict__ k_scale)
{
    __shared__ float sbuf[4];
    int i = blockIdx.x, h = blockIdx.y, d = threadIdx.x;
    const float* hrow = g_h + (size_t)(LX + i) * W1OUT;
    float q = hrow[h * HDIM + d];
    float k = hrow[HIDDEN + h * HDIM + d];
    float v = hrow[2 * HIDDEN + h * HDIM + d];
    float msq = block_sum<128>(q * q, sbuf) * (1.f / 128.f);
    float msk = block_sum<128>(k * k, sbuf) * (1.f / 128.f);
    float qn = q * rsqrtf(msq + 1e-6f) * q_scale[d];
    float kn = k * rsqrtf(msk + 1e-6f) * k_scale[d];
    g_q2[((size_t)h * NC + i) * HDIM + d] = rope_pair(qn, cpe, i, d);
    g_k2[((size_t)h * LC + i) * HDIM + d] = rope_pair(kn, cpe, i, d);
    g_vt2[((size_t)h * HDIM + d) * LC + i] = v;
}

// ---------------- row softmax (block-2 path) -------------------------------
__global__ void __launch_bounds__(256) softmax_rows(float* __restrict__ S, int ncol)
{
    __shared__ float sbuf[8];
    float* row = S + (size_t)blockIdx.x * ncol;
    int tid = threadIdx.x;
    float v[17];
    float mx = -1e30f;
    #pragma unroll
    for (int i = 0; i < 17; i++) {
        int c = tid + 256 * i;
        v[i] = (c < ncol) ? row[c] : -1e30f;
        mx = fmaxf(mx, v[i]);
    }
    mx = block_max<256>(mx, sbuf);
    float s = 0.f;
    #pragma unroll
    for (int i = 0; i < 17; i++) { v[i] = __expf(v[i] - mx); s += v[i]; }
    s = block_sum<256>(s, sbuf);
    float inv = 1.f / s;
    #pragma unroll
    for (int i = 0; i < 17; i++) {
        int c = tid + 256 * i;
        if (c < ncol) row[c] = v[i] * inv;
    }
}

// ---------------- gelu(tanh) on mlp part into cc planes --------------------
__global__ void __launch_bounds__(256) gelu_kernel()
{
    size_t idx = (size_t)blockIdx.x * 256 + threadIdx.x;
    if (idx >= (size_t)NROWS * MLPH) return;
    size_t r = idx / MLPH;
    int c = (int)(idx % MLPH);
    float xv = g_h[r * W1OUT + 3 * HIDDEN + c];
    float inner = 0.7978845608028654f * fmaf(0.044715f * xv * xv, xv, xv);
    float gv = 0.5f * xv * (1.f + tanhf(inner));
    bf16 h, l;
    split1(gv, h, l);
    g_cch[r * CCW + HIDDEN + c] = h;
    g_ccl[r * CCW + HIDDEN + c] = l;
}

// ---------------- residual: out = base + gate * block_out ------------------
__global__ void __launch_bounds__(256) final_kernel(
    const float* __restrict__ x, const float* __restrict__ concepts,
    float* __restrict__ out)
{
    size_t idx = (size_t)blockIdx.x * 256 + threadIdx.x;
    if (idx >= (size_t)NROWS * HIDDEN) return;
    int c = (int)(idx % HIDDEN);
    size_t r = idx / HIDDEN;
    float base = (r < LX) ? x[idx] : concepts[idx - (size_t)LX * HIDDEN];
    out[idx] = fmaf(g_mod[2 * HIDDEN + c], g_out[idx], base);
}

// ---------------------------------------------------------------------------
extern "C" void kernel_launch(void* const* d_in, const int* in_sizes, int n_in,
                              void* d_out, int out_size)
{
    const float* x        = (const float*)d_in[0];
    const float* concepts = (const float*)d_in[1];
    const float* vec      = (const float*)d_in[2];
    const float* pe       = (const float*)d_in[3];
    const float* cpe      = (const float*)d_in[4];
    const float* w1       = (const float*)d_in[5];
    const float* b1       = (const float*)d_in[6];
    const float* w2       = (const float*)d_in[7];
    const float* b2       = (const float*)d_in[8];
    const float* q_scale  = (const float*)d_in[9];
    const float* k_scale  = (const float*)d_in[10];
    const float* mod_w    = (const float*)d_in[11];
    const float* mod_b    = (const float*)d_in[12];
    float* out = (float*)d_out;

    void* p;
    cudaGetSymbolAddress(&p, g_xmh);  bf16* xmh = (bf16*)p;
    cudaGetSymbolAddress(&p, g_xml);  bf16* xml = (bf16*)p;
    cudaGetSymbolAddress(&p, g_w1h);  bf16* w1h = (bf16*)p;
    cudaGetSymbolAddress(&p, g_w1l);  bf16* w1l = (bf16*)p;
    cudaGetSymbolAddress(&p, g_w2h);  bf16* w2h = (bf16*)p;
    cudaGetSymbolAddress(&p, g_w2l);  bf16* w2l = (bf16*)p;
    cudaGetSymbolAddress(&p, g_h);    float* hbuf = (float*)p;
    cudaGetSymbolAddress(&p, g_q1h);  bf16* q1h = (bf16*)p;
    cudaGetSymbolAddress(&p, g_q1l);  bf16* q1l = (bf16*)p;
    cudaGetSymbolAddress(&p, g_k1h);  bf16* k1h = (bf16*)p;
    cudaGetSymbolAddress(&p, g_k1l);  bf16* k1l = (bf16*)p;
    cudaGetSymbolAddress(&p, g_v1h);  bf16* v1h = (bf16*)p;
    cudaGetSymbolAddress(&p, g_v1l);  bf16* v1l = (bf16*)p;
    cudaGetSymbolAddress(&p, g_q2);   float* q2b  = (float*)p;
    cudaGetSymbolAddress(&p, g_k2);   float* k2b  = (float*)p;
    cudaGetSymbolAddress(&p, g_vt2);  float* vt2b = (float*)p;
    cudaGetSymbolAddress(&p, g_s2);   float* s2b  = (float*)p;
    cudaGetSymbolAddress(&p, g_cch);  bf16* cch = (bf16*)p;
    cudaGetSymbolAddress(&p, g_ccl);  bf16* ccl = (bf16*)p;
    cudaGetSymbolAddress(&p, g_out);  float* outb = (float*)p;

    cudaFuncSetAttribute(gemm_bf, cudaFuncAttributeMaxDynamicSharedMemorySize,
                         HG_SMEM);
    cudaFuncSetAttribute(flash1, cudaFuncAttributeMaxDynamicSharedMemorySize,
                         FLASH_SMEM);

    const float scl = 0.08838834764831845f;  // 1/sqrt(128)

    // modulation vector (shift | scale | gate)
    mod_kernel<<<(3 * HIDDEN + 3) / 4, 128>>>(vec, mod_w, mod_b);
    // weight splitting (hi/lo bf16 planes)
    {
        int n4 = (W1OUT * HIDDEN) / 4;
        convert_split<<<(n4 + 255) / 256, 256>>>(
            (const float4*)w1, (uint2*)w1h, (uint2*)w1l, n4);
        n4 = (HIDDEN * CCW) / 4;
        convert_split<<<(n4 + 255) / 256, 256>>>(
            (const float4*)w2, (uint2*)w2h, (uint2*)w2l, n4);
    }
    // layernorm + modulate -> xm planes
    ln_mod_kernel<<<NROWS, 256>>>(x, concepts);
    // GEMM1: h = xm @ w1^T + b1
    gemm_bf<<<dim3(W1OUT / 128, (NROWS + 127) / 128, 1), 256, HG_SMEM>>>(
        xmh, xml, HIDDEN, 0, w1h, w1l, HIDDEN, 0,
        hbuf, W1OUT, 0, NROWS, W1OUT, HIDDEN, 1.f, b1);
    // rmsnorm + rope -> q/k/v planes (+ block2 fp32 arrays)
    attn_prep1<<<dim3(LX, NHEADS), 128>>>(pe, cpe, q_scale, k_scale);
    attn_prep2<<<dim3(NC, NHEADS), 128>>>(cpe, q_scale, k_scale);
    // block1 fused flash attention -> cc planes cols [0,1536)
    flash1<<<dim3(LX / 128, NHEADS), 256, FLASH_SMEM>>>(
        q1h, q1l, k1h, k1l, v1h, v1l, cch, ccl);
    // block2 attention (20 queries over 4116 keys) — SIMT path
    sgemm_abt<<<dim3((LC + 127) / 128, 1, NHEADS), 256>>>(
        q2b, HDIM, (long long)NC * HDIM, k2b, HDIM, (long long)LC * HDIM,
        s2b, nullptr, nullptr, LC, (long long)NC * LC,
        NC, LC, HDIM, scl, 0);
    softmax_rows<<<NHEADS * NC, 256>>>(s2b, LC);
    sgemm_abt<<<dim3(1, 1, NHEADS), 256>>>(
        s2b, LC, (long long)NC * LC, vt2b, LC, (long long)HDIM * LC,
        nullptr, cch + (size_t)LX * CCW, ccl + (size_t)LX * CCW, CCW, 128,
        NC, HDIM, LC, 1.f, 1);
    // gelu on mlp half -> cc planes
    gelu_kernel<<<(unsigned)(((size_t)NROWS * MLPH + 255) / 256), 256>>>();
    // GEMM2: out = cc @ w2^T + b2
    gemm_bf<<<dim3(HIDDEN / 128, (NROWS + 127) / 128, 1), 256, HG_SMEM>>>(
        cch, ccl, CCW, 0, w2h, w2l, CCW, 0,
        outb, HIDDEN, 0, NROWS, HIDDEN, CCW, 1.f, b2);
    // residual + gate
    final_kernel<<<(unsigned)(((size_t)NROWS * HIDDEN + 255) / 256), 256>>>(
        x, concepts, out);
}

// round 6
// speedup vs baseline: 1.2322x; 1.0676x over previous
#include <cuda_runtime.h>
#include <cuda_bf16.h>
#include <math.h>
#include <stdint.h>

#define HIDDEN 1536
#define NHEADS 12
#define HDIM 128
#define MLPH 6144
#define TXT 256
#define LX 4352
#define NC 20
#define LC 4116
#define NROWS 4372          // LX + NC
#define W1OUT 10752         // 3*HIDDEN + MLPH
#define QKVW 4608           // 3*HIDDEN
#define CCW 7680            // HIDDEN + MLPH

typedef __nv_bfloat16 bf16;

// ---------------- scratch (static device globals; no runtime allocation) ---
static __device__ float g_mod[3 * HIDDEN];
static __device__ bf16  g_xmh[(size_t)NROWS * HIDDEN];
static __device__ bf16  g_xml[(size_t)NROWS * HIDDEN];
static __device__ bf16  g_w1h[(size_t)W1OUT * HIDDEN];
static __device__ bf16  g_w1l[(size_t)W1OUT * HIDDEN];
static __device__ bf16  g_w2h[(size_t)HIDDEN * CCW];
static __device__ bf16  g_w2l[(size_t)HIDDEN * CCW];
static __device__ float g_h[(size_t)NROWS * QKVW];
static __device__ bf16  g_q1h[(size_t)NHEADS * LX * HDIM];
static __device__ bf16  g_q1l[(size_t)NHEADS * LX * HDIM];
static __device__ bf16  g_k1h[(size_t)NHEADS * LX * HDIM];
static __device__ bf16  g_k1l[(size_t)NHEADS * LX * HDIM];
static __device__ bf16  g_v1h[(size_t)NHEADS * LX * HDIM];
static __device__ bf16  g_v1l[(size_t)NHEADS * LX * HDIM];
static __device__ float g_q2[(size_t)NHEADS * NC * HDIM];
static __device__ float g_k2[(size_t)NHEADS * LC * HDIM];
static __device__ float g_vt2[(size_t)NHEADS * HDIM * LC];
static __device__ float g_s2[(size_t)NHEADS * NC * LC];
static __device__ bf16  g_cch[(size_t)NROWS * CCW];
static __device__ bf16  g_ccl[(size_t)NROWS * CCW];
static __device__ float g_out[(size_t)NROWS * HIDDEN];

// ---------------- reductions ----------------------------------------------
__device__ __forceinline__ float warp_sum(float v) {
    #pragma unroll
    for (int o = 16; o > 0; o >>= 1) v += __shfl_xor_sync(0xffffffffu, v, o);
    return v;
}
__device__ __forceinline__ float warp_max(float v) {
    #pragma unroll
    for (int o = 16; o > 0; o >>= 1) v = fmaxf(v, __shfl_xor_sync(0xffffffffu, v, o));
    return v;
}
template <int NT>
__device__ __forceinline__ float block_sum(float v, float* sbuf) {
    v = warp_sum(v);
    int lane = threadIdx.x & 31, w = threadIdx.x >> 5;
    if (lane == 0) sbuf[w] = v;
    __syncthreads();
    if (threadIdx.x < 32) {
        float x = (threadIdx.x < NT / 32) ? sbuf[threadIdx.x] : 0.f;
        x = warp_sum(x);
        if (threadIdx.x == 0) sbuf[0] = x;
    }
    __syncthreads();
    float r = sbuf[0];
    __syncthreads();
    return r;
}
template <int NT>
__device__ __forceinline__ float block_max(float v, float* sbuf) {
    v = warp_max(v);
    int lane = threadIdx.x & 31, w = threadIdx.x >> 5;
    if (lane == 0) sbuf[w] = v;
    __syncthreads();
    if (threadIdx.x < 32) {
        float x = (threadIdx.x < NT / 32) ? sbuf[threadIdx.x] : -1e30f;
        x = warp_max(x);
        if (threadIdx.x == 0) sbuf[0] = x;
    }
    __syncthreads();
    float r = sbuf[0];
    __syncthreads();
    return r;
}

// ---------------- split helpers --------------------------------------------
__device__ __forceinline__ void split1(float v, bf16& h, bf16& l) {
    h = __float2bfloat16(v);
    l = __float2bfloat16(v - __bfloat162float(h));
}
__device__ __forceinline__ void split2(float x, float y, uint32_t& h, uint32_t& l) {
    bf16 hx, lx, hy, ly;
    split1(x, hx, lx); split1(y, hy, ly);
    __nv_bfloat162 hh(hx, hy), ll(lx, ly);
    h = *reinterpret_cast<uint32_t*>(&hh);
    l = *reinterpret_cast<uint32_t*>(&ll);
}
__device__ __forceinline__ void split4(float4 v, uint2& h, uint2& l) {
    split2(v.x, v.y, h.x, l.x);
    split2(v.z, v.w, h.y, l.y);
}
__device__ __forceinline__ float gelu_f(float xv) {
    float inner = 0.7978845608028654f * fmaf(0.044715f * xv * xv, xv, xv);
    return 0.5f * xv * (1.f + tanhf(inner));
}

// ======================= HMMA helpers ======================================
__device__ __forceinline__ uint32_t smem_u32(const void* p) {
    uint32_t a;
    asm("{ .reg .u64 t; cvta.to.shared.u64 t, %1; cvt.u32.u64 %0, t; }"
        : "=r"(a) : "l"(p));
    return a;
}
__device__ __forceinline__ void ldsm4(uint32_t* r, uint32_t addr) {
    asm volatile("ldmatrix.sync.aligned.m8n8.x4.shared.b16 {%0,%1,%2,%3}, [%4];"
                 : "=r"(r[0]), "=r"(r[1]), "=r"(r[2]), "=r"(r[3]) : "r"(addr));
}
__device__ __forceinline__ void ldsm4t(uint32_t* r, uint32_t addr) {
    asm volatile("ldmatrix.sync.aligned.m8n8.x4.trans.shared.b16 {%0,%1,%2,%3}, [%4];"
                 : "=r"(r[0]), "=r"(r[1]), "=r"(r[2]), "=r"(r[3]) : "r"(addr));
}
__device__ __forceinline__ void mma_bf16(float* c, const uint32_t* a,
                                         uint32_t b0, uint32_t b1) {
    asm volatile(
        "mma.sync.aligned.m16n8k16.row.col.f32.bf16.bf16.f32 "
        "{%0,%1,%2,%3}, {%4,%5,%6,%7}, {%8,%9}, {%0,%1,%2,%3};"
        : "+f"(c[0]), "+f"(c[1]), "+f"(c[2]), "+f"(c[3])
        : "r"(a[0]), "r"(a[1]), "r"(a[2]), "r"(a[3]), "r"(b0), "r"(b1));
}
__device__ __forceinline__ void cp_async16(uint32_t dst, const void* src, int sz) {
    asm volatile("cp.async.cg.shared.global [%0], [%1], 16, %2;"
                 :: "r"(dst), "l"(src), "r"(sz) : "memory");
}
__device__ __forceinline__ void cp_commit() {
    asm volatile("cp.async.commit_group;" ::: "memory");
}
__device__ __forceinline__ void cp_wait0() {
    asm volatile("cp.async.wait_group 0;" ::: "memory");
}
__device__ __forceinline__ void cp_wait1() {
    asm volatile("cp.async.wait_group 1;" ::: "memory");
}

// smem: per stage 4 tiles (Ah, Al, Bh, Bl): 128 rows x 32 bf16, row stride 80 B
#define SPB      80
#define T_BYTES  (128 * SPB)          // 10240
#define STAGE_B  (4 * T_BYTES)        // 40960
#define HG_SMEM  (2 * STAGE_B)        // 81920 -> 2 CTAs/SM

// ======== split-bf16 HMMA GEMM: C = A@B^T + bias ===========================
// Pre-split bf16 hi/lo operand planes. Columns n >= gelu_n0 get bias+gelu and
// are split-written to Gh/Gl at column HIDDEN + n - gelu_n0 (stride CCW);
// columns n < gelu_n0 are written fp32 to C (stride ldc).
__global__ void __launch_bounds__(256, 2) gemm_bf(
    const bf16* __restrict__ Ah, const bf16* __restrict__ Al, int lda,
    const bf16* __restrict__ Bh, const bf16* __restrict__ Bl, int ldb,
    float* __restrict__ C, int ldc,
    bf16* __restrict__ Gh, bf16* __restrict__ Gl, int gelu_n0,
    int M, int N, int K, const float* __restrict__ bias)
{
    extern __shared__ char smem[];
    uint32_t sbase = smem_u32(smem);
    int tid = threadIdx.x, wid = tid >> 5, lane = tid & 31;

    // supertile swizzle for L2 reuse: GROUP m-tiles per CTA stripe
    const int GRP = 8;
    int npn = gridDim.x, npm = gridDim.y;
    int pid = blockIdx.y * npn + blockIdx.x;
    int gsz = GRP * npn;
    int gid = pid / gsz;
    int fm = gid * GRP;
    int gm = min(GRP, npm - fm);
    int pid_m = fm + (pid % gsz) % gm;
    int pid_n = (pid % gsz) / gm;
    int m0 = pid_m * 128, n0 = pid_n * 128;

    int warp_m = wid & 3;
    int warp_n = wid >> 2;
    int lrow = lane & 15, lhalf = lane >> 4;

    uint32_t a_off[2], b_off[4];
    #pragma unroll
    for (int i = 0; i < 2; ++i)
        a_off[i] = (uint32_t)((warp_m * 32 + i * 16 + lrow) * SPB + lhalf * 16);
    #pragma unroll
    for (int g = 0; g < 4; ++g)
        b_off[g] = (uint32_t)((warp_n * 64 + g * 16 + lrow) * SPB + lhalf * 16);

    float acc[2][8][4];
    #pragma unroll
    for (int i = 0; i < 2; ++i)
        #pragma unroll
        for (int j = 0; j < 8; ++j)
            #pragma unroll
            for (int t = 0; t < 4; ++t) acc[i][j][t] = 0.f;

    int nch = K >> 5;

    auto issue = [&](int c) {
        if (c < nch) {
            int kc = c << 5;
            uint32_t sb = sbase + (uint32_t)(c & 1) * STAGE_B;
            #pragma unroll
            for (int u8 = 0; u8 < 8; ++u8) {
                int u = tid + 256 * u8;
                int tile = u >> 9;
                int r = (u >> 2) & 127;
                int c16 = u & 3;
                uint32_t dst = sb + (uint32_t)(tile * T_BYTES + r * SPB + c16 * 16);
                if (tile == 0) {
                    int sz = (m0 + r < M) ? 16 : 0;
                    cp_async16(dst, Ah + (size_t)(m0 + r) * lda + kc + c16 * 8, sz);
                } else if (tile == 1) {
                    int sz = (m0 + r < M) ? 16 : 0;
                    cp_async16(dst, Al + (size_t)(m0 + r) * lda + kc + c16 * 8, sz);
                } else if (tile == 2) {
                    cp_async16(dst, Bh + (size_t)(n0 + r) * ldb + kc + c16 * 8, 16);
                } else {
                    cp_async16(dst, Bl + (size_t)(n0 + r) * ldb + kc + c16 * 8, 16);
                }
            }
        }
        cp_commit();
    };

    issue(0); issue(1);

    for (int c = 0; c < nch; ++c) {
        cp_wait1();
        __syncthreads();
        uint32_t sb = sbase + (uint32_t)(c & 1) * STAGE_B;
        #pragma unroll
        for (int k16 = 0; k16 < 2; ++k16) {
            uint32_t koff = (uint32_t)(k16 * 32);
            uint32_t ah[2][4], al[2][4];
            #pragma unroll
            for (int i = 0; i < 2; ++i) {
                ldsm4(ah[i], sb + 0 * T_BYTES + a_off[i] + koff);
                ldsm4(al[i], sb + 1 * T_BYTES + a_off[i] + koff);
            }
            #pragma unroll
            for (int g = 0; g < 4; ++g) {
                uint32_t bh[4], bl[4];
                ldsm4(bh, sb + 2 * T_BYTES + b_off[g] + koff);
                ldsm4(bl, sb + 3 * T_BYTES + b_off[g] + koff);
                #pragma unroll
                for (int i = 0; i < 2; ++i)
                    #pragma unroll
                    for (int sI = 0; sI < 2; ++sI)
                        mma_bf16(acc[i][2 * g + sI], ah[i], bh[sI], bh[sI + 2]);
                #pragma unroll
                for (int i = 0; i < 2; ++i)
                    #pragma unroll
                    for (int sI = 0; sI < 2; ++sI)
                        mma_bf16(acc[i][2 * g + sI], al[i], bh[sI], bh[sI + 2]);
                #pragma unroll
                for (int i = 0; i < 2; ++i)
                    #pragma unroll
                    for (int sI = 0; sI < 2; ++sI)
                        mma_bf16(acc[i][2 * g + sI], ah[i], bl[sI], bl[sI + 2]);
            }
        }
        __syncthreads();
        issue(c + 2);
    }

    // ---- epilogue ----
    int trow = lane >> 2, tc2 = (lane & 3) * 2;
    #pragma unroll
    for (int i = 0; i < 2; ++i) {
        #pragma unroll
        for (int half = 0; half < 2; ++half) {
            int m = m0 + warp_m * 32 + i * 16 + half * 8 + trow;
            if (m >= M) continue;
            #pragma unroll
            for (int j = 0; j < 8; ++j) {
                int n = n0 + warp_n * 64 + j * 8 + tc2;
                float vx = acc[i][j][half * 2 + 0];
                float vy = acc[i][j][half * 2 + 1];
                if (bias) { vx += bias[n]; vy += bias[n + 1]; }
                if (n >= gelu_n0) {
                    vx = gelu_f(vx); vy = gelu_f(vy);
                    int cc = HIDDEN + n - gelu_n0;
                    uint32_t h, l;
                    split2(vx, vy, h, l);
                    *reinterpret_cast<uint32_t*>(Gh + (size_t)m * CCW + cc) = h;
                    *reinterpret_cast<uint32_t*>(Gl + (size_t)m * CCW + cc) = l;
                } else {
                    *reinterpret_cast<float2*>(C + (size_t)m * ldc + n) =
                        make_float2(vx, vy);
                }
            }
        }
    }
}

// ================= flash attention for block 1 =============================
#define BK 64
#define FSTR 272                       // 128*2 + 16 pad
#define FQ_PLANE (128 * FSTR)          // 34816
#define FK_PLANE (BK * FSTR)           // 17408
#define FS_OFF   (2 * FQ_PLANE)        // 69632
#define FSTAGE   (4 * FK_PLANE)        // 69632
#define FLASH_SMEM (FS_OFF + 2 * FSTAGE)  // 208896
#define NKT (LX / BK)                  // 68

__global__ void __launch_bounds__(256, 1) flash1(
    const bf16* __restrict__ Qh, const bf16* __restrict__ Ql,
    const bf16* __restrict__ Kh, const bf16* __restrict__ Kl,
    const bf16* __restrict__ Vh, const bf16* __restrict__ Vl,
    bf16* __restrict__ Och, bf16* __restrict__ Ocl)
{
    extern __shared__ char smem[];
    uint32_t sbase = smem_u32(smem);
    int tid = threadIdx.x, wid = tid >> 5, lane = tid & 31;
    int head = blockIdx.y;
    int q0 = blockIdx.x * 128;
    size_t hb = (size_t)head * LX * HDIM;
    const bf16* qp0 = Qh + hb + (size_t)q0 * HDIM;
    const bf16* qp1 = Ql + hb + (size_t)q0 * HDIM;
    const bf16* kp[4] = { Kh + hb, Kl + hb, Vh + hb, Vl + hb };

    #pragma unroll
    for (int u8 = 0; u8 < 16; ++u8) {
        int u = tid + 256 * u8;
        int pl = u >> 11, r = (u >> 4) & 127, c = u & 15;
        const bf16* src = (pl ? qp1 : qp0) + (size_t)r * HDIM + c * 8;
        cp_async16(sbase + (uint32_t)(pl * FQ_PLANE + r * FSTR + c * 16), src, 16);
    }
    cp_commit();

    auto issueKV = [&](int it) {
        int kv0 = it * BK;
        #pragma unroll
        for (int u8 = 0; u8 < 16; ++u8) {
            int u = tid + 256 * u8;
            int pl = u >> 10, r = (u >> 4) & 63, c = u & 15;
            cp_async16(sbase + (uint32_t)(FS_OFF + (it & 1) * FSTAGE +
                                          pl * FK_PLANE + r * FSTR + c * 16),
                       kp[pl] + (size_t)(kv0 + r) * HDIM + c * 8, 16);
        }
        cp_commit();
    };
    issueKV(0);
    issueKV(1);

    uint32_t a_addr = sbase + (uint32_t)((wid * 16 + (lane & 15)) * FSTR +
                                         (lane >> 4) * 16);
    uint32_t bk_rel = (uint32_t)((lane & 15) * FSTR + (lane >> 4) * 16);
    uint32_t bv_rel = (uint32_t)(((((lane >> 3) & 1) * 8) + (lane & 7)) * FSTR +
                                 ((lane >> 4) & 1) * 16);

    float accO[16][4];
    #pragma unroll
    for (int j = 0; j < 16; ++j)
        #pragma unroll
        for (int t = 0; t < 4; ++t) accO[j][t] = 0.f;
    float mrow0 = -1e30f, mrow1 = -1e30f, lsum0 = 0.f, lsum1 = 0.f;
    const float scl = 0.08838834764831845f;

    for (int it = 0; it < NKT; ++it) {
        if (it < NKT - 1) cp_wait1(); else cp_wait0();
        __syncthreads();
        uint32_t kb = sbase + FS_OFF + (uint32_t)(it & 1) * FSTAGE;

        float s[8][4];
        #pragma unroll
        for (int j = 0; j < 8; ++j)
            #pragma unroll
            for (int t = 0; t < 4; ++t) s[j][t] = 0.f;
        #pragma unroll
        for (int ks = 0; ks < 8; ++ks) {
            uint32_t aqh[4], aql[4];
            ldsm4(aqh, a_addr + ks * 32);
            ldsm4(aql, a_addr + FQ_PLANE + ks * 32);
            uint32_t bh[4][4], bl[4][4];
            #pragma unroll
            for (int g = 0; g < 4; ++g) {
                ldsm4(bh[g], kb + bk_rel + g * (16 * FSTR) + ks * 32);
                ldsm4(bl[g], kb + FK_PLANE + bk_rel + g * (16 * FSTR) + ks * 32);
            }
            #pragma unroll
            for (int j = 0; j < 8; ++j)
                mma_bf16(s[j], aqh, bh[j >> 1][j & 1], bh[j >> 1][(j & 1) + 2]);
            #pragma unroll
            for (int j = 0; j < 8; ++j)
                mma_bf16(s[j], aql, bh[j >> 1][j & 1], bh[j >> 1][(j & 1) + 2]);
            #pragma unroll
            for (int j = 0; j < 8; ++j)
                mma_bf16(s[j], aqh, bl[j >> 1][j & 1], bl[j >> 1][(j & 1) + 2]);
        }

        float m0 = -1e30f, m1 = -1e30f;
        #pragma unroll
        for (int j = 0; j < 8; ++j) {
            s[j][0] *= scl; s[j][1] *= scl; s[j][2] *= scl; s[j][3] *= scl;
            m0 = fmaxf(m0, fmaxf(s[j][0], s[j][1]));
            m1 = fmaxf(m1, fmaxf(s[j][2], s[j][3]));
        }
        m0 = fmaxf(m0, __shfl_xor_sync(0xffffffffu, m0, 1));
        m0 = fmaxf(m0, __shfl_xor_sync(0xffffffffu, m0, 2));
        m1 = fmaxf(m1, __shfl_xor_sync(0xffffffffu, m1, 1));
        m1 = fmaxf(m1, __shfl_xor_sync(0xffffffffu, m1, 2));
        float mn0 = fmaxf(mrow0, m0), mn1 = fmaxf(mrow1, m1);
        float al0 = __expf(mrow0 - mn0), al1 = __expf(mrow1 - mn1);
        mrow0 = mn0; mrow1 = mn1;

        uint32_t ph[8][2], plo[8][2];
        float ps0 = 0.f, ps1 = 0.f;
        #pragma unroll
        for (int j = 0; j < 8; ++j) {
            float p00 = __expf(s[j][0] - mn0), p01 = __expf(s[j][1] - mn0);
            float p10 = __expf(s[j][2] - mn1), p11 = __expf(s[j][3] - mn1);
            ps0 += p00 + p01; ps1 += p10 + p11;
            split2(p00, p01, ph[j][0], plo[j][0]);
            split2(p10, p11, ph[j][1], plo[j][1]);
        }
        lsum0 = lsum0 * al0 + ps0;
        lsum1 = lsum1 * al1 + ps1;
        #pragma unroll
        for (int j = 0; j < 16; ++j) {
            accO[j][0] *= al0; accO[j][1] *= al0;
            accO[j][2] *= al1; accO[j][3] *= al1;
        }

        uint32_t vb = kb + 2 * FK_PLANE;
        #pragma unroll
        for (int s4 = 0; s4 < 4; ++s4) {
            uint32_t Ahf[4] = { ph[2 * s4][0], ph[2 * s4][1],
                                ph[2 * s4 + 1][0], ph[2 * s4 + 1][1] };
            uint32_t Alf[4] = { plo[2 * s4][0], plo[2 * s4][1],
                                plo[2 * s4 + 1][0], plo[2 * s4 + 1][1] };
            #pragma unroll
            for (int g = 0; g < 8; ++g) {
                uint32_t bvh[4], bvl[4];
                ldsm4t(bvh, vb + bv_rel + s4 * (16 * FSTR) + g * 32);
                ldsm4t(bvl, vb + FK_PLANE + bv_rel + s4 * (16 * FSTR) + g * 32);
                mma_bf16(accO[2 * g],     Ahf, bvh[0], bvh[1]);
                mma_bf16(accO[2 * g + 1], Ahf, bvh[2], bvh[3]);
                mma_bf16(accO[2 * g],     Alf, bvh[0], bvh[1]);
                mma_bf16(accO[2 * g + 1], Alf, bvh[2], bvh[3]);
                mma_bf16(accO[2 * g],     Ahf, bvl[0], bvl[1]);
                mma_bf16(accO[2 * g + 1], Ahf, bvl[2], bvl[3]);
            }
        }
        __syncthreads();
        if (it + 2 < NKT) issueKV(it + 2);
    }

    lsum0 += __shfl_xor_sync(0xffffffffu, lsum0, 1);
    lsum0 += __shfl_xor_sync(0xffffffffu, lsum0, 2);
    lsum1 += __shfl_xor_sync(0xffffffffu, lsum1, 1);
    lsum1 += __shfl_xor_sync(0xffffffffu, lsum1, 2);
    float inv0 = 1.f / lsum0, inv1 = 1.f / lsum1;
    int r0 = q0 + wid * 16 + (lane >> 2);
    int cbase = head * HDIM + (lane & 3) * 2;
    #pragma unroll
    for (int j = 0; j < 16; ++j) {
        int c = cbase + j * 8;
        uint32_t h, l;
        split2(accO[j][0] * inv0, accO[j][1] * inv0, h, l);
        *reinterpret_cast<uint32_t*>(Och + (size_t)r0 * CCW + c) = h;
        *reinterpret_cast<uint32_t*>(Ocl + (size_t)r0 * CCW + c) = l;
        split2(accO[j][2] * inv1, accO[j][3] * inv1, h, l);
        *reinterpret_cast<uint32_t*>(Och + (size_t)(r0 + 8) * CCW + c) = h;
        *reinterpret_cast<uint32_t*>(Ocl + (size_t)(r0 + 8) * CCW + c) = l;
    }
}

// ---------------- SIMT GEMM for tiny block-2 attention ---------------------
__global__ void __launch_bounds__(256) sgemm_abt(
    const float* __restrict__ A, int lda, long long sA,
    const float* __restrict__ B, int ldb, long long sB,
    float* __restrict__ C, bf16* __restrict__ Ch, bf16* __restrict__ Cl,
    int ldc, long long sC,
    int M, int N, int K, float alpha, int splitout)
{
    __shared__ float As[8][128];
    __shared__ float Bs[8][128];
    int bz = blockIdx.z;
    A += (size_t)sA * bz;
    B += (size_t)sB * bz;
    if (splitout) { Ch += (size_t)sC * bz; Cl += (size_t)sC * bz; }
    else C += (size_t)sC * bz;
    int m0 = blockIdx.y * 128;
    int n0 = blockIdx.x * 128;
    int tid = threadIdx.x;
    int tx = tid & 15, ty = tid >> 4;
    int lrow = tid >> 1;
    int lcol = (tid & 1) * 4;

    float acc[8][8];
    #pragma unroll
    for (int i = 0; i < 8; i++)
        #pragma unroll
        for (int j = 0; j < 8; j++) acc[i][j] = 0.f;

    for (int k0 = 0; k0 < K; k0 += 8) {
        float4 av = make_float4(0.f, 0.f, 0.f, 0.f);
        float4 bv = make_float4(0.f, 0.f, 0.f, 0.f);
        if (m0 + lrow < M && k0 + lcol < K)
            av = *reinterpret_cast<const float4*>(A + (size_t)(m0 + lrow) * lda + k0 + lcol);
        if (n0 + lrow < N && k0 + lcol < K)
            bv = *reinterpret_cast<const float4*>(B + (size_t)(n0 + lrow) * ldb + k0 + lcol);
        As[lcol + 0][lrow] = av.x; As[lcol + 1][lrow] = av.y;
        As[lcol + 2][lrow] = av.z; As[lcol + 3][lrow] = av.w;
        Bs[lcol + 0][lrow] = bv.x; Bs[lcol + 1][lrow] = bv.y;
        Bs[lcol + 2][lrow] = bv.z; Bs[lcol + 3][lrow] = bv.w;
        __syncthreads();
        #pragma unroll
        for (int k = 0; k < 8; k++) {
            float ra[8], rb[8];
            #pragma unroll
            for (int i = 0; i < 8; i++) ra[i] = As[k][ty + 16 * i];
            #pragma unroll
            for (int j = 0; j < 8; j++) rb[j] = Bs[k][tx + 16 * j];
            #pragma unroll
            for (int i = 0; i < 8; i++)
                #pragma unroll
                for (int j = 0; j < 8; j++)
                    acc[i][j] = fmaf(ra[i], rb[j], acc[i][j]);
        }
        __syncthreads();
    }

    #pragma unroll
    for (int i = 0; i < 8; i++) {
        int m = m0 + ty + 16 * i;
        if (m >= M) continue;
        #pragma unroll
        for (int j = 0; j < 8; j++) {
            int n = n0 + tx + 16 * j;
            if (n >= N) continue;
            float v = alpha * acc[i][j];
            if (splitout) {
                bf16 h, l;
                split1(v, h, l);
                Ch[(size_t)m * ldc + n] = h;
                Cl[(size_t)m * ldc + n] = l;
            } else {
                C[(size_t)m * ldc + n] = v;
            }
        }
    }
}

// ---------------- split-convert fp32 -> bf16 hi/lo planes ------------------
__global__ void __launch_bounds__(256) convert_split(
    const float4* __restrict__ src, uint2* __restrict__ h, uint2* __restrict__ l,
    int n4)
{
    int idx = blockIdx.x * 256 + threadIdx.x;
    if (idx >= n4) return;
    uint2 hh, ll;
    split4(src[idx], hh, ll);
    h[idx] = hh;
    l[idx] = ll;
}

// ---------------- modulation: m = silu(vec) @ mod_w^T + mod_b --------------
__global__ void __launch_bounds__(128) mod_kernel(
    const float* __restrict__ vec, const float* __restrict__ mod_w,
    const float* __restrict__ mod_b)
{
    int n = blockIdx.x * 4 + (threadIdx.x >> 5);
    if (n >= 3 * HIDDEN) return;
    int lane = threadIdx.x & 31;
    const float* wrow = mod_w + (size_t)n * HIDDEN;
    float acc = 0.f;
    for (int k = lane; k < HIDDEN; k += 32) {
        float xv = vec[k];
        float s = xv / (1.f + __expf(-xv));
        acc = fmaf(s, wrow[k], acc);
    }
    acc = warp_sum(acc);
    if (lane == 0) g_mod[n] = acc + mod_b[n];
}

// ---------------- layernorm + modulate -> split planes ---------------------
__global__ void __launch_bounds__(256) ln_mod_kernel(
    const float* __restrict__ x, const float* __restrict__ concepts)
{
    __shared__ float sbuf[8];
    int row = blockIdx.x;
    const float* src = (row < LX) ? (x + (size_t)row * HIDDEN)
                                  : (concepts + (size_t)(row - LX) * HIDDEN);
    int tid = threadIdx.x;
    float v[6];
    float s = 0.f;
    #pragma unroll
    for (int i = 0; i < 6; i++) { v[i] = src[tid + 256 * i]; s += v[i]; }
    s = block_sum<256>(s, sbuf);
    float mu = s * (1.0f / 1536.0f);
    float s2 = 0.f;
    #pragma unroll
    for (int i = 0; i < 6; i++) { float d = v[i] - mu; s2 = fmaf(d, d, s2); }
    s2 = block_sum<256>(s2, sbuf);
    float rstd = rsqrtf(s2 * (1.0f / 1536.0f) + 1e-6f);
    #pragma unroll
    for (int i = 0; i < 6; i++) {
        int j = tid + 256 * i;
        float val = (1.f + g_mod[HIDDEN + j]) * ((v[i] - mu) * rstd) + g_mod[j];
        bf16 h, l;
        split1(val, h, l);
        g_xmh[(size_t)row * HIDDEN + j] = h;
        g_xml[(size_t)row * HIDDEN + j] = l;
    }
}

// ---------------- RoPE helper (pair exchange via shfl) ---------------------
__device__ __forceinline__ float rope_pair(float a, const float* __restrict__ petab,
                                           int tok, int d)
{
    float b = __shfl_xor_sync(0xffffffffu, a, 1);
    int i = d >> 1;
    const float* p = petab + ((size_t)tok * 64 + i) * 4;
    if ((d & 1) == 0) return fmaf(p[0], a, p[1] * b);
    else              return fmaf(p[2], b, p[3] * a);
}

// ---------------- attention prep for x tokens ------------------------------
__global__ void __launch_bounds__(128) attn_prep1(
    const float* __restrict__ pe, const float* __restrict__ cpe,
    const float* __restrict__ q_scale, const float* __restrict__ k_scale)
{
    __shared__ float sbuf[4];
    int t = blockIdx.x, h = blockIdx.y, d = threadIdx.x;
    const float* hrow = g_h + (size_t)t * QKVW;
    float q = hrow[h * HDIM + d];
    float k = hrow[HIDDEN + h * HDIM + d];
    float v = hrow[2 * HIDDEN + h * HDIM + d];
    float msq = block_sum<128>(q * q, sbuf) * (1.f / 128.f);
    float msk = block_sum<128>(k * k, sbuf) * (1.f / 128.f);
    float qn = q * rsqrtf(msq + 1e-6f) * q_scale[d];
    float kn = k * rsqrtf(msk + 1e-6f) * k_scale[d];
    float qr = rope_pair(qn, pe, t, d);
    float kr = rope_pair(kn, pe, t, d);
    bf16 hh, ll;
    size_t qi = ((size_t)h * LX + t) * HDIM + d;
    split1(qr, hh, ll); g_q1h[qi] = hh; g_q1l[qi] = ll;
    split1(kr, hh, ll); g_k1h[qi] = hh; g_k1l[qi] = ll;
    split1(v,  hh, ll); g_v1h[qi] = hh; g_v1l[qi] = ll;
    if (t >= TXT) {
        int j = NC + (t - TXT);
        g_k2[((size_t)h * LC + j) * HDIM + d] = rope_pair(kn, cpe, j, d);
        g_vt2[((size_t)h * HDIM + d) * LC + j] = v;
    }
}

// ---------------- attention prep for concept tokens ------------------------
__global__ void __launch_bounds__(128) attn_prep2(
    const float* __restrict__ cpe,
    const float* __restrict__ q_scale, const float* __restrict__ k_scale)
{
    __shared__ float sbuf[4];
    int i = blockIdx.x, h = blockIdx.y, d = threadIdx.x;
    const float* hrow = g_h + (size_t)(LX + i) * QKVW;
    float q = hrow[h * HDIM + d];
    float k = hrow[HIDDEN + h * HDIM + d];
    float v = hrow[2 * HIDDEN + h * HDIM + d];
    float msq = block_sum<128>(q * q, sbuf) * (1.f / 128.f);
    float msk = block_sum<128>(k * k, sbuf) * (1.f / 128.f);
    float qn = q * rsqrtf(msq + 1e-6f) * q_scale[d];
    float kn = k * rsqrtf(msk + 1e-6f) * k_scale[d];
    g_q2[((size_t)h * NC + i) * HDIM + d] = rope_pair(qn, cpe, i, d);
    g_k2[((size_t)h * LC + i) * HDIM + d] = rope_pair(kn, cpe, i, d);
    g_vt2[((size_t)h * HDIM + d) * LC + i] = v;
}

// ---------------- row softmax (block-2 path) -------------------------------
__global__ void __launch_bounds__(256) softmax_rows(float* __restrict__ S, int ncol)
{
    __shared__ float sbuf[8];
    float* row = S + (size_t)blockIdx.x * ncol;
    int tid = threadIdx.x;
    float v[17];
    float mx = -1e30f;
    #pragma unroll
    for (int i = 0; i < 17; i++) {
        int c = tid + 256 * i;
        v[i] = (c < ncol) ? row[c] : -1e30f;
        mx = fmaxf(mx, v[i]);
    }
    mx = block_max<256>(mx, sbuf);
    float s = 0.f;
    #pragma unroll
    for (int i = 0; i < 17; i++) { v[i] = __expf(v[i] - mx); s += v[i]; }
    s = block_sum<256>(s, sbuf);
    float inv = 1.f / s;
    #pragma unroll
    for (int i = 0; i < 17; i++) {
        int c = tid + 256 * i;
        if (c < ncol) row[c] = v[i] * inv;
    }
}

// ---------------- residual: out = base + gate * block_out ------------------
__global__ void __launch_bounds__(256) final_kernel(
    const float* __restrict__ x, const float* __restrict__ concepts,
    float* __restrict__ out)
{
    size_t idx = (size_t)blockIdx.x * 256 + threadIdx.x;
    if (idx >= (size_t)NROWS * HIDDEN) return;
    int c = (int)(idx % HIDDEN);
    size_t r = idx / HIDDEN;
    float base = (r < LX) ? x[idx] : concepts[idx - (size_t)LX * HIDDEN];
    out[idx] = fmaf(g_mod[2 * HIDDEN + c], g_out[idx], base);
}

// ---------------------------------------------------------------------------
extern "C" void kernel_launch(void* const* d_in, const int* in_sizes, int n_in,
                              void* d_out, int out_size)
{
    const float* x        = (const float*)d_in[0];
    const float* concepts = (const float*)d_in[1];
    const float* vec      = (const float*)d_in[2];
    const float* pe       = (const float*)d_in[3];
    const float* cpe      = (const float*)d_in[4];
    const float* w1       = (const float*)d_in[5];
    const float* b1       = (const float*)d_in[6];
    const float* w2       = (const float*)d_in[7];
    const float* b2       = (const float*)d_in[8];
    const float* q_scale  = (const float*)d_in[9];
    const float* k_scale  = (const float*)d_in[10];
    const float* mod_w    = (const float*)d_in[11];
    const float* mod_b    = (const float*)d_in[12];
    float* out = (float*)d_out;

    void* p;
    cudaGetSymbolAddress(&p, g_xmh);  bf16* xmh = (bf16*)p;
    cudaGetSymbolAddress(&p, g_xml);  bf16* xml = (bf16*)p;
    cudaGetSymbolAddress(&p, g_w1h);  bf16* w1h = (bf16*)p;
    cudaGetSymbolAddress(&p, g_w1l);  bf16* w1l = (bf16*)p;
    cudaGetSymbolAddress(&p, g_w2h);  bf16* w2h = (bf16*)p;
    cudaGetSymbolAddress(&p, g_w2l);  bf16* w2l = (bf16*)p;
    cudaGetSymbolAddress(&p, g_h);    float* hbuf = (float*)p;
    cudaGetSymbolAddress(&p, g_q1h);  bf16* q1h = (bf16*)p;
    cudaGetSymbolAddress(&p, g_q1l);  bf16* q1l = (bf16*)p;
    cudaGetSymbolAddress(&p, g_k1h);  bf16* k1h = (bf16*)p;
    cudaGetSymbolAddress(&p, g_k1l);  bf16* k1l = (bf16*)p;
    cudaGetSymbolAddress(&p, g_v1h);  bf16* v1h = (bf16*)p;
    cudaGetSymbolAddress(&p, g_v1l);  bf16* v1l = (bf16*)p;
    cudaGetSymbolAddress(&p, g_q2);   float* q2b  = (float*)p;
    cudaGetSymbolAddress(&p, g_k2);   float* k2b  = (float*)p;
    cudaGetSymbolAddress(&p, g_vt2);  float* vt2b = (float*)p;
    cudaGetSymbolAddress(&p, g_s2);   float* s2b  = (float*)p;
    cudaGetSymbolAddress(&p, g_cch);  bf16* cch = (bf16*)p;
    cudaGetSymbolAddress(&p, g_ccl);  bf16* ccl = (bf16*)p;
    cudaGetSymbolAddress(&p, g_out);  float* outb = (float*)p;

    cudaFuncSetAttribute(gemm_bf, cudaFuncAttributeMaxDynamicSharedMemorySize,
                         HG_SMEM);
    cudaFuncSetAttribute(flash1, cudaFuncAttributeMaxDynamicSharedMemorySize,
                         FLASH_SMEM);

    const float scl = 0.08838834764831845f;  // 1/sqrt(128)

    // modulation vector (shift | scale | gate)
    mod_kernel<<<(3 * HIDDEN + 3) / 4, 128>>>(vec, mod_w, mod_b);
    // weight splitting (hi/lo bf16 planes)
    {
        int n4 = (W1OUT * HIDDEN) / 4;
        convert_split<<<(n4 + 255) / 256, 256>>>(
            (const float4*)w1, (uint2*)w1h, (uint2*)w1l, n4);
        n4 = (HIDDEN * CCW) / 4;
        convert_split<<<(n4 + 255) / 256, 256>>>(
            (const float4*)w2, (uint2*)w2h, (uint2*)w2l, n4);
    }
    // layernorm + modulate -> xm planes
    ln_mod_kernel<<<NROWS, 256>>>(x, concepts);
    // GEMM1: h = xm @ w1^T + b1; qkv cols -> fp32 h, mlp cols -> gelu cc planes
    gemm_bf<<<dim3(W1OUT / 128, (NROWS + 127) / 128), 256, HG_SMEM>>>(
        xmh, xml, HIDDEN, w1h, w1l, HIDDEN,
        hbuf, QKVW, cch, ccl, QKVW,
        NROWS, W1OUT, HIDDEN, b1);
    // rmsnorm + rope -> q/k/v planes (+ block2 fp32 arrays)
    attn_prep1<<<dim3(LX, NHEADS), 128>>>(pe, cpe, q_scale, k_scale);
    attn_prep2<<<dim3(NC, NHEADS), 128>>>(cpe, q_scale, k_scale);
    // block1 fused flash attention -> cc planes cols [0,1536)
    flash1<<<dim3(LX / 128, NHEADS), 256, FLASH_SMEM>>>(
        q1h, q1l, k1h, k1l, v1h, v1l, cch, ccl);
    // block2 attention (20 queries over 4116 keys) — SIMT path
    sgemm_abt<<<dim3((LC + 127) / 128, 1, NHEADS), 256>>>(
        q2b, HDIM, (long long)NC * HDIM, k2b, HDIM, (long long)LC * HDIM,
        s2b, nullptr, nullptr, LC, (long long)NC * LC,
        NC, LC, HDIM, scl, 0);
    softmax_rows<<<NHEADS * NC, 256>>>(s2b, LC);
    sgemm_abt<<<dim3(1, 1, NHEADS), 256>>>(
        s2b, LC, (long long)NC * LC, vt2b, LC, (long long)HDIM * LC,
        nullptr, cch + (size_t)LX * CCW, ccl + (size_t)LX * CCW, CCW, 128,
        NC, HDIM, LC, 1.f, 1);
    // GEMM2: out = cc @ w2^T + b2 (no gelu: gelu_n0 = HIDDEN > all n)
    gemm_bf<<<dim3(HIDDEN / 128, (NROWS + 127) / 128), 256, HG_SMEM>>>(
        cch, ccl, CCW, w2h, w2l, CCW,
        outb, HIDDEN, nullptr, nullptr, HIDDEN,
        NROWS, HIDDEN, CCW, b2);
    // residual + gate
    final_kernel<<<(unsigned)(((size_t)NROWS * HIDDEN + 255) / 256), 256>>>(
        x, concepts, out);
}

// round 7
// speedup vs baseline: 1.6110x; 1.3074x over previous
#include <cuda_runtime.h>
#include <cuda_fp16.h>
#include <math.h>
#include <stdint.h>

#define HIDDEN 1536
#define NHEADS 12
#define HDIM 128
#define MLPH 6144
#define TXT 256
#define LX 4352
#define NC 20
#define LC 4116
#define NROWS 4372          // LX + NC
#define W1OUT 10752         // 3*HIDDEN + MLPH
#define QKVW 4608           // 3*HIDDEN
#define CCW 7680            // HIDDEN + MLPH

typedef __half f16;

// ---------------- scratch (static device globals; no runtime allocation) ---
static __device__ float g_mod[3 * HIDDEN];
static __device__ f16   g_xmh[(size_t)NROWS * HIDDEN];
static __device__ f16   g_xml[(size_t)NROWS * HIDDEN];
static __device__ f16   g_w1h[(size_t)W1OUT * HIDDEN];
static __device__ f16   g_w2h[(size_t)HIDDEN * CCW];
static __device__ float g_h[(size_t)NROWS * QKVW];
static __device__ f16   g_q1h[(size_t)NHEADS * LX * HDIM];
static __device__ f16   g_q1l[(size_t)NHEADS * LX * HDIM];
static __device__ f16   g_k1h[(size_t)NHEADS * LX * HDIM];
static __device__ f16   g_v1h[(size_t)NHEADS * LX * HDIM];
static __device__ float g_q2[(size_t)NHEADS * NC * HDIM];
static __device__ float g_k2[(size_t)NHEADS * LC * HDIM];
static __device__ float g_vt2[(size_t)NHEADS * HDIM * LC];
static __device__ float g_s2[(size_t)NHEADS * NC * LC];
static __device__ f16   g_cch[(size_t)NROWS * CCW];
static __device__ f16   g_ccl[(size_t)NROWS * CCW];
static __device__ float g_out[(size_t)NROWS * HIDDEN];

// ---------------- reductions ----------------------------------------------
__device__ __forceinline__ float warp_sum(float v) {
    #pragma unroll
    for (int o = 16; o > 0; o >>= 1) v += __shfl_xor_sync(0xffffffffu, v, o);
    return v;
}
__device__ __forceinline__ float warp_max(float v) {
    #pragma unroll
    for (int o = 16; o > 0; o >>= 1) v = fmaxf(v, __shfl_xor_sync(0xffffffffu, v, o));
    return v;
}
template <int NT>
__device__ __forceinline__ float block_sum(float v, float* sbuf) {
    v = warp_sum(v);
    int lane = threadIdx.x & 31, w = threadIdx.x >> 5;
    if (lane == 0) sbuf[w] = v;
    __syncthreads();
    if (threadIdx.x < 32) {
        float x = (threadIdx.x < NT / 32) ? sbuf[threadIdx.x] : 0.f;
        x = warp_sum(x);
        if (threadIdx.x == 0) sbuf[0] = x;
    }
    __syncthreads();
    float r = sbuf[0];
    __syncthreads();
    return r;
}
template <int NT>
__device__ __forceinline__ float block_max(float v, float* sbuf) {
    v = warp_max(v);
    int lane = threadIdx.x & 31, w = threadIdx.x >> 5;
    if (lane == 0) sbuf[w] = v;
    __syncthreads();
    if (threadIdx.x < 32) {
        float x = (threadIdx.x < NT / 32) ? sbuf[threadIdx.x] : -1e30f;
        x = warp_max(x);
        if (threadIdx.x == 0) sbuf[0] = x;
    }
    __syncthreads();
    float r = sbuf[0];
    __syncthreads();
    return r;
}

// ---------------- fp16 split helpers ---------------------------------------
__device__ __forceinline__ void split1(float v, f16& h, f16& l) {
    h = __float2half_rn(v);
    l = __float2half_rn(v - __half2float(h));
}
__device__ __forceinline__ void split2(float x, float y, uint32_t& h, uint32_t& l) {
    f16 hx, lx, hy, ly;
    split1(x, hx, lx); split1(y, hy, ly);
    __half2 hh = __halves2half2(hx, hy), ll = __halves2half2(lx, ly);
    h = *reinterpret_cast<uint32_t*>(&hh);
    l = *reinterpret_cast<uint32_t*>(&ll);
}
__device__ __forceinline__ float gelu_f(float xv) {
    float inner = 0.7978845608028654f * fmaf(0.044715f * xv * xv, xv, xv);
    return 0.5f * xv * (1.f + tanhf(inner));
}

// ======================= HMMA helpers ======================================
__device__ __forceinline__ uint32_t smem_u32(const void* p) {
    uint32_t a;
    asm("{ .reg .u64 t; cvta.to.shared.u64 t, %1; cvt.u32.u64 %0, t; }"
        : "=r"(a) : "l"(p));
    return a;
}
__device__ __forceinline__ void ldsm4(uint32_t* r, uint32_t addr) {
    asm volatile("ldmatrix.sync.aligned.m8n8.x4.shared.b16 {%0,%1,%2,%3}, [%4];"
                 : "=r"(r[0]), "=r"(r[1]), "=r"(r[2]), "=r"(r[3]) : "r"(addr));
}
__device__ __forceinline__ void ldsm4t(uint32_t* r, uint32_t addr) {
    asm volatile("ldmatrix.sync.aligned.m8n8.x4.trans.shared.b16 {%0,%1,%2,%3}, [%4];"
                 : "=r"(r[0]), "=r"(r[1]), "=r"(r[2]), "=r"(r[3]) : "r"(addr));
}
__device__ __forceinline__ void mma_f16(float* c, const uint32_t* a,
                                        uint32_t b0, uint32_t b1) {
    asm volatile(
        "mma.sync.aligned.m16n8k16.row.col.f32.f16.f16.f32 "
        "{%0,%1,%2,%3}, {%4,%5,%6,%7}, {%8,%9}, {%0,%1,%2,%3};"
        : "+f"(c[0]), "+f"(c[1]), "+f"(c[2]), "+f"(c[3])
        : "r"(a[0]), "r"(a[1]), "r"(a[2]), "r"(a[3]), "r"(b0), "r"(b1));
}
__device__ __forceinline__ void cp_async16(uint32_t dst, const void* src, int sz) {
    asm volatile("cp.async.cg.shared.global [%0], [%1], 16, %2;"
                 :: "r"(dst), "l"(src), "r"(sz) : "memory");
}
__device__ __forceinline__ void cp_commit() {
    asm volatile("cp.async.commit_group;" ::: "memory");
}
__device__ __forceinline__ void cp_wait0() {
    asm volatile("cp.async.wait_group 0;" ::: "memory");
}
__device__ __forceinline__ void cp_wait1() {
    asm volatile("cp.async.wait_group 1;" ::: "memory");
}
__device__ __forceinline__ void cp_wait2() {
    asm volatile("cp.async.wait_group 2;" ::: "memory");
}

// smem: per stage 3 tiles (Ah, Al, Bh): 128 rows x 32 f16, row stride 80 B
#define SPB      80
#define T_BYTES  (128 * SPB)          // 10240
#define STAGE_B  (3 * T_BYTES)        // 30720
#define NSTAGE   3
#define HG_SMEM  (NSTAGE * STAGE_B)   // 92160 -> 2 CTAs/SM

// ======== fp16 2-product GEMM: C = A@B^T + bias  (A split hi/lo, B hi) =====
// Columns n >= gelu_n0: bias+gelu, split-written to Gh/Gl at col
// HIDDEN + n - gelu_n0 (stride CCW). Columns n < gelu_n0: fp32 to C (ldc).
__global__ void __launch_bounds__(256, 2) gemm_f16(
    const f16* __restrict__ Ah, const f16* __restrict__ Al, int lda,
    const f16* __restrict__ Bh, int ldb,
    float* __restrict__ C, int ldc,
    f16* __restrict__ Gh, f16* __restrict__ Gl, int gelu_n0,
    int M, int N, int K, const float* __restrict__ bias)
{
    extern __shared__ char smem[];
    uint32_t sbase = smem_u32(smem);
    int tid = threadIdx.x, wid = tid >> 5, lane = tid & 31;

    // supertile swizzle for L2 reuse
    const int GRP = 8;
    int npn = gridDim.x, npm = gridDim.y;
    int pid = blockIdx.y * npn + blockIdx.x;
    int gsz = GRP * npn;
    int gid = pid / gsz;
    int fm = gid * GRP;
    int gm = min(GRP, npm - fm);
    int pid_m = fm + (pid % gsz) % gm;
    int pid_n = (pid % gsz) / gm;
    int m0 = pid_m * 128, n0 = pid_n * 128;

    int warp_m = wid & 3;
    int warp_n = wid >> 2;
    int lrow = lane & 15, lhalf = lane >> 4;

    uint32_t a_off[2], b_off[4];
    #pragma unroll
    for (int i = 0; i < 2; ++i)
        a_off[i] = (uint32_t)((warp_m * 32 + i * 16 + lrow) * SPB + lhalf * 16);
    #pragma unroll
    for (int g = 0; g < 4; ++g)
        b_off[g] = (uint32_t)((warp_n * 64 + g * 16 + lrow) * SPB + lhalf * 16);

    float acc[2][8][4];
    #pragma unroll
    for (int i = 0; i < 2; ++i)
        #pragma unroll
        for (int j = 0; j < 8; ++j)
            #pragma unroll
            for (int t = 0; t < 4; ++t) acc[i][j][t] = 0.f;

    int nch = K >> 5;

    // cp.async producer: 6x 16B units per thread (1536 units/stage)
    auto issue = [&](int c) {
        if (c < nch) {
            int kc = c << 5;
            uint32_t sb = sbase + (uint32_t)(c % NSTAGE) * STAGE_B;
            #pragma unroll
            for (int u6 = 0; u6 < 6; ++u6) {
                int u = tid + 256 * u6;
                int tile = u >> 9;              // 0=Ah,1=Al,2=Bh
                int r = (u >> 2) & 127;
                int c16 = u & 3;
                uint32_t dst = sb + (uint32_t)(tile * T_BYTES + r * SPB + c16 * 16);
                if (tile == 0) {
                    int sz = (m0 + r < M) ? 16 : 0;
                    cp_async16(dst, Ah + (size_t)(m0 + r) * lda + kc + c16 * 8, sz);
                } else if (tile == 1) {
                    int sz = (m0 + r < M) ? 16 : 0;
                    cp_async16(dst, Al + (size_t)(m0 + r) * lda + kc + c16 * 8, sz);
                } else {
                    cp_async16(dst, Bh + (size_t)(n0 + r) * ldb + kc + c16 * 8, 16);
                }
            }
        }
        cp_commit();
    };

    issue(0); issue(1); issue(2);

    for (int c = 0; c < nch; ++c) {
        cp_wait2();
        __syncthreads();
        uint32_t sb = sbase + (uint32_t)(c % NSTAGE) * STAGE_B;
        #pragma unroll
        for (int k16 = 0; k16 < 2; ++k16) {
            uint32_t koff = (uint32_t)(k16 * 32);
            uint32_t ah[2][4], al[2][4], bh[4][4];
            #pragma unroll
            for (int i = 0; i < 2; ++i) {
                ldsm4(ah[i], sb + 0 * T_BYTES + a_off[i] + koff);
                ldsm4(al[i], sb + 1 * T_BYTES + a_off[i] + koff);
            }
            #pragma unroll
            for (int g = 0; g < 4; ++g)
                ldsm4(bh[g], sb + 2 * T_BYTES + b_off[g] + koff);
            #pragma unroll
            for (int i = 0; i < 2; ++i)
                #pragma unroll
                for (int j = 0; j < 8; ++j) {
                    int g = j >> 1, sI = j & 1;
                    mma_f16(acc[i][j], ah[i], bh[g][sI], bh[g][sI + 2]);
                }
            #pragma unroll
            for (int i = 0; i < 2; ++i)
                #pragma unroll
                for (int j = 0; j < 8; ++j) {
                    int g = j >> 1, sI = j & 1;
                    mma_f16(acc[i][j], al[i], bh[g][sI], bh[g][sI + 2]);
                }
        }
        __syncthreads();
        issue(c + NSTAGE);
    }

    // ---- epilogue ----
    int trow = lane >> 2, tc2 = (lane & 3) * 2;
    #pragma unroll
    for (int i = 0; i < 2; ++i) {
        #pragma unroll
        for (int half = 0; half < 2; ++half) {
            int m = m0 + warp_m * 32 + i * 16 + half * 8 + trow;
            if (m >= M) continue;
            #pragma unroll
            for (int j = 0; j < 8; ++j) {
                int n = n0 + warp_n * 64 + j * 8 + tc2;
                float vx = acc[i][j][half * 2 + 0];
                float vy = acc[i][j][half * 2 + 1];
                if (bias) { vx += bias[n]; vy += bias[n + 1]; }
                if (n >= gelu_n0) {
                    vx = gelu_f(vx); vy = gelu_f(vy);
                    int cc = HIDDEN + n - gelu_n0;
                    uint32_t h, l;
                    split2(vx, vy, h, l);
                    *reinterpret_cast<uint32_t*>(Gh + (size_t)m * CCW + cc) = h;
                    *reinterpret_cast<uint32_t*>(Gl + (size_t)m * CCW + cc) = l;
                } else {
                    *reinterpret_cast<float2*>(C + (size_t)m * ldc + n) =
                        make_float2(vx, vy);
                }
            }
        }
    }
}

// ================= flash attention for block 1 =============================
// Q tile 128 rows, KV 64-row double-buffered tiles. Q split hi/lo; K,V hi only.
// P split hi/lo in registers (2-product PV).
#define BK 64
#define FSTR 272                       // 128*2 + 16 pad
#define FQ_PLANE (128 * FSTR)          // 34816
#define FK_PLANE (BK * FSTR)           // 17408
#define FS_OFF   (2 * FQ_PLANE)        // 69632
#define FSTAGE   (2 * FK_PLANE)        // 34816 (K hi + V hi)
#define FLASH_SMEM (FS_OFF + 2 * FSTAGE)  // 139264
#define NKT (LX / BK)                  // 68

__global__ void __launch_bounds__(256, 1) flash1(
    const f16* __restrict__ Qh, const f16* __restrict__ Ql,
    const f16* __restrict__ Kh, const f16* __restrict__ Vh,
    f16* __restrict__ Och, f16* __restrict__ Ocl)
{
    extern __shared__ char smem[];
    uint32_t sbase = smem_u32(smem);
    int tid = threadIdx.x, wid = tid >> 5, lane = tid & 31;
    int head = blockIdx.y;
    int q0 = blockIdx.x * 128;
    size_t hb = (size_t)head * LX * HDIM;
    const f16* qp0 = Qh + hb + (size_t)q0 * HDIM;
    const f16* qp1 = Ql + hb + (size_t)q0 * HDIM;
    const f16* kp[2] = { Kh + hb, Vh + hb };

    #pragma unroll
    for (int u8 = 0; u8 < 16; ++u8) {
        int u = tid + 256 * u8;
        int pl = u >> 11, r = (u >> 4) & 127, c = u & 15;
        const f16* src = (pl ? qp1 : qp0) + (size_t)r * HDIM + c * 8;
        cp_async16(sbase + (uint32_t)(pl * FQ_PLANE + r * FSTR + c * 16), src, 16);
    }
    cp_commit();

    auto issueKV = [&](int it) {
        int kv0 = it * BK;
        #pragma unroll
        for (int u8 = 0; u8 < 8; ++u8) {
            int u = tid + 256 * u8;
            int pl = u >> 10, r = (u >> 4) & 63, c = u & 15;
            cp_async16(sbase + (uint32_t)(FS_OFF + (it & 1) * FSTAGE +
                                          pl * FK_PLANE + r * FSTR + c * 16),
                       kp[pl] + (size_t)(kv0 + r) * HDIM + c * 8, 16);
        }
        cp_commit();
    };
    issueKV(0);
    issueKV(1);

    uint32_t a_addr = sbase + (uint32_t)((wid * 16 + (lane & 15)) * FSTR +
                                         (lane >> 4) * 16);
    uint32_t bk_rel = (uint32_t)((lane & 15) * FSTR + (lane >> 4) * 16);
    uint32_t bv_rel = (uint32_t)(((((lane >> 3) & 1) * 8) + (lane & 7)) * FSTR +
                                 ((lane >> 4) & 1) * 16);

    float accO[16][4];
    #pragma unroll
    for (int j = 0; j < 16; ++j)
        #pragma unroll
        for (int t = 0; t < 4; ++t) accO[j][t] = 0.f;
    float mrow0 = -1e30f, mrow1 = -1e30f, lsum0 = 0.f, lsum1 = 0.f;
    const float scl = 0.08838834764831845f;

    for (int it = 0; it < NKT; ++it) {
        if (it < NKT - 1) cp_wait1(); else cp_wait0();
        __syncthreads();
        uint32_t kb = sbase + FS_OFF + (uint32_t)(it & 1) * FSTAGE;

        float s[8][4];
        #pragma unroll
        for (int j = 0; j < 8; ++j)
            #pragma unroll
            for (int t = 0; t < 4; ++t) s[j][t] = 0.f;
        #pragma unroll
        for (int ks = 0; ks < 8; ++ks) {
            uint32_t aqh[4], aql[4];
            ldsm4(aqh, a_addr + ks * 32);
            ldsm4(aql, a_addr + FQ_PLANE + ks * 32);
            uint32_t bh[4][4];
            #pragma unroll
            for (int g = 0; g < 4; ++g)
                ldsm4(bh[g], kb + bk_rel + g * (16 * FSTR) + ks * 32);
            #pragma unroll
            for (int j = 0; j < 8; ++j)
                mma_f16(s[j], aqh, bh[j >> 1][j & 1], bh[j >> 1][(j & 1) + 2]);
            #pragma unroll
            for (int j = 0; j < 8; ++j)
                mma_f16(s[j], aql, bh[j >> 1][j & 1], bh[j >> 1][(j & 1) + 2]);
        }

        float m0 = -1e30f, m1 = -1e30f;
        #pragma unroll
        for (int j = 0; j < 8; ++j) {
            s[j][0] *= scl; s[j][1] *= scl; s[j][2] *= scl; s[j][3] *= scl;
            m0 = fmaxf(m0, fmaxf(s[j][0], s[j][1]));
            m1 = fmaxf(m1, fmaxf(s[j][2], s[j][3]));
        }
        m0 = fmaxf(m0, __shfl_xor_sync(0xffffffffu, m0, 1));
        m0 = fmaxf(m0, __shfl_xor_sync(0xffffffffu, m0, 2));
        m1 = fmaxf(m1, __shfl_xor_sync(0xffffffffu, m1, 1));
        m1 = fmaxf(m1, __shfl_xor_sync(0xffffffffu, m1, 2));
        float mn0 = fmaxf(mrow0, m0), mn1 = fmaxf(mrow1, m1);
        float al0 = __expf(mrow0 - mn0), al1 = __expf(mrow1 - mn1);
        mrow0 = mn0; mrow1 = mn1;

        uint32_t ph[8][2], plo[8][2];
        float ps0 = 0.f, ps1 = 0.f;
        #pragma unroll
        for (int j = 0; j < 8; ++j) {
            float p00 = __expf(s[j][0] - mn0), p01 = __expf(s[j][1] - mn0);
            float p10 = __expf(s[j][2] - mn1), p11 = __expf(s[j][3] - mn1);
            ps0 += p00 + p01; ps1 += p10 + p11;
            split2(p00, p01, ph[j][0], plo[j][0]);
            split2(p10, p11, ph[j][1], plo[j][1]);
        }
        lsum0 = lsum0 * al0 + ps0;
        lsum1 = lsum1 * al1 + ps1;
        #pragma unroll
        for (int j = 0; j < 16; ++j) {
            accO[j][0] *= al0; accO[j][1] *= al0;
            accO[j][2] *= al1; accO[j][3] *= al1;
        }

        uint32_t vb = kb + FK_PLANE;
        #pragma unroll
        for (int s4 = 0; s4 < 4; ++s4) {
            uint32_t Ahf[4] = { ph[2 * s4][0], ph[2 * s4][1],
                                ph[2 * s4 + 1][0], ph[2 * s4 + 1][1] };
            uint32_t Alf[4] = { plo[2 * s4][0], plo[2 * s4][1],
                                plo[2 * s4 + 1][0], plo[2 * s4 + 1][1] };
            #pragma unroll
            for (int g = 0; g < 8; ++g) {
                uint32_t bvh[4];
                ldsm4t(bvh, vb + bv_rel + s4 * (16 * FSTR) + g * 32);
                mma_f16(accO[2 * g],     Ahf, bvh[0], bvh[1]);
                mma_f16(accO[2 * g + 1], Ahf, bvh[2], bvh[3]);
                mma_f16(accO[2 * g],     Alf, bvh[0], bvh[1]);
                mma_f16(accO[2 * g + 1], Alf, bvh[2], bvh[3]);
            }
        }
        __syncthreads();
        if (it + 2 < NKT) issueKV(it + 2);
    }

    lsum0 += __shfl_xor_sync(0xffffffffu, lsum0, 1);
    lsum0 += __shfl_xor_sync(0xffffffffu, lsum0, 2);
    lsum1 += __shfl_xor_sync(0xffffffffu, lsum1, 1);
    lsum1 += __shfl_xor_sync(0xffffffffu, lsum1, 2);
    float inv0 = 1.f / lsum0, inv1 = 1.f / lsum1;
    int r0 = q0 + wid * 16 + (lane >> 2);
    int cbase = head * HDIM + (lane & 3) * 2;
    #pragma unroll
    for (int j = 0; j < 16; ++j) {
        int c = cbase + j * 8;
        uint32_t h, l;
        split2(accO[j][0] * inv0, accO[j][1] * inv0, h, l);
        *reinterpret_cast<uint32_t*>(Och + (size_t)r0 * CCW + c) = h;
        *reinterpret_cast<uint32_t*>(Ocl + (size_t)r0 * CCW + c) = l;
        split2(accO[j][2] * inv1, accO[j][3] * inv1, h, l);
        *reinterpret_cast<uint32_t*>(Och + (size_t)(r0 + 8) * CCW + c) = h;
        *reinterpret_cast<uint32_t*>(Ocl + (size_t)(r0 + 8) * CCW + c) = l;
    }
}

// ---------------- SIMT GEMM for tiny block-2 attention ---------------------
__global__ void __launch_bounds__(256) sgemm_abt(
    const float* __restrict__ A, int lda, long long sA,
    const float* __restrict__ B, int ldb, long long sB,
    float* __restrict__ C, f16* __restrict__ Ch, f16* __restrict__ Cl,
    int ldc, long long sC,
    int M, int N, int K, float alpha, int splitout)
{
    __shared__ float As[8][128];
    __shared__ float Bs[8][128];
    int bz = blockIdx.z;
    A += (size_t)sA * bz;
    B += (size_t)sB * bz;
    if (splitout) { Ch += (size_t)sC * bz; Cl += (size_t)sC * bz; }
    else C += (size_t)sC * bz;
    int m0 = blockIdx.y * 128;
    int n0 = blockIdx.x * 128;
    int tid = threadIdx.x;
    int tx = tid & 15, ty = tid >> 4;
    int lrow = tid >> 1;
    int lcol = (tid & 1) * 4;

    float acc[8][8];
    #pragma unroll
    for (int i = 0; i < 8; i++)
        #pragma unroll
        for (int j = 0; j < 8; j++) acc[i][j] = 0.f;

    for (int k0 = 0; k0 < K; k0 += 8) {
        float4 av = make_float4(0.f, 0.f, 0.f, 0.f);
        float4 bv = make_float4(0.f, 0.f, 0.f, 0.f);
        if (m0 + lrow < M && k0 + lcol < K)
            av = *reinterpret_cast<const float4*>(A + (size_t)(m0 + lrow) * lda + k0 + lcol);
        if (n0 + lrow < N && k0 + lcol < K)
            bv = *reinterpret_cast<const float4*>(B + (size_t)(n0 + lrow) * ldb + k0 + lcol);
        As[lcol + 0][lrow] = av.x; As[lcol + 1][lrow] = av.y;
        As[lcol + 2][lrow] = av.z; As[lcol + 3][lrow] = av.w;
        Bs[lcol + 0][lrow] = bv.x; Bs[lcol + 1][lrow] = bv.y;
        Bs[lcol + 2][lrow] = bv.z; Bs[lcol + 3][lrow] = bv.w;
        __syncthreads();
        #pragma unroll
        for (int k = 0; k < 8; k++) {
            float ra[8], rb[8];
            #pragma unroll
            for (int i = 0; i < 8; i++) ra[i] = As[k][ty + 16 * i];
            #pragma unroll
            for (int j = 0; j < 8; j++) rb[j] = Bs[k][tx + 16 * j];
            #pragma unroll
            for (int i = 0; i < 8; i++)
                #pragma unroll
                for (int j = 0; j < 8; j++)
                    acc[i][j] = fmaf(ra[i], rb[j], acc[i][j]);
        }
        __syncthreads();
    }

    #pragma unroll
    for (int i = 0; i < 8; i++) {
        int m = m0 + ty + 16 * i;
        if (m >= M) continue;
        #pragma unroll
        for (int j = 0; j < 8; j++) {
            int n = n0 + tx + 16 * j;
            if (n >= N) continue;
            float v = alpha * acc[i][j];
            if (splitout) {
                f16 h, l;
                split1(v, h, l);
                Ch[(size_t)m * ldc + n] = h;
                Cl[(size_t)m * ldc + n] = l;
            } else {
                C[(size_t)m * ldc + n] = v;
            }
        }
    }
}

// ---------------- convert fp32 -> fp16 hi plane ----------------------------
__global__ void __launch_bounds__(256) convert_h(
    const float4* __restrict__ src, uint2* __restrict__ h, int n4)
{
    int idx = blockIdx.x * 256 + threadIdx.x;
    if (idx >= n4) return;
    float4 v = src[idx];
    __half2 a = __halves2half2(__float2half_rn(v.x), __float2half_rn(v.y));
    __half2 b = __halves2half2(__float2half_rn(v.z), __float2half_rn(v.w));
    uint2 r;
    r.x = *reinterpret_cast<uint32_t*>(&a);
    r.y = *reinterpret_cast<uint32_t*>(&b);
    h[idx] = r;
}

// ---------------- modulation: m = silu(vec) @ mod_w^T + mod_b --------------
__global__ void __launch_bounds__(128) mod_kernel(
    const float* __restrict__ vec, const float* __restrict__ mod_w,
    const float* __restrict__ mod_b)
{
    int n = blockIdx.x * 4 + (threadIdx.x >> 5);
    if (n >= 3 * HIDDEN) return;
    int lane = threadIdx.x & 31;
    const float* wrow = mod_w + (size_t)n * HIDDEN;
    float acc = 0.f;
    for (int k = lane; k < HIDDEN; k += 32) {
        float xv = vec[k];
        float s = xv / (1.f + __expf(-xv));
        acc = fmaf(s, wrow[k], acc);
    }
    acc = warp_sum(acc);
    if (lane == 0) g_mod[n] = acc + mod_b[n];
}

// ---------------- layernorm + modulate -> fp16 split planes ----------------
__global__ void __launch_bounds__(256) ln_mod_kernel(
    const float* __restrict__ x, const float* __restrict__ concepts)
{
    __shared__ float sbuf[8];
    int row = blockIdx.x;
    const float* src = (row < LX) ? (x + (size_t)row * HIDDEN)
                                  : (concepts + (size_t)(row - LX) * HIDDEN);
    int tid = threadIdx.x;
    float v[6];
    float s = 0.f;
    #pragma unroll
    for (int i = 0; i < 6; i++) { v[i] = src[tid + 256 * i]; s += v[i]; }
    s = block_sum<256>(s, sbuf);
    float mu = s * (1.0f / 1536.0f);
    float s2 = 0.f;
    #pragma unroll
    for (int i = 0; i < 6; i++) { float d = v[i] - mu; s2 = fmaf(d, d, s2); }
    s2 = block_sum<256>(s2, sbuf);
    float rstd = rsqrtf(s2 * (1.0f / 1536.0f) + 1e-6f);
    #pragma unroll
    for (int i = 0; i < 6; i++) {
        int j = tid + 256 * i;
        float val = (1.f + g_mod[HIDDEN + j]) * ((v[i] - mu) * rstd) + g_mod[j];
        f16 h, l;
        split1(val, h, l);
        g_xmh[(size_t)row * HIDDEN + j] = h;
        g_xml[(size_t)row * HIDDEN + j] = l;
    }
}

// ---------------- RoPE helper (pair exchange via shfl) ---------------------
__device__ __forceinline__ float rope_pair(float a, const float* __restrict__ petab,
                                           int tok, int d)
{
    float b = __shfl_xor_sync(0xffffffffu, a, 1);
    int i = d >> 1;
    const float* p = petab + ((size_t)tok * 64 + i) * 4;
    if ((d & 1) == 0) return fmaf(p[0], a, p[1] * b);
    else              return fmaf(p[2], b, p[3] * a);
}

// ---------------- attention prep for x tokens ------------------------------
__global__ void __launch_bounds__(128) attn_prep1(
    const float* __restrict__ pe, const float* __restrict__ cpe,
    const float* __restrict__ q_scale, const float* __restrict__ k_scale)
{
    __shared__ float sbuf[4];
    int t = blockIdx.x, h = blockIdx.y, d = threadIdx.x;
    const float* hrow = g_h + (size_t)t * QKVW;
    float q = hrow[h * HDIM + d];
    float k = hrow[HIDDEN + h * HDIM + d];
    float v = hrow[2 * HIDDEN + h * HDIM + d];
    float msq = block_sum<128>(q * q, sbuf) * (1.f / 128.f);
    float msk = block_sum<128>(k * k, sbuf) * (1.f / 128.f);
    float qn = q * rsqrtf(msq + 1e-6f) * q_scale[d];
    float kn = k * rsqrtf(msk + 1e-6f) * k_scale[d];
    float qr = rope_pair(qn, pe, t, d);
    float kr = rope_pair(kn, pe, t, d);
    f16 hh, ll;
    size_t qi = ((size_t)h * LX + t) * HDIM + d;
    split1(qr, hh, ll); g_q1h[qi] = hh; g_q1l[qi] = ll;
    g_k1h[qi] = __float2half_rn(kr);
    g_v1h[qi] = __float2half_rn(v);
    if (t >= TXT) {
        int j = NC + (t - TXT);
        g_k2[((size_t)h * LC + j) * HDIM + d] = rope_pair(kn, cpe, j, d);
        g_vt2[((size_t)h * HDIM + d) * LC + j] = v;
    }
}

// ---------------- attention prep for concept tokens ------------------------
__global__ void __launch_bounds__(128) attn_prep2(
    const float* __restrict__ cpe,
    const float* __restrict__ q_scale, const float* __restrict__ k_scale)
{
    __shared__ float sbuf[4];
    int i = blockIdx.x, h = blockIdx.y, d = threadIdx.x;
    const float* hrow = g_h + (size_t)(LX + i) * QKVW;
    float q = hrow[h * HDIM + d];
    float k = hrow[HIDDEN + h * HDIM + d];
    float v = hrow[2 * HIDDEN + h * HDIM + d];
    float msq = block_sum<128>(q * q, sbuf) * (1.f / 128.f);
    float msk = block_sum<128>(k * k, sbuf) * (1.f / 128.f);
    float qn = q * rsqrtf(msq + 1e-6f) * q_scale[d];
    float kn = k * rsqrtf(msk + 1e-6f) * k_scale[d];
    g_q2[((size_t)h * NC + i) * HDIM + d] = rope_pair(qn, cpe, i, d);
    g_k2[((size_t)h * LC + i) * HDIM + d] = rope_pair(kn, cpe, i, d);
    g_vt2[((size_t)h * HDIM + d) * LC + i] = v;
}

// ---------------- row softmax (block-2 path) -------------------------------
__global__ void __launch_bounds__(256) softmax_rows(float* __restrict__ S, int ncol)
{
    __shared__ float sbuf[8];
    float* row = S + (size_t)blockIdx.x * ncol;
    int tid = threadIdx.x;
    float v[17];
    float mx = -1e30f;
    #pragma unroll
    for (int i = 0; i < 17; i++) {
        int c = tid + 256 * i;
        v[i] = (c < ncol) ? row[c] : -1e30f;
        mx = fmaxf(mx, v[i]);
    }
    mx = block_max<256>(mx, sbuf);
    float s = 0.f;
    #pragma unroll
    for (int i = 0; i < 17; i++) { v[i] = __expf(v[i] - mx); s += v[i]; }
    s = block_sum<256>(s, sbuf);
    float inv = 1.f / s;
    #pragma unroll
    for (int i = 0; i < 17; i++) {
        int c = tid + 256 * i;
        if (c < ncol) row[c] = v[i] * inv;
    }
}

// ---------------- residual: out = base + gate * block_out ------------------
__global__ void __launch_bounds__(256) final_kernel(
    const float* __restrict__ x, const float* __restrict__ concepts,
    float* __restrict__ out)
{
    size_t idx = (size_t)blockIdx.x * 256 + threadIdx.x;
    if (idx >= (size_t)NROWS * HIDDEN) return;
    int c = (int)(idx % HIDDEN);
    size_t r = idx / HIDDEN;
    float base = (r < LX) ? x[idx] : concepts[idx - (size_t)LX * HIDDEN];
    out[idx] = fmaf(g_mod[2 * HIDDEN + c], g_out[idx], base);
}

// ---------------------------------------------------------------------------
extern "C" void kernel_launch(void* const* d_in, const int* in_sizes, int n_in,
                              void* d_out, int out_size)
{
    const float* x        = (const float*)d_in[0];
    const float* concepts = (const float*)d_in[1];
    const float* vec      = (const float*)d_in[2];
    const float* pe       = (const float*)d_in[3];
    const float* cpe      = (const float*)d_in[4];
    const float* w1       = (const float*)d_in[5];
    const float* b1       = (const float*)d_in[6];
    const float* w2       = (const float*)d_in[7];
    const float* b2       = (const float*)d_in[8];
    const float* q_scale  = (const float*)d_in[9];
    const float* k_scale  = (const float*)d_in[10];
    const float* mod_w    = (const float*)d_in[11];
    const float* mod_b    = (const float*)d_in[12];
    float* out = (float*)d_out;

    void* p;
    cudaGetSymbolAddress(&p, g_xmh);  f16* xmh = (f16*)p;
    cudaGetSymbolAddress(&p, g_xml);  f16* xml = (f16*)p;
    cudaGetSymbolAddress(&p, g_w1h);  f16* w1h = (f16*)p;
    cudaGetSymbolAddress(&p, g_w2h);  f16* w2h = (f16*)p;
    cudaGetSymbolAddress(&p, g_h);    float* hbuf = (float*)p;
    cudaGetSymbolAddress(&p, g_q1h);  f16* q1h = (f16*)p;
    cudaGetSymbolAddress(&p, g_q1l);  f16* q1l = (f16*)p;
    cudaGetSymbolAddress(&p, g_k1h);  f16* k1h = (f16*)p;
    cudaGetSymbolAddress(&p, g_v1h);  f16* v1h = (f16*)p;
    cudaGetSymbolAddress(&p, g_q2);   float* q2b  = (float*)p;
    cudaGetSymbolAddress(&p, g_k2);   float* k2b  = (float*)p;
    cudaGetSymbolAddress(&p, g_vt2);  float* vt2b = (float*)p;
    cudaGetSymbolAddress(&p, g_s2);   float* s2b  = (float*)p;
    cudaGetSymbolAddress(&p, g_cch);  f16* cch = (f16*)p;
    cudaGetSymbolAddress(&p, g_ccl);  f16* ccl = (f16*)p;
    cudaGetSymbolAddress(&p, g_out);  float* outb = (float*)p;

    cudaFuncSetAttribute(gemm_f16, cudaFuncAttributeMaxDynamicSharedMemorySize,
                         HG_SMEM);
    cudaFuncSetAttribute(flash1, cudaFuncAttributeMaxDynamicSharedMemorySize,
                         FLASH_SMEM);

    const float scl = 0.08838834764831845f;  // 1/sqrt(128)

    // modulation vector (shift | scale | gate)
    mod_kernel<<<(3 * HIDDEN + 3) / 4, 128>>>(vec, mod_w, mod_b);
    // weight conversion (fp16 hi plane only)
    {
        int n4 = (W1OUT * HIDDEN) / 4;
        convert_h<<<(n4 + 255) / 256, 256>>>((const float4*)w1, (uint2*)w1h, n4);
        n4 = (HIDDEN * CCW) / 4;
        convert_h<<<(n4 + 255) / 256, 256>>>((const float4*)w2, (uint2*)w2h, n4);
    }
    // layernorm + modulate -> xm planes
    ln_mod_kernel<<<NROWS, 256>>>(x, concepts);
    // GEMM1: h = xm @ w1^T + b1; qkv cols -> fp32 h, mlp cols -> gelu cc planes
    gemm_f16<<<dim3(W1OUT / 128, (NROWS + 127) / 128), 256, HG_SMEM>>>(
        xmh, xml, HIDDEN, w1h, HIDDEN,
        hbuf, QKVW, cch, ccl, QKVW,
        NROWS, W1OUT, HIDDEN, b1);
    // rmsnorm + rope -> q(split)/k/v fp16 (+ block2 fp32 arrays)
    attn_prep1<<<dim3(LX, NHEADS), 128>>>(pe, cpe, q_scale, k_scale);
    attn_prep2<<<dim3(NC, NHEADS), 128>>>(cpe, q_scale, k_scale);
    // block1 fused flash attention -> cc planes cols [0,1536)
    flash1<<<dim3(LX / 128, NHEADS), 256, FLASH_SMEM>>>(
        q1h, q1l, k1h, v1h, cch, ccl);
    // block2 attention (20 queries over 4116 keys) — SIMT path
    sgemm_abt<<<dim3((LC + 127) / 128, 1, NHEADS), 256>>>(
        q2b, HDIM, (long long)NC * HDIM, k2b, HDIM, (long long)LC * HDIM,
        s2b, nullptr, nullptr, LC, (long long)NC * LC,
        NC, LC, HDIM, scl, 0);
    softmax_rows<<<NHEADS * NC, 256>>>(s2b, LC);
    sgemm_abt<<<dim3(1, 1, NHEADS), 256>>>(
        s2b, LC, (long long)NC * LC, vt2b, LC, (long long)HDIM * LC,
        nullptr, cch + (size_t)LX * CCW, ccl + (size_t)LX * CCW, CCW, 128,
        NC, HDIM, LC, 1.f, 1);
    // GEMM2: out = cc @ w2^T + b2
    gemm_f16<<<dim3(HIDDEN / 128, (NROWS + 127) / 128), 256, HG_SMEM>>>(
        cch, ccl, CCW, w2h, CCW,
        outb, HIDDEN, nullptr, nullptr, HIDDEN,
        NROWS, HIDDEN, CCW, b2);
    // residual + gate
    final_kernel<<<(unsigned)(((size_t)NROWS * HIDDEN + 255) / 256), 256>>>(
        x, concepts, out);
}

// round 8
// speedup vs baseline: 2.2377x; 1.3891x over previous
#include <cuda_runtime.h>
#include <cuda_fp16.h>
#include <math.h>
#include <stdint.h>

#define HIDDEN 1536
#define NHEADS 12
#define HDIM 128
#define MLPH 6144
#define TXT 256
#define LX 4352
#define NC 20
#define LC 4116
#define NROWS 4372          // LX + NC
#define W1OUT 10752         // 3*HIDDEN + MLPH
#define QKVW 4608           // 3*HIDDEN
#define CCW 7680            // HIDDEN + MLPH

typedef __half f16;

// ---------------- scratch (static device globals; no runtime allocation) ---
static __device__ float g_mod[3 * HIDDEN];
static __device__ f16   g_xmh[(size_t)NROWS * HIDDEN];
static __device__ f16   g_w1h[(size_t)W1OUT * HIDDEN];
static __device__ f16   g_w2h[(size_t)HIDDEN * CCW];
static __device__ float g_h[(size_t)NROWS * QKVW];
static __device__ f16   g_q1h[(size_t)NHEADS * LX * HDIM];
static __device__ f16   g_k1h[(size_t)NHEADS * LX * HDIM];
static __device__ f16   g_v1h[(size_t)NHEADS * LX * HDIM];
static __device__ float g_q2[(size_t)NHEADS * NC * HDIM];
static __device__ float g_k2[(size_t)NHEADS * LC * HDIM];
static __device__ float g_vt2[(size_t)NHEADS * HDIM * LC];
static __device__ float g_s2[(size_t)NHEADS * NC * LC];
static __device__ f16   g_cch[(size_t)NROWS * CCW];
static __device__ float g_out[(size_t)NROWS * HIDDEN];

// ---------------- reductions ----------------------------------------------
__device__ __forceinline__ float warp_sum(float v) {
    #pragma unroll
    for (int o = 16; o > 0; o >>= 1) v += __shfl_xor_sync(0xffffffffu, v, o);
    return v;
}
__device__ __forceinline__ float warp_max(float v) {
    #pragma unroll
    for (int o = 16; o > 0; o >>= 1) v = fmaxf(v, __shfl_xor_sync(0xffffffffu, v, o));
    return v;
}
template <int NT>
__device__ __forceinline__ float block_sum(float v, float* sbuf) {
    v = warp_sum(v);
    int lane = threadIdx.x & 31, w = threadIdx.x >> 5;
    if (lane == 0) sbuf[w] = v;
    __syncthreads();
    if (threadIdx.x < 32) {
        float x = (threadIdx.x < NT / 32) ? sbuf[threadIdx.x] : 0.f;
        x = warp_sum(x);
        if (threadIdx.x == 0) sbuf[0] = x;
    }
    __syncthreads();
    float r = sbuf[0];
    __syncthreads();
    return r;
}
template <int NT>
__device__ __forceinline__ float block_max(float v, float* sbuf) {
    v = warp_max(v);
    int lane = threadIdx.x & 31, w = threadIdx.x >> 5;
    if (lane == 0) sbuf[w] = v;
    __syncthreads();
    if (threadIdx.x < 32) {
        float x = (threadIdx.x < NT / 32) ? sbuf[threadIdx.x] : -1e30f;
        x = warp_max(x);
        if (threadIdx.x == 0) sbuf[0] = x;
    }
    __syncthreads();
    float r = sbuf[0];
    __syncthreads();
    return r;
}

// ---------------- helpers ---------------------------------------------------
__device__ __forceinline__ uint32_t pack2h(float x, float y) {
    __half2 h = __halves2half2(__float2half_rn(x), __float2half_rn(y));
    return *reinterpret_cast<uint32_t*>(&h);
}
__device__ __forceinline__ float gelu_f(float xv) {
    float inner = 0.7978845608028654f * fmaf(0.044715f * xv * xv, xv, xv);
    return 0.5f * xv * (1.f + tanhf(inner));
}

// ======================= HMMA helpers ======================================
__device__ __forceinline__ uint32_t smem_u32(const void* p) {
    uint32_t a;
    asm("{ .reg .u64 t; cvta.to.shared.u64 t, %1; cvt.u32.u64 %0, t; }"
        : "=r"(a) : "l"(p));
    return a;
}
__device__ __forceinline__ void ldsm4(uint32_t* r, uint32_t addr) {
    asm volatile("ldmatrix.sync.aligned.m8n8.x4.shared.b16 {%0,%1,%2,%3}, [%4];"
                 : "=r"(r[0]), "=r"(r[1]), "=r"(r[2]), "=r"(r[3]) : "r"(addr));
}
__device__ __forceinline__ void ldsm4t(uint32_t* r, uint32_t addr) {
    asm volatile("ldmatrix.sync.aligned.m8n8.x4.trans.shared.b16 {%0,%1,%2,%3}, [%4];"
                 : "=r"(r[0]), "=r"(r[1]), "=r"(r[2]), "=r"(r[3]) : "r"(addr));
}
__device__ __forceinline__ void mma_f16(float* c, const uint32_t* a,
                                        uint32_t b0, uint32_t b1) {
    asm volatile(
        "mma.sync.aligned.m16n8k16.row.col.f32.f16.f16.f32 "
        "{%0,%1,%2,%3}, {%4,%5,%6,%7}, {%8,%9}, {%0,%1,%2,%3};"
        : "+f"(c[0]), "+f"(c[1]), "+f"(c[2]), "+f"(c[3])
        : "r"(a[0]), "r"(a[1]), "r"(a[2]), "r"(a[3]), "r"(b0), "r"(b1));
}
__device__ __forceinline__ void cp_async16(uint32_t dst, const void* src, int sz) {
    asm volatile("cp.async.cg.shared.global [%0], [%1], 16, %2;"
                 :: "r"(dst), "l"(src), "r"(sz) : "memory");
}
__device__ __forceinline__ void cp_commit() {
    asm volatile("cp.async.commit_group;" ::: "memory");
}
__device__ __forceinline__ void cp_wait0() {
    asm volatile("cp.async.wait_group 0;" ::: "memory");
}
__device__ __forceinline__ void cp_wait1() {
    asm volatile("cp.async.wait_group 1;" ::: "memory");
}
__device__ __forceinline__ void cp_wait2() {
    asm volatile("cp.async.wait_group 2;" ::: "memory");
}

// smem: per stage 2 tiles (A, B): 128 rows x 32 f16, row stride 80 B
#define SPB      80
#define T_BYTES  (128 * SPB)          // 10240
#define STAGE_B  (2 * T_BYTES)        // 20480
#define NSTAGE   4
#define HG_SMEM  (NSTAGE * STAGE_B)   // 81920 -> 2 CTAs/SM

// ======== fp16 GEMM: C = A@B^T + bias ======================================
// Columns n >= gelu_n0: bias+gelu, fp16 to Gh at col HIDDEN + n - gelu_n0
// (stride CCW). Columns n < gelu_n0: fp32 to C (ldc).
__global__ void __launch_bounds__(256, 2) gemm_f16(
    const f16* __restrict__ Ah, int lda,
    const f16* __restrict__ Bh, int ldb,
    float* __restrict__ C, int ldc,
    f16* __restrict__ Gh, int gelu_n0,
    int M, int N, int K, const float* __restrict__ bias)
{
    extern __shared__ char smem[];
    uint32_t sbase = smem_u32(smem);
    int tid = threadIdx.x, wid = tid >> 5, lane = tid & 31;

    // supertile swizzle for L2 reuse
    const int GRP = 8;
    int npn = gridDim.x, npm = gridDim.y;
    int pid = blockIdx.y * npn + blockIdx.x;
    int gsz = GRP * npn;
    int gid = pid / gsz;
    int fm = gid * GRP;
    int gm = min(GRP, npm - fm);
    int pid_m = fm + (pid % gsz) % gm;
    int pid_n = (pid % gsz) / gm;
    int m0 = pid_m * 128, n0 = pid_n * 128;

    int warp_m = wid & 3;
    int warp_n = wid >> 2;
    int lrow = lane & 15, lhalf = lane >> 4;

    uint32_t a_off[2], b_off[4];
    #pragma unroll
    for (int i = 0; i < 2; ++i)
        a_off[i] = (uint32_t)((warp_m * 32 + i * 16 + lrow) * SPB + lhalf * 16);
    #pragma unroll
    for (int g = 0; g < 4; ++g)
        b_off[g] = (uint32_t)((warp_n * 64 + g * 16 + lrow) * SPB + lhalf * 16);

    float acc[2][8][4];
    #pragma unroll
    for (int i = 0; i < 2; ++i)
        #pragma unroll
        for (int j = 0; j < 8; ++j)
            #pragma unroll
            for (int t = 0; t < 4; ++t) acc[i][j][t] = 0.f;

    int nch = K >> 5;

    // cp.async producer: 4x 16B units per thread (1024 units/stage)
    auto issue = [&](int c) {
        if (c < nch) {
            int kc = c << 5;
            uint32_t sb = sbase + (uint32_t)(c % NSTAGE) * STAGE_B;
            #pragma unroll
            for (int u4 = 0; u4 < 4; ++u4) {
                int u = tid + 256 * u4;
                int tile = u >> 9;              // 0=A, 1=B
                int r = (u >> 2) & 127;
                int c16 = u & 3;
                uint32_t dst = sb + (uint32_t)(tile * T_BYTES + r * SPB + c16 * 16);
                if (tile == 0) {
                    int sz = (m0 + r < M) ? 16 : 0;
                    cp_async16(dst, Ah + (size_t)(m0 + r) * lda + kc + c16 * 8, sz);
                } else {
                    cp_async16(dst, Bh + (size_t)(n0 + r) * ldb + kc + c16 * 8, 16);
                }
            }
        }
        cp_commit();
    };

    issue(0); issue(1); issue(2);

    for (int c = 0; c < nch; ++c) {
        cp_wait2();
        __syncthreads();
        uint32_t sb = sbase + (uint32_t)(c % NSTAGE) * STAGE_B;
        #pragma unroll
        for (int k16 = 0; k16 < 2; ++k16) {
            uint32_t koff = (uint32_t)(k16 * 32);
            uint32_t ah[2][4], bh[4][4];
            #pragma unroll
            for (int i = 0; i < 2; ++i)
                ldsm4(ah[i], sb + 0 * T_BYTES + a_off[i] + koff);
            #pragma unroll
            for (int g = 0; g < 4; ++g)
                ldsm4(bh[g], sb + 1 * T_BYTES + b_off[g] + koff);
            #pragma unroll
            for (int i = 0; i < 2; ++i)
                #pragma unroll
                for (int j = 0; j < 8; ++j) {
                    int g = j >> 1, sI = j & 1;
                    mma_f16(acc[i][j], ah[i], bh[g][sI], bh[g][sI + 2]);
                }
        }
        __syncthreads();
        issue(c + 3);
    }

    // ---- epilogue ----
    int trow = lane >> 2, tc2 = (lane & 3) * 2;
    #pragma unroll
    for (int i = 0; i < 2; ++i) {
        #pragma unroll
        for (int half = 0; half < 2; ++half) {
            int m = m0 + warp_m * 32 + i * 16 + half * 8 + trow;
            if (m >= M) continue;
            #pragma unroll
            for (int j = 0; j < 8; ++j) {
                int n = n0 + warp_n * 64 + j * 8 + tc2;
                float vx = acc[i][j][half * 2 + 0];
                float vy = acc[i][j][half * 2 + 1];
                if (bias) { vx += bias[n]; vy += bias[n + 1]; }
                if (n >= gelu_n0) {
                    vx = gelu_f(vx); vy = gelu_f(vy);
                    int cc = HIDDEN + n - gelu_n0;
                    *reinterpret_cast<uint32_t*>(Gh + (size_t)m * CCW + cc) =
                        pack2h(vx, vy);
                } else {
                    *reinterpret_cast<float2*>(C + (size_t)m * ldc + n) =
                        make_float2(vx, vy);
                }
            }
        }
    }
}

// ================= flash attention for block 1 =============================
// Q tile 128 rows, KV 64-row double-buffered tiles. Pure fp16 operands,
// fp32 accumulate.
#define BK 64
#define FSTR 272                       // 128*2 + 16 pad
#define FQ_PLANE (128 * FSTR)          // 34816
#define FK_PLANE (BK * FSTR)           // 17408
#define FS_OFF   FQ_PLANE              // 34816
#define FSTAGE   (2 * FK_PLANE)        // 34816 (K + V)
#define FLASH_SMEM (FS_OFF + 2 * FSTAGE)  // 104448
#define NKT (LX / BK)                  // 68

__global__ void __launch_bounds__(256, 1) flash1(
    const f16* __restrict__ Qh,
    const f16* __restrict__ Kh, const f16* __restrict__ Vh,
    f16* __restrict__ Och)
{
    extern __shared__ char smem[];
    uint32_t sbase = smem_u32(smem);
    int tid = threadIdx.x, wid = tid >> 5, lane = tid & 31;
    int head = blockIdx.y;
    int q0 = blockIdx.x * 128;
    size_t hb = (size_t)head * LX * HDIM;
    const f16* qp0 = Qh + hb + (size_t)q0 * HDIM;
    const f16* kp[2] = { Kh + hb, Vh + hb };

    #pragma unroll
    for (int u8 = 0; u8 < 8; ++u8) {
        int u = tid + 256 * u8;
        int r = (u >> 4) & 127, c = u & 15;
        cp_async16(sbase + (uint32_t)(r * FSTR + c * 16),
                   qp0 + (size_t)r * HDIM + c * 8, 16);
    }
    cp_commit();

    auto issueKV = [&](int it) {
        int kv0 = it * BK;
        #pragma unroll
        for (int u8 = 0; u8 < 8; ++u8) {
            int u = tid + 256 * u8;
            int pl = u >> 10, r = (u >> 4) & 63, c = u & 15;
            cp_async16(sbase + (uint32_t)(FS_OFF + (it & 1) * FSTAGE +
                                          pl * FK_PLANE + r * FSTR + c * 16),
                       kp[pl] + (size_t)(kv0 + r) * HDIM + c * 8, 16);
        }
        cp_commit();
    };
    issueKV(0);
    issueKV(1);

    uint32_t a_addr = sbase + (uint32_t)((wid * 16 + (lane & 15)) * FSTR +
                                         (lane >> 4) * 16);
    uint32_t bk_rel = (uint32_t)((lane & 15) * FSTR + (lane >> 4) * 16);
    uint32_t bv_rel = (uint32_t)(((((lane >> 3) & 1) * 8) + (lane & 7)) * FSTR +
                                 ((lane >> 4) & 1) * 16);

    float accO[16][4];
    #pragma unroll
    for (int j = 0; j < 16; ++j)
        #pragma unroll
        for (int t = 0; t < 4; ++t) accO[j][t] = 0.f;
    float mrow0 = -1e30f, mrow1 = -1e30f, lsum0 = 0.f, lsum1 = 0.f;
    const float scl = 0.08838834764831845f;

    for (int it = 0; it < NKT; ++it) {
        if (it < NKT - 1) cp_wait1(); else cp_wait0();
        __syncthreads();
        uint32_t kb = sbase + FS_OFF + (uint32_t)(it & 1) * FSTAGE;

        float s[8][4];
        #pragma unroll
        for (int j = 0; j < 8; ++j)
            #pragma unroll
            for (int t = 0; t < 4; ++t) s[j][t] = 0.f;
        #pragma unroll
        for (int ks = 0; ks < 8; ++ks) {
            uint32_t aqh[4];
            ldsm4(aqh, a_addr + ks * 32);
            uint32_t bh[4][4];
            #pragma unroll
            for (int g = 0; g < 4; ++g)
                ldsm4(bh[g], kb + bk_rel + g * (16 * FSTR) + ks * 32);
            #pragma unroll
            for (int j = 0; j < 8; ++j)
                mma_f16(s[j], aqh, bh[j >> 1][j & 1], bh[j >> 1][(j & 1) + 2]);
        }

        float m0 = -1e30f, m1 = -1e30f;
        #pragma unroll
        for (int j = 0; j < 8; ++j) {
            s[j][0] *= scl; s[j][1] *= scl; s[j][2] *= scl; s[j][3] *= scl;
            m0 = fmaxf(m0, fmaxf(s[j][0], s[j][1]));
            m1 = fmaxf(m1, fmaxf(s[j][2], s[j][3]));
        }
        m0 = fmaxf(m0, __shfl_xor_sync(0xffffffffu, m0, 1));
        m0 = fmaxf(m0, __shfl_xor_sync(0xffffffffu, m0, 2));
        m1 = fmaxf(m1, __shfl_xor_sync(0xffffffffu, m1, 1));
        m1 = fmaxf(m1, __shfl_xor_sync(0xffffffffu, m1, 2));
        float mn0 = fmaxf(mrow0, m0), mn1 = fmaxf(mrow1, m1);
        float al0 = __expf(mrow0 - mn0), al1 = __expf(mrow1 - mn1);
        mrow0 = mn0; mrow1 = mn1;

        uint32_t ph[8][2];
        float ps0 = 0.f, ps1 = 0.f;
        #pragma unroll
        for (int j = 0; j < 8; ++j) {
            float p00 = __expf(s[j][0] - mn0), p01 = __expf(s[j][1] - mn0);
            float p10 = __expf(s[j][2] - mn1), p11 = __expf(s[j][3] - mn1);
            ps0 += p00 + p01; ps1 += p10 + p11;
            ph[j][0] = pack2h(p00, p01);
            ph[j][1] = pack2h(p10, p11);
        }
        lsum0 = lsum0 * al0 + ps0;
        lsum1 = lsum1 * al1 + ps1;
        #pragma unroll
        for (int j = 0; j < 16; ++j) {
            accO[j][0] *= al0; accO[j][1] *= al0;
            accO[j][2] *= al1; accO[j][3] *= al1;
        }

        uint32_t vb = kb + FK_PLANE;
        #pragma unroll
        for (int s4 = 0; s4 < 4; ++s4) {
            uint32_t Ahf[4] = { ph[2 * s4][0], ph[2 * s4][1],
                                ph[2 * s4 + 1][0], ph[2 * s4 + 1][1] };
            #pragma unroll
            for (int g = 0; g < 8; ++g) {
                uint32_t bvh[4];
                ldsm4t(bvh, vb + bv_rel + s4 * (16 * FSTR) + g * 32);
                mma_f16(accO[2 * g],     Ahf, bvh[0], bvh[1]);
                mma_f16(accO[2 * g + 1], Ahf, bvh[2], bvh[3]);
            }
        }
        __syncthreads();
        if (it + 2 < NKT) issueKV(it + 2);
    }

    lsum0 += __shfl_xor_sync(0xffffffffu, lsum0, 1);
    lsum0 += __shfl_xor_sync(0xffffffffu, lsum0, 2);
    lsum1 += __shfl_xor_sync(0xffffffffu, lsum1, 1);
    lsum1 += __shfl_xor_sync(0xffffffffu, lsum1, 2);
    float inv0 = 1.f / lsum0, inv1 = 1.f / lsum1;
    int r0 = q0 + wid * 16 + (lane >> 2);
    int cbase = head * HDIM + (lane & 3) * 2;
    #pragma unroll
    for (int j = 0; j < 16; ++j) {
        int c = cbase + j * 8;
        *reinterpret_cast<uint32_t*>(Och + (size_t)r0 * CCW + c) =
            pack2h(accO[j][0] * inv0, accO[j][1] * inv0);
        *reinterpret_cast<uint32_t*>(Och + (size_t)(r0 + 8) * CCW + c) =
            pack2h(accO[j][2] * inv1, accO[j][3] * inv1);
    }
}

// ---------------- SIMT GEMM for tiny block-2 attention ---------------------
__global__ void __launch_bounds__(256) sgemm_abt(
    const float* __restrict__ A, int lda, long long sA,
    const float* __restrict__ B, int ldb, long long sB,
    float* __restrict__ C, f16* __restrict__ Ch,
    int ldc, long long sC,
    int M, int N, int K, float alpha, int halfout)
{
    __shared__ float As[8][128];
    __shared__ float Bs[8][128];
    int bz = blockIdx.z;
    A += (size_t)sA * bz;
    B += (size_t)sB * bz;
    if (halfout) Ch += (size_t)sC * bz;
    else C += (size_t)sC * bz;
    int m0 = blockIdx.y * 128;
    int n0 = blockIdx.x * 128;
    int tid = threadIdx.x;
    int tx = tid & 15, ty = tid >> 4;
    int lrow = tid >> 1;
    int lcol = (tid & 1) * 4;

    float acc[8][8];
    #pragma unroll
    for (int i = 0; i < 8; i++)
        #pragma unroll
        for (int j = 0; j < 8; j++) acc[i][j] = 0.f;

    for (int k0 = 0; k0 < K; k0 += 8) {
        float4 av = make_float4(0.f, 0.f, 0.f, 0.f);
        float4 bv = make_float4(0.f, 0.f, 0.f, 0.f);
        if (m0 + lrow < M && k0 + lcol < K)
            av = *reinterpret_cast<const float4*>(A + (size_t)(m0 + lrow) * lda + k0 + lcol);
        if (n0 + lrow < N && k0 + lcol < K)
            bv = *reinterpret_cast<const float4*>(B + (size_t)(n0 + lrow) * ldb + k0 + lcol);
        As[lcol + 0][lrow] = av.x; As[lcol + 1][lrow] = av.y;
        As[lcol + 2][lrow] = av.z; As[lcol + 3][lrow] = av.w;
        Bs[lcol + 0][lrow] = bv.x; Bs[lcol + 1][lrow] = bv.y;
        Bs[lcol + 2][lrow] = bv.z; Bs[lcol + 3][lrow] = bv.w;
        __syncthreads();
        #pragma unroll
        for (int k = 0; k < 8; k++) {
            float ra[8], rb[8];
            #pragma unroll
            for (int i = 0; i < 8; i++) ra[i] = As[k][ty + 16 * i];
            #pragma unroll
            for (int j = 0; j < 8; j++) rb[j] = Bs[k][tx + 16 * j];
            #pragma unroll
            for (int i = 0; i < 8; i++)
                #pragma unroll
                for (int j = 0; j < 8; j++)
                    acc[i][j] = fmaf(ra[i], rb[j], acc[i][j]);
        }
        __syncthreads();
    }

    #pragma unroll
    for (int i = 0; i < 8; i++) {
        int m = m0 + ty + 16 * i;
        if (m >= M) continue;
        #pragma unroll
        for (int j = 0; j < 8; j++) {
            int n = n0 + tx + 16 * j;
            if (n >= N) continue;
            float v = alpha * acc[i][j];
            if (halfout) Ch[(size_t)m * ldc + n] = __float2half_rn(v);
            else         C[(size_t)m * ldc + n] = v;
        }
    }
}

// ---------------- convert fp32 -> fp16 -------------------------------------
__global__ void __launch_bounds__(256) convert_h(
    const float4* __restrict__ src, uint2* __restrict__ h, int n4)
{
    int idx = blockIdx.x * 256 + threadIdx.x;
    if (idx >= n4) return;
    float4 v = src[idx];
    uint2 r;
    r.x = pack2h(v.x, v.y);
    r.y = pack2h(v.z, v.w);
    h[idx] = r;
}

// ---------------- modulation: m = silu(vec) @ mod_w^T + mod_b --------------
__global__ void __launch_bounds__(128) mod_kernel(
    const float* __restrict__ vec, const float* __restrict__ mod_w,
    const float* __restrict__ mod_b)
{
    int n = blockIdx.x * 4 + (threadIdx.x >> 5);
    if (n >= 3 * HIDDEN) return;
    int lane = threadIdx.x & 31;
    const float* wrow = mod_w + (size_t)n * HIDDEN;
    float acc = 0.f;
    for (int k = lane; k < HIDDEN; k += 32) {
        float xv = vec[k];
        float s = xv / (1.f + __expf(-xv));
        acc = fmaf(s, wrow[k], acc);
    }
    acc = warp_sum(acc);
    if (lane == 0) g_mod[n] = acc + mod_b[n];
}

// ---------------- layernorm + modulate -> fp16 ------------------------------
__global__ void __launch_bounds__(256) ln_mod_kernel(
    const float* __restrict__ x, const float* __restrict__ concepts)
{
    __shared__ float sbuf[8];
    int row = blockIdx.x;
    const float* src = (row < LX) ? (x + (size_t)row * HIDDEN)
                                  : (concepts + (size_t)(row - LX) * HIDDEN);
    int tid = threadIdx.x;
    float v[6];
    float s = 0.f;
    #pragma unroll
    for (int i = 0; i < 6; i++) { v[i] = src[tid + 256 * i]; s += v[i]; }
    s = block_sum<256>(s, sbuf);
    float mu = s * (1.0f / 1536.0f);
    float s2 = 0.f;
    #pragma unroll
    for (int i = 0; i < 6; i++) { float d = v[i] - mu; s2 = fmaf(d, d, s2); }
    s2 = block_sum<256>(s2, sbuf);
    float rstd = rsqrtf(s2 * (1.0f / 1536.0f) + 1e-6f);
    #pragma unroll
    for (int i = 0; i < 6; i++) {
        int j = tid + 256 * i;
        float val = (1.f + g_mod[HIDDEN + j]) * ((v[i] - mu) * rstd) + g_mod[j];
        g_xmh[(size_t)row * HIDDEN + j] = __float2half_rn(val);
    }
}

// ---------------- RoPE helper (pair exchange via shfl) ---------------------
__device__ __forceinline__ float rope_pair(float a, const float* __restrict__ petab,
                                           int tok, int d)
{
    float b = __shfl_xor_sync(0xffffffffu, a, 1);
    int i = d >> 1;
    const float* p = petab + ((size_t)tok * 64 + i) * 4;
    if ((d & 1) == 0) return fmaf(p[0], a, p[1] * b);
    else              return fmaf(p[2], b, p[3] * a);
}

// ---------------- attention prep for x tokens ------------------------------
__global__ void __launch_bounds__(128) attn_prep1(
    const float* __restrict__ pe, const float* __restrict__ cpe,
    const float* __restrict__ q_scale, const float* __restrict__ k_scale)
{
    __shared__ float sbuf[4];
    int t = blockIdx.x, h = blockIdx.y, d = threadIdx.x;
    const float* hrow = g_h + (size_t)t * QKVW;
    float q = hrow[h * HDIM + d];
    float k = hrow[HIDDEN + h * HDIM + d];
    float v = hrow[2 * HIDDEN + h * HDIM + d];
    float msq = block_sum<128>(q * q, sbuf) * (1.f / 128.f);
    float msk = block_sum<128>(k * k, sbuf) * (1.f / 128.f);
    float qn = q * rsqrtf(msq + 1e-6f) * q_scale[d];
    float kn = k * rsqrtf(msk + 1e-6f) * k_scale[d];
    float qr = rope_pair(qn, pe, t, d);
    float kr = rope_pair(kn, pe, t, d);
    size_t qi = ((size_t)h * LX + t) * HDIM + d;
    g_q1h[qi] = __float2half_rn(qr);
    g_k1h[qi] = __float2half_rn(kr);
    g_v1h[qi] = __float2half_rn(v);
    if (t >= TXT) {
        int j = NC + (t - TXT);
        g_k2[((size_t)h * LC + j) * HDIM + d] = rope_pair(kn, cpe, j, d);
        g_vt2[((size_t)h * HDIM + d) * LC + j] = v;
    }
}

// ---------------- attention prep for concept tokens ------------------------
__global__ void __launch_bounds__(128) attn_prep2(
    const float* __restrict__ cpe,
    const float* __restrict__ q_scale, const float* __restrict__ k_scale)
{
    __shared__ float sbuf[4];
    int i = blockIdx.x, h = blockIdx.y, d = threadIdx.x;
    const float* hrow = g_h + (size_t)(LX + i) * QKVW;
    float q = hrow[h * HDIM + d];
    float k = hrow[HIDDEN + h * HDIM + d];
    float v = hrow[2 * HIDDEN + h * HDIM + d];
    float msq = block_sum<128>(q * q, sbuf) * (1.f / 128.f);
    float msk = block_sum<128>(k * k, sbuf) * (1.f / 128.f);
    float qn = q * rsqrtf(msq + 1e-6f) * q_scale[d];
    float kn = k * rsqrtf(msk + 1e-6f) * k_scale[d];
    g_q2[((size_t)h * NC + i) * HDIM + d] = rope_pair(qn, cpe, i, d);
    g_k2[((size_t)h * LC + i) * HDIM + d] = rope_pair(kn, cpe, i, d);
    g_vt2[((size_t)h * HDIM + d) * LC + i] = v;
}

// ---------------- row softmax (block-2 path) -------------------------------
__global__ void __launch_bounds__(256) softmax_rows(float* __restrict__ S, int ncol)
{
    __shared__ float sbuf[8];
    float* row = S + (size_t)blockIdx.x * ncol;
    int tid = threadIdx.x;
    float v[17];
    float mx = -1e30f;
    #pragma unroll
    for (int i = 0; i < 17; i++) {
        int c = tid + 256 * i;
        v[i] = (c < ncol) ? row[c] : -1e30f;
        mx = fmaxf(mx, v[i]);
    }
    mx = block_max<256>(mx, sbuf);
    float s = 0.f;
    #pragma unroll
    for (int i = 0; i < 17; i++) { v[i] = __expf(v[i] - mx); s += v[i]; }
    s = block_sum<256>(s, sbuf);
    float inv = 1.f / s;
    #pragma unroll
    for (int i = 0; i < 17; i++) {
        int c = tid + 256 * i;
        if (c < ncol) row[c] = v[i] * inv;
    }
}

// ---------------- residual: out = base + gate * block_out ------------------
__global__ void __launch_bounds__(256) final_kernel(
    const float* __restrict__ x, const float* __restrict__ concepts,
    float* __restrict__ out)
{
    size_t idx = (size_t)blockIdx.x * 256 + threadIdx.x;
    if (idx >= (size_t)NROWS * HIDDEN) return;
    int c = (int)(idx % HIDDEN);
    size_t r = idx / HIDDEN;
    float base = (r < LX) ? x[idx] : concepts[idx - (size_t)LX * HIDDEN];
    out[idx] = fmaf(g_mod[2 * HIDDEN + c], g_out[idx], base);
}

// ---------------------------------------------------------------------------
extern "C" void kernel_launch(void* const* d_in, const int* in_sizes, int n_in,
                              void* d_out, int out_size)
{
    const float* x        = (const float*)d_in[0];
    const float* concepts = (const float*)d_in[1];
    const float* vec      = (const float*)d_in[2];
    const float* pe       = (const float*)d_in[3];
    const float* cpe      = (const float*)d_in[4];
    const float* w1       = (const float*)d_in[5];
    const float* b1       = (const float*)d_in[6];
    const float* w2       = (const float*)d_in[7];
    const float* b2       = (const float*)d_in[8];
    const float* q_scale  = (const float*)d_in[9];
    const float* k_scale  = (const float*)d_in[10];
    const float* mod_w    = (const float*)d_in[11];
    const float* mod_b    = (const float*)d_in[12];
    float* out = (float*)d_out;

    void* p;
    cudaGetSymbolAddress(&p, g_xmh);  f16* xmh = (f16*)p;
    cudaGetSymbolAddress(&p, g_w1h);  f16* w1h = (f16*)p;
    cudaGetSymbolAddress(&p, g_w2h);  f16* w2h = (f16*)p;
    cudaGetSymbolAddress(&p, g_h);    float* hbuf = (float*)p;
    cudaGetSymbolAddress(&p, g_q1h);  f16* q1h = (f16*)p;
    cudaGetSymbolAddress(&p, g_k1h);  f16* k1h = (f16*)p;
    cudaGetSymbolAddress(&p, g_v1h);  f16* v1h = (f16*)p;
    cudaGetSymbolAddress(&p, g_q2);   float* q2b  = (float*)p;
    cudaGetSymbolAddress(&p, g_k2);   float* k2b  = (float*)p;
    cudaGetSymbolAddress(&p, g_vt2);  float* vt2b = (float*)p;
    cudaGetSymbolAddress(&p, g_s2);   float* s2b  = (float*)p;
    cudaGetSymbolAddress(&p, g_cch);  f16* cch = (f16*)p;
    cudaGetSymbolAddress(&p, g_out);  float* outb = (float*)p;

    cudaFuncSetAttribute(gemm_f16, cudaFuncAttributeMaxDynamicSharedMemorySize,
                         HG_SMEM);
    cudaFuncSetAttribute(flash1, cudaFuncAttributeMaxDynamicSharedMemorySize,
                         FLASH_SMEM);

    const float scl = 0.08838834764831845f;  // 1/sqrt(128)

    // modulation vector (shift | scale | gate)
    mod_kernel<<<(3 * HIDDEN + 3) / 4, 128>>>(vec, mod_w, mod_b);
    // weight conversion (fp16)
    {
        int n4 = (W1OUT * HIDDEN) / 4;
        convert_h<<<(n4 + 255) / 256, 256>>>((const float4*)w1, (uint2*)w1h, n4);
        n4 = (HIDDEN * CCW) / 4;
        convert_h<<<(n4 + 255) / 256, 256>>>((const float4*)w2, (uint2*)w2h, n4);
    }
    // layernorm + modulate -> xm fp16
    ln_mod_kernel<<<NROWS, 256>>>(x, concepts);
    // GEMM1: h = xm @ w1^T + b1; qkv cols -> fp32 h, mlp cols -> gelu cc fp16
    gemm_f16<<<dim3(W1OUT / 128, (NROWS + 127) / 128), 256, HG_SMEM>>>(
        xmh, HIDDEN, w1h, HIDDEN,
        hbuf, QKVW, cch, QKVW,
        NROWS, W1OUT, HIDDEN, b1);
    // rmsnorm + rope -> q/k/v fp16 (+ block2 fp32 arrays)
    attn_prep1<<<dim3(LX, NHEADS), 128>>>(pe, cpe, q_scale, k_scale);
    attn_prep2<<<dim3(NC, NHEADS), 128>>>(cpe, q_scale, k_scale);
    // block1 fused flash attention -> cc fp16 cols [0,1536)
    flash1<<<dim3(LX / 128, NHEADS), 256, FLASH_SMEM>>>(q1h, k1h, v1h, cch);
    // block2 attention (20 queries over 4116 keys) — SIMT path
    sgemm_abt<<<dim3((LC + 127) / 128, 1, NHEADS), 256>>>(
        q2b, HDIM, (long long)NC * HDIM, k2b, HDIM, (long long)LC * HDIM,
        s2b, nullptr, LC, (long long)NC * LC,
        NC, LC, HDIM, scl, 0);
    softmax_rows<<<NHEADS * NC, 256>>>(s2b, LC);
    sgemm_abt<<<dim3(1, 1, NHEADS), 256>>>(
        s2b, LC, (long long)NC * LC, vt2b, LC, (long long)HDIM * LC,
        nullptr, cch + (size_t)LX * CCW, CCW, 128,
        NC, HDIM, LC, 1.f, 1);
    // GEMM2: out = cc @ w2^T + b2
    gemm_f16<<<dim3(HIDDEN / 128, (NROWS + 127) / 128), 256, HG_SMEM>>>(
        cch, CCW, w2h, CCW,
        outb, HIDDEN, nullptr, HIDDEN,
        NROWS, HIDDEN, CCW, b2);
    // residual + gate
    final_kernel<<<(unsigned)(((size_t)NROWS * HIDDEN + 255) / 256), 256>>>(
        x, concepts, out);
}

// round 9
// speedup vs baseline: 3.4388x; 1.5367x over previous
#include <cuda_runtime.h>
#include <cuda_fp16.h>
#include <math.h>
#include <stdint.h>

#define HIDDEN 1536
#define NHEADS 12
#define HDIM 128
#define MLPH 6144
#define TXT 256
#define LX 4352
#define NC 20
#define LC 4116
#define NROWS 4372          // LX + NC
#define W1OUT 10752         // 3*HIDDEN + MLPH
#define QKVW 4608           // 3*HIDDEN
#define CCW 7680            // HIDDEN + MLPH

typedef __half f16;

// ---------------- scratch (static device globals; no runtime allocation) ---
static __device__ float g_mod[3 * HIDDEN];
static __device__ f16   g_xmh[(size_t)NROWS * HIDDEN];
static __device__ f16   g_w1h[(size_t)W1OUT * HIDDEN];
static __device__ f16   g_w2h[(size_t)HIDDEN * CCW];
static __device__ float g_h[(size_t)NROWS * QKVW];
static __device__ f16   g_q1h[(size_t)NHEADS * LX * HDIM];
static __device__ f16   g_k1h[(size_t)NHEADS * LX * HDIM];
static __device__ f16   g_v1h[(size_t)NHEADS * LX * HDIM];
static __device__ float g_q2[(size_t)NHEADS * NC * HDIM];
static __device__ float g_k2[(size_t)NHEADS * LC * HDIM];
static __device__ float g_v2[(size_t)NHEADS * LC * HDIM];
static __device__ float g_s2[(size_t)NHEADS * NC * LC];
static __device__ float g_o2[(size_t)NHEADS * NC * HDIM];
static __device__ f16   g_cch[(size_t)NROWS * CCW];
static __device__ float g_out[(size_t)NROWS * HIDDEN];

// ---------------- reductions ----------------------------------------------
__device__ __forceinline__ float warp_sum(float v) {
    #pragma unroll
    for (int o = 16; o > 0; o >>= 1) v += __shfl_xor_sync(0xffffffffu, v, o);
    return v;
}
__device__ __forceinline__ float warp_max(float v) {
    #pragma unroll
    for (int o = 16; o > 0; o >>= 1) v = fmaxf(v, __shfl_xor_sync(0xffffffffu, v, o));
    return v;
}
template <int NT>
__device__ __forceinline__ float block_sum(float v, float* sbuf) {
    v = warp_sum(v);
    int lane = threadIdx.x & 31, w = threadIdx.x >> 5;
    if (lane == 0) sbuf[w] = v;
    __syncthreads();
    if (threadIdx.x < 32) {
        float x = (threadIdx.x < NT / 32) ? sbuf[threadIdx.x] : 0.f;
        x = warp_sum(x);
        if (threadIdx.x == 0) sbuf[0] = x;
    }
    __syncthreads();
    float r = sbuf[0];
    __syncthreads();
    return r;
}
template <int NT>
__device__ __forceinline__ float block_max(float v, float* sbuf) {
    v = warp_max(v);
    int lane = threadIdx.x & 31, w = threadIdx.x >> 5;
    if (lane == 0) sbuf[w] = v;
    __syncthreads();
    if (threadIdx.x < 32) {
        float x = (threadIdx.x < NT / 32) ? sbuf[threadIdx.x] : -1e30f;
        x = warp_max(x);
        if (threadIdx.x == 0) sbuf[0] = x;
    }
    __syncthreads();
    float r = sbuf[0];
    __syncthreads();
    return r;
}

// ---------------- helpers ---------------------------------------------------
__device__ __forceinline__ uint32_t pack2h(float x, float y) {
    __half2 h = __halves2half2(__float2half_rn(x), __float2half_rn(y));
    return *reinterpret_cast<uint32_t*>(&h);
}
__device__ __forceinline__ float gelu_f(float xv) {
    float inner = 0.7978845608028654f * fmaf(0.044715f * xv * xv, xv, xv);
    return 0.5f * xv * (1.f + tanhf(inner));
}

// ======================= HMMA helpers ======================================
__device__ __forceinline__ uint32_t smem_u32(const void* p) {
    uint32_t a;
    asm("{ .reg .u64 t; cvta.to.shared.u64 t, %1; cvt.u32.u64 %0, t; }"
        : "=r"(a) : "l"(p));
    return a;
}
__device__ __forceinline__ void ldsm4(uint32_t* r, uint32_t addr) {
    asm volatile("ldmatrix.sync.aligned.m8n8.x4.shared.b16 {%0,%1,%2,%3}, [%4];"
                 : "=r"(r[0]), "=r"(r[1]), "=r"(r[2]), "=r"(r[3]) : "r"(addr));
}
__device__ __forceinline__ void ldsm4t(uint32_t* r, uint32_t addr) {
    asm volatile("ldmatrix.sync.aligned.m8n8.x4.trans.shared.b16 {%0,%1,%2,%3}, [%4];"
                 : "=r"(r[0]), "=r"(r[1]), "=r"(r[2]), "=r"(r[3]) : "r"(addr));
}
__device__ __forceinline__ void mma_f16(float* c, const uint32_t* a,
                                        uint32_t b0, uint32_t b1) {
    asm volatile(
        "mma.sync.aligned.m16n8k16.row.col.f32.f16.f16.f32 "
        "{%0,%1,%2,%3}, {%4,%5,%6,%7}, {%8,%9}, {%0,%1,%2,%3};"
        : "+f"(c[0]), "+f"(c[1]), "+f"(c[2]), "+f"(c[3])
        : "r"(a[0]), "r"(a[1]), "r"(a[2]), "r"(a[3]), "r"(b0), "r"(b1));
}
__device__ __forceinline__ void cp_async16(uint32_t dst, const void* src, int sz) {
    asm volatile("cp.async.cg.shared.global [%0], [%1], 16, %2;"
                 :: "r"(dst), "l"(src), "r"(sz) : "memory");
}
__device__ __forceinline__ void cp_commit() {
    asm volatile("cp.async.commit_group;" ::: "memory");
}
__device__ __forceinline__ void cp_wait1() {
    asm volatile("cp.async.wait_group 1;" ::: "memory");
}
__device__ __forceinline__ void cp_wait2() {
    asm volatile("cp.async.wait_group 2;" ::: "memory");
}

// smem: per stage 2 tiles (A, B): 128 rows x 32 f16, row stride 80 B
#define SPB      80
#define T_BYTES  (128 * SPB)          // 10240
#define STAGE_B  (2 * T_BYTES)        // 20480
#define NSTAGE   4
#define HG_SMEM  (NSTAGE * STAGE_B)   // 81920 -> 2 CTAs/SM

// ======== fp16 GEMM: C = A@B^T + bias ======================================
// Columns n >= gelu_n0: bias+gelu, fp16 to Gh at col HIDDEN + n - gelu_n0
// (stride CCW). Columns n < gelu_n0: fp32 to C (ldc).
// Pipeline: cp_wait -> barrier -> issue(c+3) -> compute (no trailing barrier).
__global__ void __launch_bounds__(256, 2) gemm_f16(
    const f16* __restrict__ Ah, int lda,
    const f16* __restrict__ Bh, int ldb,
    float* __restrict__ C, int ldc,
    f16* __restrict__ Gh, int gelu_n0,
    int M, int N, int K, const float* __restrict__ bias)
{
    extern __shared__ char smem[];
    uint32_t sbase = smem_u32(smem);
    int tid = threadIdx.x, wid = tid >> 5, lane = tid & 31;

    // supertile swizzle for L2 reuse
    const int GRP = 8;
    int npn = gridDim.x, npm = gridDim.y;
    int pid = blockIdx.y * npn + blockIdx.x;
    int gsz = GRP * npn;
    int gid = pid / gsz;
    int fm = gid * GRP;
    int gm = min(GRP, npm - fm);
    int pid_m = fm + (pid % gsz) % gm;
    int pid_n = (pid % gsz) / gm;
    int m0 = pid_m * 128, n0 = pid_n * 128;

    int warp_m = wid & 3;
    int warp_n = wid >> 2;
    int lrow = lane & 15, lhalf = lane >> 4;

    uint32_t a_off[2], b_off[4];
    #pragma unroll
    for (int i = 0; i < 2; ++i)
        a_off[i] = (uint32_t)((warp_m * 32 + i * 16 + lrow) * SPB + lhalf * 16);
    #pragma unroll
    for (int g = 0; g < 4; ++g)
        b_off[g] = (uint32_t)((warp_n * 64 + g * 16 + lrow) * SPB + lhalf * 16);

    float acc[2][8][4];
    #pragma unroll
    for (int i = 0; i < 2; ++i)
        #pragma unroll
        for (int j = 0; j < 8; ++j)
            #pragma unroll
            for (int t = 0; t < 4; ++t) acc[i][j][t] = 0.f;

    int nch = K >> 5;

    auto issue = [&](int c) {
        if (c < nch) {
            int kc = c << 5;
            uint32_t sb = sbase + (uint32_t)(c % NSTAGE) * STAGE_B;
            #pragma unroll
            for (int u4 = 0; u4 < 4; ++u4) {
                int u = tid + 256 * u4;
                int tile = u >> 9;              // 0=A, 1=B
                int r = (u >> 2) & 127;
                int c16 = u & 3;
                uint32_t dst = sb + (uint32_t)(tile * T_BYTES + r * SPB + c16 * 16);
                if (tile == 0) {
                    int sz = (m0 + r < M) ? 16 : 0;
                    cp_async16(dst, Ah + (size_t)(m0 + r) * lda + kc + c16 * 8, sz);
                } else {
                    cp_async16(dst, Bh + (size_t)(n0 + r) * ldb + kc + c16 * 8, 16);
                }
            }
        }
        cp_commit();
    };

    issue(0); issue(1); issue(2);

    for (int c = 0; c < nch; ++c) {
        cp_wait2();            // groups c..c+2 pending -> c complete
        __syncthreads();       // data visible to all; all warps past c-1
        issue(c + 3);          // overwrites (c+3)%4, consumed at c-1: safe
        uint32_t sb = sbase + (uint32_t)(c % NSTAGE) * STAGE_B;
        #pragma unroll
        for (int k16 = 0; k16 < 2; ++k16) {
            uint32_t koff = (uint32_t)(k16 * 32);
            uint32_t ah[2][4], bh[4][4];
            #pragma unroll
            for (int i = 0; i < 2; ++i)
                ldsm4(ah[i], sb + 0 * T_BYTES + a_off[i] + koff);
            #pragma unroll
            for (int g = 0; g < 4; ++g)
                ldsm4(bh[g], sb + 1 * T_BYTES + b_off[g] + koff);
            #pragma unroll
            for (int i = 0; i < 2; ++i)
                #pragma unroll
                for (int j = 0; j < 8; ++j) {
                    int g = j >> 1, sI = j & 1;
                    mma_f16(acc[i][j], ah[i], bh[g][sI], bh[g][sI + 2]);
                }
        }
    }

    // ---- epilogue ----
    int trow = lane >> 2, tc2 = (lane & 3) * 2;
    #pragma unroll
    for (int i = 0; i < 2; ++i) {
        #pragma unroll
        for (int half = 0; half < 2; ++half) {
            int m = m0 + warp_m * 32 + i * 16 + half * 8 + trow;
            if (m >= M) continue;
            #pragma unroll
            for (int j = 0; j < 8; ++j) {
                int n = n0 + warp_n * 64 + j * 8 + tc2;
                float vx = acc[i][j][half * 2 + 0];
                float vy = acc[i][j][half * 2 + 1];
                if (bias) { vx += bias[n]; vy += bias[n + 1]; }
                if (n >= gelu_n0) {
                    vx = gelu_f(vx); vy = gelu_f(vy);
                    int cc = HIDDEN + n - gelu_n0;
                    *reinterpret_cast<uint32_t*>(Gh + (size_t)m * CCW + cc) =
                        pack2h(vx, vy);
                } else {
                    *reinterpret_cast<float2*>(C + (size_t)m * ldc + n) =
                        make_float2(vx, vy);
                }
            }
        }
    }
}

// ================= flash attention for block 1 =============================
// Q tile 128 rows, KV 64-row tiles, 3-stage ring, ONE barrier per iteration
// (at top, before early issue) so warps drift through softmax and keep the
// tensor pipe busy.
#define BK 64
#define FSTR 272                       // 128*2 + 16 pad
#define FQ_PLANE (128 * FSTR)          // 34816
#define FK_PLANE (BK * FSTR)           // 17408
#define FS_OFF   FQ_PLANE              // 34816
#define FSTAGE   (2 * FK_PLANE)        // 34816 (K + V)
#define FNS      3
#define FLASH_SMEM (FS_OFF + FNS * FSTAGE)  // 139264
#define NKT (LX / BK)                  // 68

__global__ void __launch_bounds__(256, 1) flash1(
    const f16* __restrict__ Qh,
    const f16* __restrict__ Kh, const f16* __restrict__ Vh,
    f16* __restrict__ Och)
{
    extern __shared__ char smem[];
    uint32_t sbase = smem_u32(smem);
    int tid = threadIdx.x, wid = tid >> 5, lane = tid & 31;
    int head = blockIdx.y;
    int q0 = blockIdx.x * 128;
    size_t hb = (size_t)head * LX * HDIM;
    const f16* qp0 = Qh + hb + (size_t)q0 * HDIM;
    const f16* kp[2] = { Kh + hb, Vh + hb };

    #pragma unroll
    for (int u8 = 0; u8 < 8; ++u8) {
        int u = tid + 256 * u8;
        int r = (u >> 4) & 127, c = u & 15;
        cp_async16(sbase + (uint32_t)(r * FSTR + c * 16),
                   qp0 + (size_t)r * HDIM + c * 8, 16);
    }
    cp_commit();

    auto issueKV = [&](int it) {
        if (it < NKT) {
            int kv0 = it * BK;
            #pragma unroll
            for (int u8 = 0; u8 < 8; ++u8) {
                int u = tid + 256 * u8;
                int pl = u >> 10, r = (u >> 4) & 63, c = u & 15;
                cp_async16(sbase + (uint32_t)(FS_OFF + (it % FNS) * FSTAGE +
                                              pl * FK_PLANE + r * FSTR + c * 16),
                           kp[pl] + (size_t)(kv0 + r) * HDIM + c * 8, 16);
            }
        }
        cp_commit();
    };
    issueKV(0);
    issueKV(1);

    uint32_t a_addr = sbase + (uint32_t)((wid * 16 + (lane & 15)) * FSTR +
                                         (lane >> 4) * 16);
    uint32_t bk_rel = (uint32_t)((lane & 15) * FSTR + (lane >> 4) * 16);
    uint32_t bv_rel = (uint32_t)(((((lane >> 3) & 1) * 8) + (lane & 7)) * FSTR +
                                 ((lane >> 4) & 1) * 16);

    float accO[16][4];
    #pragma unroll
    for (int j = 0; j < 16; ++j)
        #pragma unroll
        for (int t = 0; t < 4; ++t) accO[j][t] = 0.f;
    float mrow0 = -1e30f, mrow1 = -1e30f, lsum0 = 0.f, lsum1 = 0.f;
    const float scl = 0.08838834764831845f;

    for (int it = 0; it < NKT; ++it) {
        cp_wait1();            // pending it..it+1 -> KV(it) (and Q) complete
        __syncthreads();       // visibility + all warps past it-1
        issueKV(it + 2);       // writes (it+2)%3, consumed at it-1: safe
        uint32_t kb = sbase + FS_OFF + (uint32_t)(it % FNS) * FSTAGE;

        float s[8][4];
        #pragma unroll
        for (int j = 0; j < 8; ++j)
            #pragma unroll
            for (int t = 0; t < 4; ++t) s[j][t] = 0.f;
        #pragma unroll
        for (int ks = 0; ks < 8; ++ks) {
            uint32_t aqh[4];
            ldsm4(aqh, a_addr + ks * 32);
            uint32_t bh[4][4];
            #pragma unroll
            for (int g = 0; g < 4; ++g)
                ldsm4(bh[g], kb + bk_rel + g * (16 * FSTR) + ks * 32);
            #pragma unroll
            for (int j = 0; j < 8; ++j)
                mma_f16(s[j], aqh, bh[j >> 1][j & 1], bh[j >> 1][(j & 1) + 2]);
        }

        float m0 = -1e30f, m1 = -1e30f;
        #pragma unroll
        for (int j = 0; j < 8; ++j) {
            s[j][0] *= scl; s[j][1] *= scl; s[j][2] *= scl; s[j][3] *= scl;
            m0 = fmaxf(m0, fmaxf(s[j][0], s[j][1]));
            m1 = fmaxf(m1, fmaxf(s[j][2], s[j][3]));
        }
        m0 = fmaxf(m0, __shfl_xor_sync(0xffffffffu, m0, 1));
        m0 = fmaxf(m0, __shfl_xor_sync(0xffffffffu, m0, 2));
        m1 = fmaxf(m1, __shfl_xor_sync(0xffffffffu, m1, 1));
        m1 = fmaxf(m1, __shfl_xor_sync(0xffffffffu, m1, 2));
        float mn0 = fmaxf(mrow0, m0), mn1 = fmaxf(mrow1, m1);
        float al0 = __expf(mrow0 - mn0), al1 = __expf(mrow1 - mn1);
        mrow0 = mn0; mrow1 = mn1;

        uint32_t ph[8][2];
        float ps0 = 0.f, ps1 = 0.f;
        #pragma unroll
        for (int j = 0; j < 8; ++j) {
            float p00 = __expf(s[j][0] - mn0), p01 = __expf(s[j][1] - mn0);
            float p10 = __expf(s[j][2] - mn1), p11 = __expf(s[j][3] - mn1);
            ps0 += p00 + p01; ps1 += p10 + p11;
            ph[j][0] = pack2h(p00, p01);
            ph[j][1] = pack2h(p10, p11);
        }
        lsum0 = lsum0 * al0 + ps0;
        lsum1 = lsum1 * al1 + ps1;
        #pragma unroll
        for (int j = 0; j < 16; ++j) {
            accO[j][0] *= al0; accO[j][1] *= al0;
            accO[j][2] *= al1; accO[j][3] *= al1;
        }

        uint32_t vb = kb + FK_PLANE;
        #pragma unroll
        for (int s4 = 0; s4 < 4; ++s4) {
            uint32_t Ahf[4] = { ph[2 * s4][0], ph[2 * s4][1],
                                ph[2 * s4 + 1][0], ph[2 * s4 + 1][1] };
            #pragma unroll
            for (int g = 0; g < 8; ++g) {
                uint32_t bvh[4];
                ldsm4t(bvh, vb + bv_rel + s4 * (16 * FSTR) + g * 32);
                mma_f16(accO[2 * g],     Ahf, bvh[0], bvh[1]);
                mma_f16(accO[2 * g + 1], Ahf, bvh[2], bvh[3]);
            }
        }
        // no trailing barrier — warps drift; top-of-iter barrier bounds skew
    }

    lsum0 += __shfl_xor_sync(0xffffffffu, lsum0, 1);
    lsum0 += __shfl_xor_sync(0xffffffffu, lsum0, 2);
    lsum1 += __shfl_xor_sync(0xffffffffu, lsum1, 1);
    lsum1 += __shfl_xor_sync(0xffffffffu, lsum1, 2);
    float inv0 = 1.f / lsum0, inv1 = 1.f / lsum1;
    int r0 = q0 + wid * 16 + (lane >> 2);
    int cbase = head * HDIM + (lane & 3) * 2;
    #pragma unroll
    for (int j = 0; j < 16; ++j) {
        int c = cbase + j * 8;
        *reinterpret_cast<uint32_t*>(Och + (size_t)r0 * CCW + c) =
            pack2h(accO[j][0] * inv0, accO[j][1] * inv0);
        *reinterpret_cast<uint32_t*>(Och + (size_t)(r0 + 8) * CCW + c) =
            pack2h(accO[j][2] * inv1, accO[j][3] * inv1);
    }
}

// ---------------- SIMT GEMM (block-2 QK^T only) ----------------------------
__global__ void __launch_bounds__(256) sgemm_abt(
    const float* __restrict__ A, int lda, long long sA,
    const float* __restrict__ B, int ldb, long long sB,
    float* __restrict__ C, int ldc, long long sC,
    int M, int N, int K, float alpha)
{
    __shared__ float As[8][128];
    __shared__ float Bs[8][128];
    int bz = blockIdx.z;
    A += (size_t)sA * bz;
    B += (size_t)sB * bz;
    C += (size_t)sC * bz;
    int m0 = blockIdx.y * 128;
    int n0 = blockIdx.x * 128;
    int tid = threadIdx.x;
    int tx = tid & 15, ty = tid >> 4;
    int lrow = tid >> 1;
    int lcol = (tid & 1) * 4;

    float acc[8][8];
    #pragma unroll
    for (int i = 0; i < 8; i++)
        #pragma unroll
        for (int j = 0; j < 8; j++) acc[i][j] = 0.f;

    for (int k0 = 0; k0 < K; k0 += 8) {
        float4 av = make_float4(0.f, 0.f, 0.f, 0.f);
        float4 bv = make_float4(0.f, 0.f, 0.f, 0.f);
        if (m0 + lrow < M && k0 + lcol < K)
            av = *reinterpret_cast<const float4*>(A + (size_t)(m0 + lrow) * lda + k0 + lcol);
        if (n0 + lrow < N && k0 + lcol < K)
            bv = *reinterpret_cast<const float4*>(B + (size_t)(n0 + lrow) * ldb + k0 + lcol);
        As[lcol + 0][lrow] = av.x; As[lcol + 1][lrow] = av.y;
        As[lcol + 2][lrow] = av.z; As[lcol + 3][lrow] = av.w;
        Bs[lcol + 0][lrow] = bv.x; Bs[lcol + 1][lrow] = bv.y;
        Bs[lcol + 2][lrow] = bv.z; Bs[lcol + 3][lrow] = bv.w;
        __syncthreads();
        #pragma unroll
        for (int k = 0; k < 8; k++) {
            float ra[8], rb[8];
            #pragma unroll
            for (int i = 0; i < 8; i++) ra[i] = As[k][ty + 16 * i];
            #pragma unroll
            for (int j = 0; j < 8; j++) rb[j] = Bs[k][tx + 16 * j];
            #pragma unroll
            for (int i = 0; i < 8; i++)
                #pragma unroll
                for (int j = 0; j < 8; j++)
                    acc[i][j] = fmaf(ra[i], rb[j], acc[i][j]);
        }
        __syncthreads();
    }

    #pragma unroll
    for (int i = 0; i < 8; i++) {
        int m = m0 + ty + 16 * i;
        if (m >= M) continue;
        #pragma unroll
        for (int j = 0; j < 8; j++) {
            int n = n0 + tx + 16 * j;
            if (n >= N) continue;
            C[(size_t)m * ldc + n] = alpha * acc[i][j];
        }
    }
}

// ---------------- block-2 PV: split-K rank-1 updates -----------------------
#define KSPLIT 16
__global__ void __launch_bounds__(256) zero_o2()
{
    int idx = blockIdx.x * 256 + threadIdx.x;
    if (idx < NHEADS * NC * HDIM) g_o2[idx] = 0.f;
}
__global__ void __launch_bounds__(256) pv2_kernel()
{
    int h = blockIdx.y, ks = blockIdx.x;
    int chunk = (LC + KSPLIT - 1) / KSPLIT;
    int k0 = ks * chunk, k1 = min(LC, k0 + chunk);
    int d = threadIdx.x & 127, g = threadIdx.x >> 7;   // g: 0..1 -> i block
    const float* S = g_s2 + (size_t)h * NC * LC;
    const float* V = g_v2 + (size_t)h * LC * HDIM;
    float acc[10];
    #pragma unroll
    for (int i = 0; i < 10; ++i) acc[i] = 0.f;
    for (int k = k0; k < k1; ++k) {
        float v = V[(size_t)k * HDIM + d];
        #pragma unroll
        for (int i = 0; i < 10; ++i)
            acc[i] = fmaf(__ldg(S + (size_t)(g * 10 + i) * LC + k), v, acc[i]);
    }
    #pragma unroll
    for (int i = 0; i < 10; ++i)
        atomicAdd(&g_o2[((size_t)h * NC + g * 10 + i) * HDIM + d], acc[i]);
}
__global__ void __launch_bounds__(256) o2_to_cc()
{
    int idx = blockIdx.x * 256 + threadIdx.x;   // h*NC*HDIM
    if (idx >= NHEADS * NC * HDIM) return;
    int d = idx & 127;
    int i = (idx >> 7) % NC;
    int h = idx / (NC * HDIM);
    g_cch[(size_t)(LX + i) * CCW + h * HDIM + d] = __float2half_rn(g_o2[idx]);
}

// ---------------- convert fp32 -> fp16 -------------------------------------
__global__ void __launch_bounds__(256) convert_h(
    const float4* __restrict__ src, uint2* __restrict__ h, int n4)
{
    int idx = blockIdx.x * 256 + threadIdx.x;
    if (idx >= n4) return;
    float4 v = src[idx];
    uint2 r;
    r.x = pack2h(v.x, v.y);
    r.y = pack2h(v.z, v.w);
    h[idx] = r;
}

// ---------------- modulation: m = silu(vec) @ mod_w^T + mod_b --------------
__global__ void __launch_bounds__(128) mod_kernel(
    const float* __restrict__ vec, const float* __restrict__ mod_w,
    const float* __restrict__ mod_b)
{
    int n = blockIdx.x * 4 + (threadIdx.x >> 5);
    if (n >= 3 * HIDDEN) return;
    int lane = threadIdx.x & 31;
    const float* wrow = mod_w + (size_t)n * HIDDEN;
    float acc = 0.f;
    for (int k = lane; k < HIDDEN; k += 32) {
        float xv = vec[k];
        float s = xv / (1.f + __expf(-xv));
        acc = fmaf(s, wrow[k], acc);
    }
    acc = warp_sum(acc);
    if (lane == 0) g_mod[n] = acc + mod_b[n];
}

// ---------------- layernorm + modulate -> fp16 ------------------------------
__global__ void __launch_bounds__(256) ln_mod_kernel(
    const float* __restrict__ x, const float* __restrict__ concepts)
{
    __shared__ float sbuf[8];
    int row = blockIdx.x;
    const float* src = (row < LX) ? (x + (size_t)row * HIDDEN)
                                  : (concepts + (size_t)(row - LX) * HIDDEN);
    int tid = threadIdx.x;
    float v[6];
    float s = 0.f;
    #pragma unroll
    for (int i = 0; i < 6; i++) { v[i] = src[tid + 256 * i]; s += v[i]; }
    s = block_sum<256>(s, sbuf);
    float mu = s * (1.0f / 1536.0f);
    float s2 = 0.f;
    #pragma unroll
    for (int i = 0; i < 6; i++) { float d = v[i] - mu; s2 = fmaf(d, d, s2); }
    s2 = block_sum<256>(s2, sbuf);
    float rstd = rsqrtf(s2 * (1.0f / 1536.0f) + 1e-6f);
    #pragma unroll
    for (int i = 0; i < 6; i++) {
        int j = tid + 256 * i;
        float val = (1.f + g_mod[HIDDEN + j]) * ((v[i] - mu) * rstd) + g_mod[j];
        g_xmh[(size_t)row * HIDDEN + j] = __float2half_rn(val);
    }
}

// ---------------- RoPE helper (pair exchange via shfl) ---------------------
__device__ __forceinline__ float rope_pair(float a, const float* __restrict__ petab,
                                           int tok, int d)
{
    float b = __shfl_xor_sync(0xffffffffu, a, 1);
    int i = d >> 1;
    const float* p = petab + ((size_t)tok * 64 + i) * 4;
    if ((d & 1) == 0) return fmaf(p[0], a, p[1] * b);
    else              return fmaf(p[2], b, p[3] * a);
}

// ---------------- attention prep for x tokens ------------------------------
__global__ void __launch_bounds__(128) attn_prep1(
    const float* __restrict__ pe, const float* __restrict__ cpe,
    const float* __restrict__ q_scale, const float* __restrict__ k_scale)
{
    __shared__ float sbuf[4];
    int t = blockIdx.x, h = blockIdx.y, d = threadIdx.x;
    const float* hrow = g_h + (size_t)t * QKVW;
    float q = hrow[h * HDIM + d];
    float k = hrow[HIDDEN + h * HDIM + d];
    float v = hrow[2 * HIDDEN + h * HDIM + d];
    float msq = block_sum<128>(q * q, sbuf) * (1.f / 128.f);
    float msk = block_sum<128>(k * k, sbuf) * (1.f / 128.f);
    float qn = q * rsqrtf(msq + 1e-6f) * q_scale[d];
    float kn = k * rsqrtf(msk + 1e-6f) * k_scale[d];
    float qr = rope_pair(qn, pe, t, d);
    float kr = rope_pair(kn, pe, t, d);
    size_t qi = ((size_t)h * LX + t) * HDIM + d;
    g_q1h[qi] = __float2half_rn(qr);
    g_k1h[qi] = __float2half_rn(kr);
    g_v1h[qi] = __float2half_rn(v);
    if (t >= TXT) {
        int j = NC + (t - TXT);
        g_k2[((size_t)h * LC + j) * HDIM + d] = rope_pair(kn, cpe, j, d);
        g_v2[((size_t)h * LC + j) * HDIM + d] = v;
    }
}

// ---------------- attention prep for concept tokens ------------------------
__global__ void __launch_bounds__(128) attn_prep2(
    const float* __restrict__ cpe,
    const float* __restrict__ q_scale, const float* __restrict__ k_scale)
{
    __shared__ float sbuf[4];
    int i = blockIdx.x, h = blockIdx.y, d = threadIdx.x;
    const float* hrow = g_h + (size_t)(LX + i) * QKVW;
    float q = hrow[h * HDIM + d];
    float k = hrow[HIDDEN + h * HDIM + d];
    float v = hrow[2 * HIDDEN + h * HDIM + d];
    float msq = block_sum<128>(q * q, sbuf) * (1.f / 128.f);
    float msk = block_sum<128>(k * k, sbuf) * (1.f / 128.f);
    float qn = q * rsqrtf(msq + 1e-6f) * q_scale[d];
    float kn = k * rsqrtf(msk + 1e-6f) * k_scale[d];
    g_q2[((size_t)h * NC + i) * HDIM + d] = rope_pair(qn, cpe, i, d);
    g_k2[((size_t)h * LC + i) * HDIM + d] = rope_pair(kn, cpe, i, d);
    g_v2[((size_t)h * LC + i) * HDIM + d] = v;
}

// ---------------- row softmax (block-2 path) -------------------------------
__global__ void __launch_bounds__(256) softmax_rows(float* __restrict__ S, int ncol)
{
    __shared__ float sbuf[8];
    float* row = S + (size_t)blockIdx.x * ncol;
    int tid = threadIdx.x;
    float v[17];
    float mx = -1e30f;
    #pragma unroll
    for (int i = 0; i < 17; i++) {
        int c = tid + 256 * i;
        v[i] = (c < ncol) ? row[c] : -1e30f;
        mx = fmaxf(mx, v[i]);
    }
    mx = block_max<256>(mx, sbuf);
    float s = 0.f;
    #pragma unroll
    for (int i = 0; i < 17; i++) { v[i] = __expf(v[i] - mx); s += v[i]; }
    s = block_sum<256>(s, sbuf);
    float inv = 1.f / s;
    #pragma unroll
    for (int i = 0; i < 17; i++) {
        int c = tid + 256 * i;
        if (c < ncol) row[c] = v[i] * inv;
    }
}

// ---------------- residual: out = base + gate * block_out ------------------
__global__ void __launch_bounds__(256) final_kernel(
    const float* __restrict__ x, const float* __restrict__ concepts,
    float* __restrict__ out)
{
    size_t idx = (size_t)blockIdx.x * 256 + threadIdx.x;
    if (idx >= (size_t)NROWS * HIDDEN) return;
    int c = (int)(idx % HIDDEN);
    size_t r = idx / HIDDEN;
    float base = (r < LX) ? x[idx] : concepts[idx - (size_t)LX * HIDDEN];
    out[idx] = fmaf(g_mod[2 * HIDDEN + c], g_out[idx], base);
}

// ---------------------------------------------------------------------------
extern "C" void kernel_launch(void* const* d_in, const int* in_sizes, int n_in,
                              void* d_out, int out_size)
{
    const float* x        = (const float*)d_in[0];
    const float* concepts = (const float*)d_in[1];
    const float* vec      = (const float*)d_in[2];
    const float* pe       = (const float*)d_in[3];
    const float* cpe      = (const float*)d_in[4];
    const float* w1       = (const float*)d_in[5];
    const float* b1       = (const float*)d_in[6];
    const float* w2       = (const float*)d_in[7];
    const float* b2       = (const float*)d_in[8];
    const float* q_scale  = (const float*)d_in[9];
    const float* k_scale  = (const float*)d_in[10];
    const float* mod_w    = (const float*)d_in[11];
    const float* mod_b    = (const float*)d_in[12];
    float* out = (float*)d_out;

    void* p;
    cudaGetSymbolAddress(&p, g_xmh);  f16* xmh = (f16*)p;
    cudaGetSymbolAddress(&p, g_w1h);  f16* w1h = (f16*)p;
    cudaGetSymbolAddress(&p, g_w2h);  f16* w2h = (f16*)p;
    cudaGetSymbolAddress(&p, g_h);    float* hbuf = (float*)p;
    cudaGetSymbolAddress(&p, g_q1h);  f16* q1h = (f16*)p;
    cudaGetSymbolAddress(&p, g_k1h);  f16* k1h = (f16*)p;
    cudaGetSymbolAddress(&p, g_v1h);  f16* v1h = (f16*)p;
    cudaGetSymbolAddress(&p, g_q2);   float* q2b  = (float*)p;
    cudaGetSymbolAddress(&p, g_k2);   float* k2b  = (float*)p;
    cudaGetSymbolAddress(&p, g_s2);   float* s2b  = (float*)p;
    cudaGetSymbolAddress(&p, g_cch);  f16* cch = (f16*)p;
    cudaGetSymbolAddress(&p, g_out);  float* outb = (float*)p;

    cudaFuncSetAttribute(gemm_f16, cudaFuncAttributeMaxDynamicSharedMemorySize,
                         HG_SMEM);
    cudaFuncSetAttribute(flash1, cudaFuncAttributeMaxDynamicSharedMemorySize,
                         FLASH_SMEM);

    const float scl = 0.08838834764831845f;  // 1/sqrt(128)

    // modulation vector (shift | scale | gate)
    mod_kernel<<<(3 * HIDDEN + 3) / 4, 128>>>(vec, mod_w, mod_b);
    // weight conversion (fp16)
    {
        int n4 = (W1OUT * HIDDEN) / 4;
        convert_h<<<(n4 + 255) / 256, 256>>>((const float4*)w1, (uint2*)w1h, n4);
        n4 = (HIDDEN * CCW) / 4;
        convert_h<<<(n4 + 255) / 256, 256>>>((const float4*)w2, (uint2*)w2h, n4);
    }
    // layernorm + modulate -> xm fp16
    ln_mod_kernel<<<NROWS, 256>>>(x, concepts);
    // GEMM1: h = xm @ w1^T + b1; qkv cols -> fp32 h, mlp cols -> gelu cc fp16
    gemm_f16<<<dim3(W1OUT / 128, (NROWS + 127) / 128), 256, HG_SMEM>>>(
        xmh, HIDDEN, w1h, HIDDEN,
        hbuf, QKVW, cch, QKVW,
        NROWS, W1OUT, HIDDEN, b1);
    // rmsnorm + rope -> q/k/v fp16 (+ block2 fp32 arrays)
    attn_prep1<<<dim3(LX, NHEADS), 128>>>(pe, cpe, q_scale, k_scale);
    attn_prep2<<<dim3(NC, NHEADS), 128>>>(cpe, q_scale, k_scale);
    // block1 fused flash attention -> cc fp16 cols [0,1536)
    flash1<<<dim3(LX / 128, NHEADS), 256, FLASH_SMEM>>>(q1h, k1h, v1h, cch);
    // block2 attention (20 queries over 4116 keys)
    zero_o2<<<(NHEADS * NC * HDIM + 255) / 256, 256>>>();
    sgemm_abt<<<dim3((LC + 127) / 128, 1, NHEADS), 256>>>(
        q2b, HDIM, (long long)NC * HDIM, k2b, HDIM, (long long)LC * HDIM,
        s2b, LC, (long long)NC * LC, NC, LC, HDIM, scl);
    softmax_rows<<<NHEADS * NC, 256>>>(s2b, LC);
    pv2_kernel<<<dim3(KSPLIT, NHEADS), 256>>>();
    o2_to_cc<<<(NHEADS * NC * HDIM + 255) / 256, 256>>>();
    // GEMM2: out = cc @ w2^T + b2
    gemm_f16<<<dim3(HIDDEN / 128, (NROWS + 127) / 128), 256, HG_SMEM>>>(
        cch, CCW, w2h, CCW,
        outb, HIDDEN, nullptr, HIDDEN,
        NROWS, HIDDEN, CCW, b2);
    // residual + gate
    final_kernel<<<(unsigned)(((size_t)NROWS * HIDDEN + 255) / 256), 256>>>(
        x, concepts, out);
}

// round 10
// speedup vs baseline: 3.5409x; 1.0297x over previous
#include <cuda_runtime.h>
#include <cuda_fp16.h>
#include <math.h>
#include <stdint.h>

#define HIDDEN 1536
#define NHEADS 12
#define HDIM 128
#define MLPH 6144
#define TXT 256
#define LX 4352
#define NC 20
#define LC 4116
#define NROWS 4372          // LX + NC
#define W1OUT 10752         // 3*HIDDEN + MLPH
#define QKVW 4608           // 3*HIDDEN
#define CCW 7680            // HIDDEN + MLPH

typedef __half f16;

// ---------------- scratch (static device globals; no runtime allocation) ---
static __device__ float g_mod[3 * HIDDEN];
static __device__ f16   g_xmh[(size_t)NROWS * HIDDEN];
static __device__ f16   g_w1h[(size_t)W1OUT * HIDDEN];
static __device__ f16   g_w2h[(size_t)HIDDEN * CCW];
static __device__ float g_h[(size_t)NROWS * QKVW];
static __device__ f16   g_q1h[(size_t)NHEADS * LX * HDIM];
static __device__ f16   g_k1h[(size_t)NHEADS * LX * HDIM];
static __device__ f16   g_v1h[(size_t)NHEADS * LX * HDIM];
static __device__ float g_q2[(size_t)NHEADS * NC * HDIM];
static __device__ float g_k2[(size_t)NHEADS * LC * HDIM];
static __device__ float g_v2[(size_t)NHEADS * LC * HDIM];
static __device__ float g_s2[(size_t)NHEADS * NC * LC];
static __device__ float g_o2[(size_t)NHEADS * NC * HDIM];
static __device__ f16   g_cch[(size_t)NROWS * CCW];
static __device__ float g_out[(size_t)NROWS * HIDDEN];

// ---------------- reductions ----------------------------------------------
__device__ __forceinline__ float warp_sum(float v) {
    #pragma unroll
    for (int o = 16; o > 0; o >>= 1) v += __shfl_xor_sync(0xffffffffu, v, o);
    return v;
}
__device__ __forceinline__ float warp_max(float v) {
    #pragma unroll
    for (int o = 16; o > 0; o >>= 1) v = fmaxf(v, __shfl_xor_sync(0xffffffffu, v, o));
    return v;
}
template <int NT>
__device__ __forceinline__ float block_sum(float v, float* sbuf) {
    v = warp_sum(v);
    int lane = threadIdx.x & 31, w = threadIdx.x >> 5;
    if (lane == 0) sbuf[w] = v;
    __syncthreads();
    if (threadIdx.x < 32) {
        float x = (threadIdx.x < NT / 32) ? sbuf[threadIdx.x] : 0.f;
        x = warp_sum(x);
        if (threadIdx.x == 0) sbuf[0] = x;
    }
    __syncthreads();
    float r = sbuf[0];
    __syncthreads();
    return r;
}
template <int NT>
__device__ __forceinline__ float block_max(float v, float* sbuf) {
    v = warp_max(v);
    int lane = threadIdx.x & 31, w = threadIdx.x >> 5;
    if (lane == 0) sbuf[w] = v;
    __syncthreads();
    if (threadIdx.x < 32) {
        float x = (threadIdx.x < NT / 32) ? sbuf[threadIdx.x] : -1e30f;
        x = warp_max(x);
        if (threadIdx.x == 0) sbuf[0] = x;
    }
    __syncthreads();
    float r = sbuf[0];
    __syncthreads();
    return r;
}

// ---------------- helpers ---------------------------------------------------
__device__ __forceinline__ uint32_t pack2h(float x, float y) {
    __half2 h = __halves2half2(__float2half_rn(x), __float2half_rn(y));
    return *reinterpret_cast<uint32_t*>(&h);
}
__device__ __forceinline__ float gelu_f(float xv) {
    float inner = 0.7978845608028654f * fmaf(0.044715f * xv * xv, xv, xv);
    return 0.5f * xv * (1.f + tanhf(inner));
}

// ======================= HMMA helpers ======================================
__device__ __forceinline__ uint32_t smem_u32(const void* p) {
    uint32_t a;
    asm("{ .reg .u64 t; cvta.to.shared.u64 t, %1; cvt.u32.u64 %0, t; }"
        : "=r"(a) : "l"(p));
    return a;
}
__device__ __forceinline__ void ldsm4(uint32_t* r, uint32_t addr) {
    asm volatile("ldmatrix.sync.aligned.m8n8.x4.shared.b16 {%0,%1,%2,%3}, [%4];"
                 : "=r"(r[0]), "=r"(r[1]), "=r"(r[2]), "=r"(r[3]) : "r"(addr));
}
__device__ __forceinline__ void ldsm4t(uint32_t* r, uint32_t addr) {
    asm volatile("ldmatrix.sync.aligned.m8n8.x4.trans.shared.b16 {%0,%1,%2,%3}, [%4];"
                 : "=r"(r[0]), "=r"(r[1]), "=r"(r[2]), "=r"(r[3]) : "r"(addr));
}
__device__ __forceinline__ void mma_f16(float* c, const uint32_t* a,
                                        uint32_t b0, uint32_t b1) {
    asm volatile(
        "mma.sync.aligned.m16n8k16.row.col.f32.f16.f16.f32 "
        "{%0,%1,%2,%3}, {%4,%5,%6,%7}, {%8,%9}, {%0,%1,%2,%3};"
        : "+f"(c[0]), "+f"(c[1]), "+f"(c[2]), "+f"(c[3])
        : "r"(a[0]), "r"(a[1]), "r"(a[2]), "r"(a[3]), "r"(b0), "r"(b1));
}
__device__ __forceinline__ void cp_async16(uint32_t dst, const void* src, int sz) {
    asm volatile("cp.async.cg.shared.global [%0], [%1], 16, %2;"
                 :: "r"(dst), "l"(src), "r"(sz) : "memory");
}
__device__ __forceinline__ void cp_commit() {
    asm volatile("cp.async.commit_group;" ::: "memory");
}
__device__ __forceinline__ void cp_wait1() {
    asm volatile("cp.async.wait_group 1;" ::: "memory");
}
__device__ __forceinline__ void cp_wait2() {
    asm volatile("cp.async.wait_group 2;" ::: "memory");
}

// smem: per stage 2 tiles (A, B): 128 rows x 32 f16, row stride 80 B
#define SPB      80
#define T_BYTES  (128 * SPB)          // 10240
#define STAGE_B  (2 * T_BYTES)        // 20480
#define NSTAGE   4
#define HG_SMEM  (NSTAGE * STAGE_B)   // 81920 -> 2 CTAs/SM

// ======== fp16 GEMM: C = A@B^T + bias ======================================
__global__ void __launch_bounds__(256, 2) gemm_f16(
    const f16* __restrict__ Ah, int lda,
    const f16* __restrict__ Bh, int ldb,
    float* __restrict__ C, int ldc,
    f16* __restrict__ Gh, int gelu_n0,
    int M, int N, int K, const float* __restrict__ bias)
{
    extern __shared__ char smem[];
    uint32_t sbase = smem_u32(smem);
    int tid = threadIdx.x, wid = tid >> 5, lane = tid & 31;

    const int GRP = 8;
    int npn = gridDim.x, npm = gridDim.y;
    int pid = blockIdx.y * npn + blockIdx.x;
    int gsz = GRP * npn;
    int gid = pid / gsz;
    int fm = gid * GRP;
    int gm = min(GRP, npm - fm);
    int pid_m = fm + (pid % gsz) % gm;
    int pid_n = (pid % gsz) / gm;
    int m0 = pid_m * 128, n0 = pid_n * 128;

    int warp_m = wid & 3;
    int warp_n = wid >> 2;
    int lrow = lane & 15, lhalf = lane >> 4;

    uint32_t a_off[2], b_off[4];
    #pragma unroll
    for (int i = 0; i < 2; ++i)
        a_off[i] = (uint32_t)((warp_m * 32 + i * 16 + lrow) * SPB + lhalf * 16);
    #pragma unroll
    for (int g = 0; g < 4; ++g)
        b_off[g] = (uint32_t)((warp_n * 64 + g * 16 + lrow) * SPB + lhalf * 16);

    float acc[2][8][4];
    #pragma unroll
    for (int i = 0; i < 2; ++i)
        #pragma unroll
        for (int j = 0; j < 8; ++j)
            #pragma unroll
            for (int t = 0; t < 4; ++t) acc[i][j][t] = 0.f;

    int nch = K >> 5;

    auto issue = [&](int c) {
        if (c < nch) {
            int kc = c << 5;
            uint32_t sb = sbase + (uint32_t)(c % NSTAGE) * STAGE_B;
            #pragma unroll
            for (int u4 = 0; u4 < 4; ++u4) {
                int u = tid + 256 * u4;
                int tile = u >> 9;              // 0=A, 1=B
                int r = (u >> 2) & 127;
                int c16 = u & 3;
                uint32_t dst = sb + (uint32_t)(tile * T_BYTES + r * SPB + c16 * 16);
                if (tile == 0) {
                    int sz = (m0 + r < M) ? 16 : 0;
                    cp_async16(dst, Ah + (size_t)(m0 + r) * lda + kc + c16 * 8, sz);
                } else {
                    cp_async16(dst, Bh + (size_t)(n0 + r) * ldb + kc + c16 * 8, 16);
                }
            }
        }
        cp_commit();
    };

    issue(0); issue(1); issue(2);

    for (int c = 0; c < nch; ++c) {
        cp_wait2();
        __syncthreads();
        issue(c + 3);
        uint32_t sb = sbase + (uint32_t)(c % NSTAGE) * STAGE_B;
        #pragma unroll
        for (int k16 = 0; k16 < 2; ++k16) {
            uint32_t koff = (uint32_t)(k16 * 32);
            uint32_t ah[2][4], bh[4][4];
            #pragma unroll
            for (int i = 0; i < 2; ++i)
                ldsm4(ah[i], sb + 0 * T_BYTES + a_off[i] + koff);
            #pragma unroll
            for (int g = 0; g < 4; ++g)
                ldsm4(bh[g], sb + 1 * T_BYTES + b_off[g] + koff);
            #pragma unroll
            for (int i = 0; i < 2; ++i)
                #pragma unroll
                for (int j = 0; j < 8; ++j) {
                    int g = j >> 1, sI = j & 1;
                    mma_f16(acc[i][j], ah[i], bh[g][sI], bh[g][sI + 2]);
                }
        }
    }

    int trow = lane >> 2, tc2 = (lane & 3) * 2;
    #pragma unroll
    for (int i = 0; i < 2; ++i) {
        #pragma unroll
        for (int half = 0; half < 2; ++half) {
            int m = m0 + warp_m * 32 + i * 16 + half * 8 + trow;
            if (m >= M) continue;
            #pragma unroll
            for (int j = 0; j < 8; ++j) {
                int n = n0 + warp_n * 64 + j * 8 + tc2;
                float vx = acc[i][j][half * 2 + 0];
                float vy = acc[i][j][half * 2 + 1];
                if (bias) { vx += bias[n]; vy += bias[n + 1]; }
                if (n >= gelu_n0) {
                    vx = gelu_f(vx); vy = gelu_f(vy);
                    int cc = HIDDEN + n - gelu_n0;
                    *reinterpret_cast<uint32_t*>(Gh + (size_t)m * CCW + cc) =
                        pack2h(vx, vy);
                } else {
                    *reinterpret_cast<float2*>(C + (size_t)m * ldc + n) =
                        make_float2(vx, vy);
                }
            }
        }
    }
}

// ================= flash attention for block 1 =============================
#define BK 64
#define FSTR 272                       // 128*2 + 16 pad
#define FQ_PLANE (128 * FSTR)          // 34816
#define FK_PLANE (BK * FSTR)           // 17408
#define FS_OFF   FQ_PLANE              // 34816
#define FSTAGE   (2 * FK_PLANE)        // 34816 (K + V)
#define FNS      3
#define FLASH_SMEM (FS_OFF + FNS * FSTAGE)  // 139264
#define NKT (LX / BK)                  // 68

__global__ void __launch_bounds__(256, 1) flash1(
    const f16* __restrict__ Qh,
    const f16* __restrict__ Kh, const f16* __restrict__ Vh,
    f16* __restrict__ Och)
{
    extern __shared__ char smem[];
    uint32_t sbase = smem_u32(smem);
    int tid = threadIdx.x, wid = tid >> 5, lane = tid & 31;
    int head = blockIdx.y;
    int q0 = blockIdx.x * 128;
    size_t hb = (size_t)head * LX * HDIM;
    const f16* qp0 = Qh + hb + (size_t)q0 * HDIM;
    const f16* kp[2] = { Kh + hb, Vh + hb };

    #pragma unroll
    for (int u8 = 0; u8 < 8; ++u8) {
        int u = tid + 256 * u8;
        int r = (u >> 4) & 127, c = u & 15;
        cp_async16(sbase + (uint32_t)(r * FSTR + c * 16),
                   qp0 + (size_t)r * HDIM + c * 8, 16);
    }
    cp_commit();

    auto issueKV = [&](int it) {
        if (it < NKT) {
            int kv0 = it * BK;
            #pragma unroll
            for (int u8 = 0; u8 < 8; ++u8) {
                int u = tid + 256 * u8;
                int pl = u >> 10, r = (u >> 4) & 63, c = u & 15;
                cp_async16(sbase + (uint32_t)(FS_OFF + (it % FNS) * FSTAGE +
                                              pl * FK_PLANE + r * FSTR + c * 16),
                           kp[pl] + (size_t)(kv0 + r) * HDIM + c * 8, 16);
            }
        }
        cp_commit();
    };
    issueKV(0);
    issueKV(1);

    uint32_t a_addr = sbase + (uint32_t)((wid * 16 + (lane & 15)) * FSTR +
                                         (lane >> 4) * 16);
    uint32_t bk_rel = (uint32_t)((lane & 15) * FSTR + (lane >> 4) * 16);
    uint32_t bv_rel = (uint32_t)(((((lane >> 3) & 1) * 8) + (lane & 7)) * FSTR +
                                 ((lane >> 4) & 1) * 16);

    float accO[16][4];
    #pragma unroll
    for (int j = 0; j < 16; ++j)
        #pragma unroll
        for (int t = 0; t < 4; ++t) accO[j][t] = 0.f;
    float mrow0 = -1e30f, mrow1 = -1e30f, lsum0 = 0.f, lsum1 = 0.f;
    const float scl = 0.08838834764831845f;

    for (int it = 0; it < NKT; ++it) {
        cp_wait1();
        __syncthreads();
        issueKV(it + 2);
        uint32_t kb = sbase + FS_OFF + (uint32_t)(it % FNS) * FSTAGE;

        float s[8][4];
        #pragma unroll
        for (int j = 0; j < 8; ++j)
            #pragma unroll
            for (int t = 0; t < 4; ++t) s[j][t] = 0.f;
        #pragma unroll
        for (int ks = 0; ks < 8; ++ks) {
            uint32_t aqh[4];
            ldsm4(aqh, a_addr + ks * 32);
            uint32_t bh[4][4];
            #pragma unroll
            for (int g = 0; g < 4; ++g)
                ldsm4(bh[g], kb + bk_rel + g * (16 * FSTR) + ks * 32);
            #pragma unroll
            for (int j = 0; j < 8; ++j)
                mma_f16(s[j], aqh, bh[j >> 1][j & 1], bh[j >> 1][(j & 1) + 2]);
        }

        float m0 = -1e30f, m1 = -1e30f;
        #pragma unroll
        for (int j = 0; j < 8; ++j) {
            s[j][0] *= scl; s[j][1] *= scl; s[j][2] *= scl; s[j][3] *= scl;
            m0 = fmaxf(m0, fmaxf(s[j][0], s[j][1]));
            m1 = fmaxf(m1, fmaxf(s[j][2], s[j][3]));
        }
        m0 = fmaxf(m0, __shfl_xor_sync(0xffffffffu, m0, 1));
        m0 = fmaxf(m0, __shfl_xor_sync(0xffffffffu, m0, 2));
        m1 = fmaxf(m1, __shfl_xor_sync(0xffffffffu, m1, 1));
        m1 = fmaxf(m1, __shfl_xor_sync(0xffffffffu, m1, 2));
        float mn0 = fmaxf(mrow0, m0), mn1 = fmaxf(mrow1, m1);
        float al0 = __expf(mrow0 - mn0), al1 = __expf(mrow1 - mn1);
        mrow0 = mn0; mrow1 = mn1;

        uint32_t ph[8][2];
        float ps0 = 0.f, ps1 = 0.f;
        #pragma unroll
        for (int j = 0; j < 8; ++j) {
            float p00 = __expf(s[j][0] - mn0), p01 = __expf(s[j][1] - mn0);
            float p10 = __expf(s[j][2] - mn1), p11 = __expf(s[j][3] - mn1);
            ps0 += p00 + p01; ps1 += p10 + p11;
            ph[j][0] = pack2h(p00, p01);
            ph[j][1] = pack2h(p10, p11);
        }
        lsum0 = lsum0 * al0 + ps0;
        lsum1 = lsum1 * al1 + ps1;
        #pragma unroll
        for (int j = 0; j < 16; ++j) {
            accO[j][0] *= al0; accO[j][1] *= al0;
            accO[j][2] *= al1; accO[j][3] *= al1;
        }

        uint32_t vb = kb + FK_PLANE;
        #pragma unroll
        for (int s4 = 0; s4 < 4; ++s4) {
            uint32_t Ahf[4] = { ph[2 * s4][0], ph[2 * s4][1],
                                ph[2 * s4 + 1][0], ph[2 * s4 + 1][1] };
            #pragma unroll
            for (int g = 0; g < 8; ++g) {
                uint32_t bvh[4];
                ldsm4t(bvh, vb + bv_rel + s4 * (16 * FSTR) + g * 32);
                mma_f16(accO[2 * g],     Ahf, bvh[0], bvh[1]);
                mma_f16(accO[2 * g + 1], Ahf, bvh[2], bvh[3]);
            }
        }
    }

    lsum0 += __shfl_xor_sync(0xffffffffu, lsum0, 1);
    lsum0 += __shfl_xor_sync(0xffffffffu, lsum0, 2);
    lsum1 += __shfl_xor_sync(0xffffffffu, lsum1, 1);
    lsum1 += __shfl_xor_sync(0xffffffffu, lsum1, 2);
    float inv0 = 1.f / lsum0, inv1 = 1.f / lsum1;
    int r0 = q0 + wid * 16 + (lane >> 2);
    int cbase = head * HDIM + (lane & 3) * 2;
    #pragma unroll
    for (int j = 0; j < 16; ++j) {
        int c = cbase + j * 8;
        *reinterpret_cast<uint32_t*>(Och + (size_t)r0 * CCW + c) =
            pack2h(accO[j][0] * inv0, accO[j][1] * inv0);
        *reinterpret_cast<uint32_t*>(Och + (size_t)(r0 + 8) * CCW + c) =
            pack2h(accO[j][2] * inv1, accO[j][3] * inv1);
    }
}

// ---------------- SIMT GEMM (block-2 QK^T only) ----------------------------
__global__ void __launch_bounds__(256) sgemm_abt(
    const float* __restrict__ A, int lda, long long sA,
    const float* __restrict__ B, int ldb, long long sB,
    float* __restrict__ C, int ldc, long long sC,
    int M, int N, int K, float alpha)
{
    __shared__ float As[8][128];
    __shared__ float Bs[8][128];
    int bz = blockIdx.z;
    A += (size_t)sA * bz;
    B += (size_t)sB * bz;
    C += (size_t)sC * bz;
    int m0 = blockIdx.y * 128;
    int n0 = blockIdx.x * 128;
    int tid = threadIdx.x;
    int tx = tid & 15, ty = tid >> 4;
    int lrow = tid >> 1;
    int lcol = (tid & 1) * 4;

    float acc[8][8];
    #pragma unroll
    for (int i = 0; i < 8; i++)
        #pragma unroll
        for (int j = 0; j < 8; j++) acc[i][j] = 0.f;

    for (int k0 = 0; k0 < K; k0 += 8) {
        float4 av = make_float4(0.f, 0.f, 0.f, 0.f);
        float4 bv = make_float4(0.f, 0.f, 0.f, 0.f);
        if (m0 + lrow < M && k0 + lcol < K)
            av = *reinterpret_cast<const float4*>(A + (size_t)(m0 + lrow) * lda + k0 + lcol);
        if (n0 + lrow < N && k0 + lcol < K)
            bv = *reinterpret_cast<const float4*>(B + (size_t)(n0 + lrow) * ldb + k0 + lcol);
        As[lcol + 0][lrow] = av.x; As[lcol + 1][lrow] = av.y;
        As[lcol + 2][lrow] = av.z; As[lcol + 3][lrow] = av.w;
        Bs[lcol + 0][lrow] = bv.x; Bs[lcol + 1][lrow] = bv.y;
        Bs[lcol + 2][lrow] = bv.z; Bs[lcol + 3][lrow] = bv.w;
        __syncthreads();
        #pragma unroll
        for (int k = 0; k < 8; k++) {
            float ra[8], rb[8];
            #pragma unroll
            for (int i = 0; i < 8; i++) ra[i] = As[k][ty + 16 * i];
            #pragma unroll
            for (int j = 0; j < 8; j++) rb[j] = Bs[k][tx + 16 * j];
            #pragma unroll
            for (int i = 0; i < 8; i++)
                #pragma unroll
                for (int j = 0; j < 8; j++)
                    acc[i][j] = fmaf(ra[i], rb[j], acc[i][j]);
        }
        __syncthreads();
    }

    #pragma unroll
    for (int i = 0; i < 8; i++) {
        int m = m0 + ty + 16 * i;
        if (m >= M) continue;
        #pragma unroll
        for (int j = 0; j < 8; j++) {
            int n = n0 + tx + 16 * j;
            if (n >= N) continue;
            C[(size_t)m * ldc + n] = alpha * acc[i][j];
        }
    }
}

// ---------------- block-2 PV: split-K rank-1 updates -----------------------
#define KSPLIT 16
__global__ void __launch_bounds__(256) zero_o2()
{
    int idx = blockIdx.x * 256 + threadIdx.x;
    if (idx < NHEADS * NC * HDIM) g_o2[idx] = 0.f;
}
__global__ void __launch_bounds__(256) pv2_kernel()
{
    int h = blockIdx.y, ks = blockIdx.x;
    int chunk = (LC + KSPLIT - 1) / KSPLIT;
    int k0 = ks * chunk, k1 = min(LC, k0 + chunk);
    int d = threadIdx.x & 127, g = threadIdx.x >> 7;   // g: 0..1 -> i block
    const float* S = g_s2 + (size_t)h * NC * LC;
    const float* V = g_v2 + (size_t)h * LC * HDIM;
    float acc[10];
    #pragma unroll
    for (int i = 0; i < 10; ++i) acc[i] = 0.f;
    for (int k = k0; k < k1; ++k) {
        float v = V[(size_t)k * HDIM + d];
        #pragma unroll
        for (int i = 0; i < 10; ++i)
            acc[i] = fmaf(__ldg(S + (size_t)(g * 10 + i) * LC + k), v, acc[i]);
    }
    #pragma unroll
    for (int i = 0; i < 10; ++i)
        atomicAdd(&g_o2[((size_t)h * NC + g * 10 + i) * HDIM + d], acc[i]);
}
__global__ void __launch_bounds__(256) o2_to_cc()
{
    int idx = blockIdx.x * 256 + threadIdx.x;   // h*NC*HDIM
    if (idx >= NHEADS * NC * HDIM) return;
    int d = idx & 127;
    int i = (idx >> 7) % NC;
    int h = idx / (NC * HDIM);
    g_cch[(size_t)(LX + i) * CCW + h * HDIM + d] = __float2half_rn(g_o2[idx]);
}

// ---------------- convert fp32 -> fp16 -------------------------------------
__global__ void __launch_bounds__(256) convert_h(
    const float4* __restrict__ src, uint2* __restrict__ h, int n4)
{
    int idx = blockIdx.x * 256 + threadIdx.x;
    if (idx >= n4) return;
    float4 v = src[idx];
    uint2 r;
    r.x = pack2h(v.x, v.y);
    r.y = pack2h(v.z, v.w);
    h[idx] = r;
}

// ---------------- modulation: m = silu(vec) @ mod_w^T + mod_b --------------
__global__ void __launch_bounds__(128) mod_kernel(
    const float* __restrict__ vec, const float* __restrict__ mod_w,
    const float* __restrict__ mod_b)
{
    int n = blockIdx.x * 4 + (threadIdx.x >> 5);
    if (n >= 3 * HIDDEN) return;
    int lane = threadIdx.x & 31;
    const float* wrow = mod_w + (size_t)n * HIDDEN;
    float acc = 0.f;
    for (int k = lane; k < HIDDEN; k += 32) {
        float xv = vec[k];
        float s = xv / (1.f + __expf(-xv));
        acc = fmaf(s, wrow[k], acc);
    }
    acc = warp_sum(acc);
    if (lane == 0) g_mod[n] = acc + mod_b[n];
}

// ---------------- layernorm + modulate -> fp16 ------------------------------
__global__ void __launch_bounds__(256) ln_mod_kernel(
    const float* __restrict__ x, const float* __restrict__ concepts)
{
    __shared__ float sbuf[8];
    int row = blockIdx.x;
    const float* src = (row < LX) ? (x + (size_t)row * HIDDEN)
                                  : (concepts + (size_t)(row - LX) * HIDDEN);
    int tid = threadIdx.x;
    float v[6];
    float s = 0.f;
    #pragma unroll
    for (int i = 0; i < 6; i++) { v[i] = src[tid + 256 * i]; s += v[i]; }
    s = block_sum<256>(s, sbuf);
    float mu = s * (1.0f / 1536.0f);
    float s2 = 0.f;
    #pragma unroll
    for (int i = 0; i < 6; i++) { float d = v[i] - mu; s2 = fmaf(d, d, s2); }
    s2 = block_sum<256>(s2, sbuf);
    float rstd = rsqrtf(s2 * (1.0f / 1536.0f) + 1e-6f);
    #pragma unroll
    for (int i = 0; i < 6; i++) {
        int j = tid + 256 * i;
        float val = (1.f + g_mod[HIDDEN + j]) * ((v[i] - mu) * rstd) + g_mod[j];
        g_xmh[(size_t)row * HIDDEN + j] = __float2half_rn(val);
    }
}

// ---------------- RoPE helper (pair exchange via shfl) ---------------------
__device__ __forceinline__ float rope_pair(float a, const float* __restrict__ petab,
                                           int tok, int d)
{
    float b = __shfl_xor_sync(0xffffffffu, a, 1);
    int i = d >> 1;
    const float* p = petab + ((size_t)tok * 64 + i) * 4;
    if ((d & 1) == 0) return fmaf(p[0], a, p[1] * b);
    else              return fmaf(p[2], b, p[3] * a);
}

// ---------------- attention prep for x tokens ------------------------------
__global__ void __launch_bounds__(128) attn_prep1(
    const float* __restrict__ pe, const float* __restrict__ cpe,
    const float* __restrict__ q_scale, const float* __restrict__ k_scale)
{
    __shared__ float sbuf[4];
    int t = blockIdx.x, h = blockIdx.y, d = threadIdx.x;
    const float* hrow = g_h + (size_t)t * QKVW;
    float q = hrow[h * HDIM + d];
    float k = hrow[HIDDEN + h * HDIM + d];
    float v = hrow[2 * HIDDEN + h * HDIM + d];
    float msq = block_sum<128>(q * q, sbuf) * (1.f / 128.f);
    float msk = block_sum<128>(k * k, sbuf) * (1.f / 128.f);
    float qn = q * rsqrtf(msq + 1e-6f) * q_scale[d];
    float kn = k * rsqrtf(msk + 1e-6f) * k_scale[d];
    float qr = rope_pair(qn, pe, t, d);
    float kr = rope_pair(kn, pe, t, d);
    size_t qi = ((size_t)h * LX + t) * HDIM + d;
    g_q1h[qi] = __float2half_rn(qr);
    g_k1h[qi] = __float2half_rn(kr);
    g_v1h[qi] = __float2half_rn(v);
    if (t >= TXT) {
        int j = NC + (t - TXT);
        g_k2[((size_t)h * LC + j) * HDIM + d] = rope_pair(kn, cpe, j, d);
        g_v2[((size_t)h * LC + j) * HDIM + d] = v;
    }
}

// ---------------- attention prep for concept tokens ------------------------
__global__ void __launch_bounds__(128) attn_prep2(
    const float* __restrict__ cpe,
    const float* __restrict__ q_scale, const float* __restrict__ k_scale)
{
    __shared__ float sbuf[4];
    int i = blockIdx.x, h = blockIdx.y, d = threadIdx.x;
    const float* hrow = g_h + (size_t)(LX + i) * QKVW;
    float q = hrow[h * HDIM + d];
    float k = hrow[HIDDEN + h * HDIM + d];
    float v = hrow[2 * HIDDEN + h * HDIM + d];
    float msq = block_sum<128>(q * q, sbuf) * (1.f / 128.f);
    float msk = block_sum<128>(k * k, sbuf) * (1.f / 128.f);
    float qn = q * rsqrtf(msq + 1e-6f) * q_scale[d];
    float kn = k * rsqrtf(msk + 1e-6f) * k_scale[d];
    g_q2[((size_t)h * NC + i) * HDIM + d] = rope_pair(qn, cpe, i, d);
    g_k2[((size_t)h * LC + i) * HDIM + d] = rope_pair(kn, cpe, i, d);
    g_v2[((size_t)h * LC + i) * HDIM + d] = v;
}

// ---------------- row softmax (block-2 path) -------------------------------
__global__ void __launch_bounds__(256) softmax_rows(float* __restrict__ S, int ncol)
{
    __shared__ float sbuf[8];
    float* row = S + (size_t)blockIdx.x * ncol;
    int tid = threadIdx.x;
    float v[17];
    float mx = -1e30f;
    #pragma unroll
    for (int i = 0; i < 17; i++) {
        int c = tid + 256 * i;
        v[i] = (c < ncol) ? row[c] : -1e30f;
        mx = fmaxf(mx, v[i]);
    }
    mx = block_max<256>(mx, sbuf);
    float s = 0.f;
    #pragma unroll
    for (int i = 0; i < 17; i++) { v[i] = __expf(v[i] - mx); s += v[i]; }
    s = block_sum<256>(s, sbuf);
    float inv = 1.f / s;
    #pragma unroll
    for (int i = 0; i < 17; i++) {
        int c = tid + 256 * i;
        if (c < ncol) row[c] = v[i] * inv;
    }
}

// ---------------- residual: out = base + gate * block_out ------------------
__global__ void __launch_bounds__(256) final_kernel(
    const float* __restrict__ x, const float* __restrict__ concepts,
    float* __restrict__ out)
{
    size_t idx = (size_t)blockIdx.x * 256 + threadIdx.x;
    if (idx >= (size_t)NROWS * HIDDEN) return;
    int c = (int)(idx % HIDDEN);
    size_t r = idx / HIDDEN;
    float base = (r < LX) ? x[idx] : concepts[idx - (size_t)LX * HIDDEN];
    out[idx] = fmaf(g_mod[2 * HIDDEN + c], g_out[idx], base);
}

// ---------------------------------------------------------------------------
extern "C" void kernel_launch(void* const* d_in, const int* in_sizes, int n_in,
                              void* d_out, int out_size)
{
    const float* x        = (const float*)d_in[0];
    const float* concepts = (const float*)d_in[1];
    const float* vec      = (const float*)d_in[2];
    const float* pe       = (const float*)d_in[3];
    const float* cpe      = (const float*)d_in[4];
    const float* w1       = (const float*)d_in[5];
    const float* b1       = (const float*)d_in[6];
    const float* w2       = (const float*)d_in[7];
    const float* b2       = (const float*)d_in[8];
    const float* q_scale  = (const float*)d_in[9];
    const float* k_scale  = (const float*)d_in[10];
    const float* mod_w    = (const float*)d_in[11];
    const float* mod_b    = (const float*)d_in[12];
    float* out = (float*)d_out;

    void* p;
    cudaGetSymbolAddress(&p, g_xmh);  f16* xmh = (f16*)p;
    cudaGetSymbolAddress(&p, g_w1h);  f16* w1h = (f16*)p;
    cudaGetSymbolAddress(&p, g_w2h);  f16* w2h = (f16*)p;
    cudaGetSymbolAddress(&p, g_h);    float* hbuf = (float*)p;
    cudaGetSymbolAddress(&p, g_q1h);  f16* q1h = (f16*)p;
    cudaGetSymbolAddress(&p, g_k1h);  f16* k1h = (f16*)p;
    cudaGetSymbolAddress(&p, g_v1h);  f16* v1h = (f16*)p;
    cudaGetSymbolAddress(&p, g_q2);   float* q2b  = (float*)p;
    cudaGetSymbolAddress(&p, g_k2);   float* k2b  = (float*)p;
    cudaGetSymbolAddress(&p, g_s2);   float* s2b  = (float*)p;
    cudaGetSymbolAddress(&p, g_cch);  f16* cch = (f16*)p;
    cudaGetSymbolAddress(&p, g_out);  float* outb = (float*)p;

    // one-time side stream + fork/join events (created on first, uncaptured call)
    static cudaStream_t s1 = nullptr;
    static cudaEvent_t evFork = nullptr, evW1 = nullptr, evFork2 = nullptr,
                       evSide = nullptr;
    if (s1 == nullptr) {
        cudaStreamCreateWithFlags(&s1, cudaStreamNonBlocking);
        cudaEventCreateWithFlags(&evFork, cudaEventDisableTiming);
        cudaEventCreateWithFlags(&evW1, cudaEventDisableTiming);
        cudaEventCreateWithFlags(&evFork2, cudaEventDisableTiming);
        cudaEventCreateWithFlags(&evSide, cudaEventDisableTiming);
        cudaFuncSetAttribute(gemm_f16,
                             cudaFuncAttributeMaxDynamicSharedMemorySize, HG_SMEM);
        cudaFuncSetAttribute(flash1,
                             cudaFuncAttributeMaxDynamicSharedMemorySize, FLASH_SMEM);
    }

    const float scl = 0.08838834764831845f;  // 1/sqrt(128)

    // fork: side stream converts weights while main does mod + layernorm
    cudaEventRecord(evFork, 0);
    cudaStreamWaitEvent(s1, evFork, 0);
    {
        int n4 = (W1OUT * HIDDEN) / 4;
        convert_h<<<(n4 + 255) / 256, 256, 0, s1>>>(
            (const float4*)w1, (uint2*)w1h, n4);
    }
    cudaEventRecord(evW1, s1);
    {
        // w2 conversion + o2 zeroing: only needed much later; stays on s1
        int n4 = (HIDDEN * CCW) / 4;
        convert_h<<<(n4 + 255) / 256, 256, 0, s1>>>(
            (const float4*)w2, (uint2*)w2h, n4);
        zero_o2<<<(NHEADS * NC * HDIM + 255) / 256, 256, 0, s1>>>();
    }

    // main: modulation + layernorm
    mod_kernel<<<(3 * HIDDEN + 3) / 4, 128>>>(vec, mod_w, mod_b);
    ln_mod_kernel<<<NROWS, 256>>>(x, concepts);

    // join w1 before GEMM1
    cudaStreamWaitEvent(0, evW1, 0);
    // GEMM1: h = xm @ w1^T + b1; qkv cols -> fp32 h, mlp cols -> gelu cc fp16
    gemm_f16<<<dim3(W1OUT / 128, (NROWS + 127) / 128), 256, HG_SMEM>>>(
        xmh, HIDDEN, w1h, HIDDEN,
        hbuf, QKVW, cch, QKVW,
        NROWS, W1OUT, HIDDEN, b1);
    // rmsnorm + rope -> q/k/v fp16 (+ block2 fp32 arrays)
    attn_prep1<<<dim3(LX, NHEADS), 128>>>(pe, cpe, q_scale, k_scale);
    attn_prep2<<<dim3(NC, NHEADS), 128>>>(cpe, q_scale, k_scale);

    // fork: block-2 chain on s1 concurrent with flash1 on main
    cudaEventRecord(evFork2, 0);
    cudaStreamWaitEvent(s1, evFork2, 0);
    sgemm_abt<<<dim3((LC + 127) / 128, 1, NHEADS), 256, 0, s1>>>(
        q2b, HDIM, (long long)NC * HDIM, k2b, HDIM, (long long)LC * HDIM,
        s2b, LC, (long long)NC * LC, NC, LC, HDIM, scl);
    softmax_rows<<<NHEADS * NC, 256, 0, s1>>>(s2b, LC);
    pv2_kernel<<<dim3(KSPLIT, NHEADS), 256, 0, s1>>>();
    o2_to_cc<<<(NHEADS * NC * HDIM + 255) / 256, 256, 0, s1>>>();
    cudaEventRecord(evSide, s1);

    // main: block1 fused flash attention -> cc fp16 cols [0,1536)
    flash1<<<dim3(LX / 128, NHEADS), 256, FLASH_SMEM>>>(q1h, k1h, v1h, cch);

    // join side (implies w2 conversion done) before GEMM2
    cudaStreamWaitEvent(0, evSide, 0);
    // GEMM2: out = cc @ w2^T + b2
    gemm_f16<<<dim3(HIDDEN / 128, (NROWS + 127) / 128), 256, HG_SMEM>>>(
        cch, CCW, w2h, CCW,
        outb, HIDDEN, nullptr, HIDDEN,
        NROWS, HIDDEN, CCW, b2);
    // residual + gate
    final_kernel<<<(unsigned)(((size_t)NROWS * HIDDEN + 255) / 256), 256>>>(
        x, concepts, out);
}

// round 11
// speedup vs baseline: 3.8055x; 1.0747x over previous
#include <cuda_runtime.h>
#include <cuda_fp16.h>
#include <math.h>
#include <stdint.h>

#define HIDDEN 1536
#define NHEADS 12
#define HDIM 128
#define MLPH 6144
#define TXT 256
#define LX 4352
#define NC 20
#define LC 4116
#define NROWS 4372          // LX + NC
#define W1OUT 10752         // 3*HIDDEN + MLPH
#define QKVW 4608           // 3*HIDDEN
#define CCW 7680            // HIDDEN + MLPH

typedef __half f16;

// ---------------- scratch (static device globals; no runtime allocation) ---
static __device__ float g_mod[3 * HIDDEN];
static __device__ f16   g_xmh[(size_t)NROWS * HIDDEN];
static __device__ f16   g_w1h[(size_t)W1OUT * HIDDEN];
static __device__ f16   g_w2h[(size_t)HIDDEN * CCW];
static __device__ float g_h[(size_t)NROWS * QKVW];
static __device__ f16   g_q1h[(size_t)NHEADS * LX * HDIM];
static __device__ f16   g_k1h[(size_t)NHEADS * LX * HDIM];
static __device__ f16   g_v1h[(size_t)NHEADS * LX * HDIM];
static __device__ float g_q2[(size_t)NHEADS * NC * HDIM];
static __device__ float g_k2[(size_t)NHEADS * LC * HDIM];
static __device__ float g_v2[(size_t)NHEADS * LC * HDIM];
static __device__ float g_s2[(size_t)NHEADS * NC * LC];
static __device__ float g_o2[(size_t)NHEADS * NC * HDIM];
static __device__ f16   g_cch[(size_t)NROWS * CCW];
static __device__ float g_out[(size_t)NROWS * HIDDEN];

// ---------------- reductions ----------------------------------------------
__device__ __forceinline__ float warp_sum(float v) {
    #pragma unroll
    for (int o = 16; o > 0; o >>= 1) v += __shfl_xor_sync(0xffffffffu, v, o);
    return v;
}
__device__ __forceinline__ float warp_max(float v) {
    #pragma unroll
    for (int o = 16; o > 0; o >>= 1) v = fmaxf(v, __shfl_xor_sync(0xffffffffu, v, o));
    return v;
}
template <int NT>
__device__ __forceinline__ float block_sum(float v, float* sbuf) {
    v = warp_sum(v);
    int lane = threadIdx.x & 31, w = threadIdx.x >> 5;
    if (lane == 0) sbuf[w] = v;
    __syncthreads();
    if (threadIdx.x < 32) {
        float x = (threadIdx.x < NT / 32) ? sbuf[threadIdx.x] : 0.f;
        x = warp_sum(x);
        if (threadIdx.x == 0) sbuf[0] = x;
    }
    __syncthreads();
    float r = sbuf[0];
    __syncthreads();
    return r;
}
template <int NT>
__device__ __forceinline__ float block_max(float v, float* sbuf) {
    v = warp_max(v);
    int lane = threadIdx.x & 31, w = threadIdx.x >> 5;
    if (lane == 0) sbuf[w] = v;
    __syncthreads();
    if (threadIdx.x < 32) {
        float x = (threadIdx.x < NT / 32) ? sbuf[threadIdx.x] : -1e30f;
        x = warp_max(x);
        if (threadIdx.x == 0) sbuf[0] = x;
    }
    __syncthreads();
    float r = sbuf[0];
    __syncthreads();
    return r;
}

// ---------------- helpers ---------------------------------------------------
__device__ __forceinline__ uint32_t pack2h(float x, float y) {
    __half2 h = __halves2half2(__float2half_rn(x), __float2half_rn(y));
    return *reinterpret_cast<uint32_t*>(&h);
}
__device__ __forceinline__ float gelu_f(float xv) {
    float inner = 0.7978845608028654f * fmaf(0.044715f * xv * xv, xv, xv);
    return 0.5f * xv * (1.f + tanhf(inner));
}

// ======================= HMMA helpers ======================================
__device__ __forceinline__ uint32_t smem_u32(const void* p) {
    uint32_t a;
    asm("{ .reg .u64 t; cvta.to.shared.u64 t, %1; cvt.u32.u64 %0, t; }"
        : "=r"(a) : "l"(p));
    return a;
}
__device__ __forceinline__ void ldsm4(uint32_t* r, uint32_t addr) {
    asm volatile("ldmatrix.sync.aligned.m8n8.x4.shared.b16 {%0,%1,%2,%3}, [%4];"
                 : "=r"(r[0]), "=r"(r[1]), "=r"(r[2]), "=r"(r[3]) : "r"(addr));
}
__device__ __forceinline__ void ldsm4t(uint32_t* r, uint32_t addr) {
    asm volatile("ldmatrix.sync.aligned.m8n8.x4.trans.shared.b16 {%0,%1,%2,%3}, [%4];"
                 : "=r"(r[0]), "=r"(r[1]), "=r"(r[2]), "=r"(r[3]) : "r"(addr));
}
__device__ __forceinline__ void mma_f16(float* c, const uint32_t* a,
                                        uint32_t b0, uint32_t b1) {
    asm volatile(
        "mma.sync.aligned.m16n8k16.row.col.f32.f16.f16.f32 "
        "{%0,%1,%2,%3}, {%4,%5,%6,%7}, {%8,%9}, {%0,%1,%2,%3};"
        : "+f"(c[0]), "+f"(c[1]), "+f"(c[2]), "+f"(c[3])
        : "r"(a[0]), "r"(a[1]), "r"(a[2]), "r"(a[3]), "r"(b0), "r"(b1));
}
__device__ __forceinline__ void cp_async16(uint32_t dst, const void* src, int sz) {
    asm volatile("cp.async.cg.shared.global [%0], [%1], 16, %2;"
                 :: "r"(dst), "l"(src), "r"(sz) : "memory");
}
__device__ __forceinline__ void cp_commit() {
    asm volatile("cp.async.commit_group;" ::: "memory");
}
__device__ __forceinline__ void cp_wait1() {
    asm volatile("cp.async.wait_group 1;" ::: "memory");
}
__device__ __forceinline__ void cp_wait2() {
    asm volatile("cp.async.wait_group 2;" ::: "memory");
}

// smem: per stage 2 tiles (A, B): 128 rows x 32 f16, row stride 80 B
#define SPB      80
#define T_BYTES  (128 * SPB)          // 10240
#define STAGE_B  (2 * T_BYTES)        // 20480
#define NSTAGE   4
#define HG_SMEM  (NSTAGE * STAGE_B)   // 81920 -> 2 CTAs/SM

// ======== fp16 GEMM: C = A@B^T + bias ======================================
__global__ void __launch_bounds__(256, 2) gemm_f16(
    const f16* __restrict__ Ah, int lda,
    const f16* __restrict__ Bh, int ldb,
    float* __restrict__ C, int ldc,
    f16* __restrict__ Gh, int gelu_n0,
    int M, int N, int K, const float* __restrict__ bias)
{
    extern __shared__ char smem[];
    uint32_t sbase = smem_u32(smem);
    int tid = threadIdx.x, wid = tid >> 5, lane = tid & 31;

    const int GRP = 8;
    int npn = gridDim.x, npm = gridDim.y;
    int pid = blockIdx.y * npn + blockIdx.x;
    int gsz = GRP * npn;
    int gid = pid / gsz;
    int fm = gid * GRP;
    int gm = min(GRP, npm - fm);
    int pid_m = fm + (pid % gsz) % gm;
    int pid_n = (pid % gsz) / gm;
    int m0 = pid_m * 128, n0 = pid_n * 128;

    int warp_m = wid & 3;
    int warp_n = wid >> 2;
    int lrow = lane & 15, lhalf = lane >> 4;

    uint32_t a_off[2], b_off[4];
    #pragma unroll
    for (int i = 0; i < 2; ++i)
        a_off[i] = (uint32_t)((warp_m * 32 + i * 16 + lrow) * SPB + lhalf * 16);
    #pragma unroll
    for (int g = 0; g < 4; ++g)
        b_off[g] = (uint32_t)((warp_n * 64 + g * 16 + lrow) * SPB + lhalf * 16);

    float acc[2][8][4];
    #pragma unroll
    for (int i = 0; i < 2; ++i)
        #pragma unroll
        for (int j = 0; j < 8; ++j)
            #pragma unroll
            for (int t = 0; t < 4; ++t) acc[i][j][t] = 0.f;

    int nch = K >> 5;

    auto issue = [&](int c) {
        if (c < nch) {
            int kc = c << 5;
            uint32_t sb = sbase + (uint32_t)(c % NSTAGE) * STAGE_B;
            #pragma unroll
            for (int u4 = 0; u4 < 4; ++u4) {
                int u = tid + 256 * u4;
                int tile = u >> 9;              // 0=A, 1=B
                int r = (u >> 2) & 127;
                int c16 = u & 3;
                uint32_t dst = sb + (uint32_t)(tile * T_BYTES + r * SPB + c16 * 16);
                if (tile == 0) {
                    int sz = (m0 + r < M) ? 16 : 0;
                    cp_async16(dst, Ah + (size_t)(m0 + r) * lda + kc + c16 * 8, sz);
                } else {
                    cp_async16(dst, Bh + (size_t)(n0 + r) * ldb + kc + c16 * 8, 16);
                }
            }
        }
        cp_commit();
    };

    issue(0); issue(1); issue(2);

    for (int c = 0; c < nch; ++c) {
        cp_wait2();
        __syncthreads();
        issue(c + 3);
        uint32_t sb = sbase + (uint32_t)(c % NSTAGE) * STAGE_B;
        #pragma unroll
        for (int k16 = 0; k16 < 2; ++k16) {
            uint32_t koff = (uint32_t)(k16 * 32);
            uint32_t ah[2][4], bh[4][4];
            #pragma unroll
            for (int i = 0; i < 2; ++i)
                ldsm4(ah[i], sb + 0 * T_BYTES + a_off[i] + koff);
            #pragma unroll
            for (int g = 0; g < 4; ++g)
                ldsm4(bh[g], sb + 1 * T_BYTES + b_off[g] + koff);
            #pragma unroll
            for (int i = 0; i < 2; ++i)
                #pragma unroll
                for (int j = 0; j < 8; ++j) {
                    int g = j >> 1, sI = j & 1;
                    mma_f16(acc[i][j], ah[i], bh[g][sI], bh[g][sI + 2]);
                }
        }
    }

    int trow = lane >> 2, tc2 = (lane & 3) * 2;
    #pragma unroll
    for (int i = 0; i < 2; ++i) {
        #pragma unroll
        for (int half = 0; half < 2; ++half) {
            int m = m0 + warp_m * 32 + i * 16 + half * 8 + trow;
            if (m >= M) continue;
            #pragma unroll
            for (int j = 0; j < 8; ++j) {
                int n = n0 + warp_n * 64 + j * 8 + tc2;
                float vx = acc[i][j][half * 2 + 0];
                float vy = acc[i][j][half * 2 + 1];
                if (bias) { vx += bias[n]; vy += bias[n + 1]; }
                if (n >= gelu_n0) {
                    vx = gelu_f(vx); vy = gelu_f(vy);
                    int cc = HIDDEN + n - gelu_n0;
                    *reinterpret_cast<uint32_t*>(Gh + (size_t)m * CCW + cc) =
                        pack2h(vx, vy);
                } else {
                    *reinterpret_cast<float2*>(C + (size_t)m * ldc + n) =
                        make_float2(vx, vy);
                }
            }
        }
    }
}

// ================= flash attention for block 1 =============================
#define BK 64
#define FSTR 272                       // 128*2 + 16 pad
#define FQ_PLANE (128 * FSTR)          // 34816
#define FK_PLANE (BK * FSTR)           // 17408
#define FS_OFF   FQ_PLANE              // 34816
#define FSTAGE   (2 * FK_PLANE)        // 34816 (K + V)
#define FNS      3
#define FLASH_SMEM (FS_OFF + FNS * FSTAGE)  // 139264
#define NKT (LX / BK)                  // 68

__global__ void __launch_bounds__(256, 1) flash1(
    const f16* __restrict__ Qh,
    const f16* __restrict__ Kh, const f16* __restrict__ Vh,
    f16* __restrict__ Och)
{
    extern __shared__ char smem[];
    uint32_t sbase = smem_u32(smem);
    int tid = threadIdx.x, wid = tid >> 5, lane = tid & 31;
    int head = blockIdx.y;
    int q0 = blockIdx.x * 128;
    size_t hb = (size_t)head * LX * HDIM;
    const f16* qp0 = Qh + hb + (size_t)q0 * HDIM;
    const f16* kp[2] = { Kh + hb, Vh + hb };

    #pragma unroll
    for (int u8 = 0; u8 < 8; ++u8) {
        int u = tid + 256 * u8;
        int r = (u >> 4) & 127, c = u & 15;
        cp_async16(sbase + (uint32_t)(r * FSTR + c * 16),
                   qp0 + (size_t)r * HDIM + c * 8, 16);
    }
    cp_commit();

    auto issueKV = [&](int it) {
        if (it < NKT) {
            int kv0 = it * BK;
            #pragma unroll
            for (int u8 = 0; u8 < 8; ++u8) {
                int u = tid + 256 * u8;
                int pl = u >> 10, r = (u >> 4) & 63, c = u & 15;
                cp_async16(sbase + (uint32_t)(FS_OFF + (it % FNS) * FSTAGE +
                                              pl * FK_PLANE + r * FSTR + c * 16),
                           kp[pl] + (size_t)(kv0 + r) * HDIM + c * 8, 16);
            }
        }
        cp_commit();
    };
    issueKV(0);
    issueKV(1);

    uint32_t a_addr = sbase + (uint32_t)((wid * 16 + (lane & 15)) * FSTR +
                                         (lane >> 4) * 16);
    uint32_t bk_rel = (uint32_t)((lane & 15) * FSTR + (lane >> 4) * 16);
    uint32_t bv_rel = (uint32_t)(((((lane >> 3) & 1) * 8) + (lane & 7)) * FSTR +
                                 ((lane >> 4) & 1) * 16);

    float accO[16][4];
    #pragma unroll
    for (int j = 0; j < 16; ++j)
        #pragma unroll
        for (int t = 0; t < 4; ++t) accO[j][t] = 0.f;
    float mrow0 = -1e30f, mrow1 = -1e30f, lsum0 = 0.f, lsum1 = 0.f;
    const float scl = 0.08838834764831845f;

    for (int it = 0; it < NKT; ++it) {
        cp_wait1();
        __syncthreads();
        issueKV(it + 2);
        uint32_t kb = sbase + FS_OFF + (uint32_t)(it % FNS) * FSTAGE;

        float s[8][4];
        #pragma unroll
        for (int j = 0; j < 8; ++j)
            #pragma unroll
            for (int t = 0; t < 4; ++t) s[j][t] = 0.f;
        #pragma unroll
        for (int ks = 0; ks < 8; ++ks) {
            uint32_t aqh[4];
            ldsm4(aqh, a_addr + ks * 32);
            uint32_t bh[4][4];
            #pragma unroll
            for (int g = 0; g < 4; ++g)
                ldsm4(bh[g], kb + bk_rel + g * (16 * FSTR) + ks * 32);
            #pragma unroll
            for (int j = 0; j < 8; ++j)
                mma_f16(s[j], aqh, bh[j >> 1][j & 1], bh[j >> 1][(j & 1) + 2]);
        }

        float m0 = -1e30f, m1 = -1e30f;
        #pragma unroll
        for (int j = 0; j < 8; ++j) {
            s[j][0] *= scl; s[j][1] *= scl; s[j][2] *= scl; s[j][3] *= scl;
            m0 = fmaxf(m0, fmaxf(s[j][0], s[j][1]));
            m1 = fmaxf(m1, fmaxf(s[j][2], s[j][3]));
        }
        m0 = fmaxf(m0, __shfl_xor_sync(0xffffffffu, m0, 1));
        m0 = fmaxf(m0, __shfl_xor_sync(0xffffffffu, m0, 2));
        m1 = fmaxf(m1, __shfl_xor_sync(0xffffffffu, m1, 1));
        m1 = fmaxf(m1, __shfl_xor_sync(0xffffffffu, m1, 2));
        float mn0 = fmaxf(mrow0, m0), mn1 = fmaxf(mrow1, m1);
        float al0 = __expf(mrow0 - mn0), al1 = __expf(mrow1 - mn1);
        mrow0 = mn0; mrow1 = mn1;

        uint32_t ph[8][2];
        float ps0 = 0.f, ps1 = 0.f;
        #pragma unroll
        for (int j = 0; j < 8; ++j) {
            float p00 = __expf(s[j][0] - mn0), p01 = __expf(s[j][1] - mn0);
            float p10 = __expf(s[j][2] - mn1), p11 = __expf(s[j][3] - mn1);
            ps0 += p00 + p01; ps1 += p10 + p11;
            ph[j][0] = pack2h(p00, p01);
            ph[j][1] = pack2h(p10, p11);
        }
        lsum0 = lsum0 * al0 + ps0;
        lsum1 = lsum1 * al1 + ps1;
        #pragma unroll
        for (int j = 0; j < 16; ++j) {
            accO[j][0] *= al0; accO[j][1] *= al0;
            accO[j][2] *= al1; accO[j][3] *= al1;
        }

        uint32_t vb = kb + FK_PLANE;
        #pragma unroll
        for (int s4 = 0; s4 < 4; ++s4) {
            uint32_t Ahf[4] = { ph[2 * s4][0], ph[2 * s4][1],
                                ph[2 * s4 + 1][0], ph[2 * s4 + 1][1] };
            #pragma unroll
            for (int g = 0; g < 8; ++g) {
                uint32_t bvh[4];
                ldsm4t(bvh, vb + bv_rel + s4 * (16 * FSTR) + g * 32);
                mma_f16(accO[2 * g],     Ahf, bvh[0], bvh[1]);
                mma_f16(accO[2 * g + 1], Ahf, bvh[2], bvh[3]);
            }
        }
    }

    lsum0 += __shfl_xor_sync(0xffffffffu, lsum0, 1);
    lsum0 += __shfl_xor_sync(0xffffffffu, lsum0, 2);
    lsum1 += __shfl_xor_sync(0xffffffffu, lsum1, 1);
    lsum1 += __shfl_xor_sync(0xffffffffu, lsum1, 2);
    float inv0 = 1.f / lsum0, inv1 = 1.f / lsum1;
    int r0 = q0 + wid * 16 + (lane >> 2);
    int cbase = head * HDIM + (lane & 3) * 2;
    #pragma unroll
    for (int j = 0; j < 16; ++j) {
        int c = cbase + j * 8;
        *reinterpret_cast<uint32_t*>(Och + (size_t)r0 * CCW + c) =
            pack2h(accO[j][0] * inv0, accO[j][1] * inv0);
        *reinterpret_cast<uint32_t*>(Och + (size_t)(r0 + 8) * CCW + c) =
            pack2h(accO[j][2] * inv1, accO[j][3] * inv1);
    }
}

// ---------------- SIMT GEMM (block-2 QK^T only) ----------------------------
__global__ void __launch_bounds__(256) sgemm_abt(
    const float* __restrict__ A, int lda, long long sA,
    const float* __restrict__ B, int ldb, long long sB,
    float* __restrict__ C, int ldc, long long sC,
    int M, int N, int K, float alpha)
{
    __shared__ float As[8][128];
    __shared__ float Bs[8][128];
    int bz = blockIdx.z;
    A += (size_t)sA * bz;
    B += (size_t)sB * bz;
    C += (size_t)sC * bz;
    int m0 = blockIdx.y * 128;
    int n0 = blockIdx.x * 128;
    int tid = threadIdx.x;
    int tx = tid & 15, ty = tid >> 4;
    int lrow = tid >> 1;
    int lcol = (tid & 1) * 4;

    float acc[8][8];
    #pragma unroll
    for (int i = 0; i < 8; i++)
        #pragma unroll
        for (int j = 0; j < 8; j++) acc[i][j] = 0.f;

    for (int k0 = 0; k0 < K; k0 += 8) {
        float4 av = make_float4(0.f, 0.f, 0.f, 0.f);
        float4 bv = make_float4(0.f, 0.f, 0.f, 0.f);
        if (m0 + lrow < M && k0 + lcol < K)
            av = *reinterpret_cast<const float4*>(A + (size_t)(m0 + lrow) * lda + k0 + lcol);
        if (n0 + lrow < N && k0 + lcol < K)
            bv = *reinterpret_cast<const float4*>(B + (size_t)(n0 + lrow) * ldb + k0 + lcol);
        As[lcol + 0][lrow] = av.x; As[lcol + 1][lrow] = av.y;
        As[lcol + 2][lrow] = av.z; As[lcol + 3][lrow] = av.w;
        Bs[lcol + 0][lrow] = bv.x; Bs[lcol + 1][lrow] = bv.y;
        Bs[lcol + 2][lrow] = bv.z; Bs[lcol + 3][lrow] = bv.w;
        __syncthreads();
        #pragma unroll
        for (int k = 0; k < 8; k++) {
            float ra[8], rb[8];
            #pragma unroll
            for (int i = 0; i < 8; i++) ra[i] = As[k][ty + 16 * i];
            #pragma unroll
            for (int j = 0; j < 8; j++) rb[j] = Bs[k][tx + 16 * j];
            #pragma unroll
            for (int i = 0; i < 8; i++)
                #pragma unroll
                for (int j = 0; j < 8; j++)
                    acc[i][j] = fmaf(ra[i], rb[j], acc[i][j]);
        }
        __syncthreads();
    }

    #pragma unroll
    for (int i = 0; i < 8; i++) {
        int m = m0 + ty + 16 * i;
        if (m >= M) continue;
        #pragma unroll
        for (int j = 0; j < 8; j++) {
            int n = n0 + tx + 16 * j;
            if (n >= N) continue;
            C[(size_t)m * ldc + n] = alpha * acc[i][j];
        }
    }
}

// ---------------- block-2 PV: split-K rank-1 updates -----------------------
#define KSPLIT 16
__global__ void __launch_bounds__(256) zero_o2()
{
    int idx = blockIdx.x * 256 + threadIdx.x;
    if (idx < NHEADS * NC * HDIM) g_o2[idx] = 0.f;
}
__global__ void __launch_bounds__(256) pv2_kernel()
{
    int h = blockIdx.y, ks = blockIdx.x;
    int chunk = (LC + KSPLIT - 1) / KSPLIT;
    int k0 = ks * chunk, k1 = min(LC, k0 + chunk);
    int d = threadIdx.x & 127, g = threadIdx.x >> 7;
    const float* S = g_s2 + (size_t)h * NC * LC;
    const float* V = g_v2 + (size_t)h * LC * HDIM;
    float acc[10];
    #pragma unroll
    for (int i = 0; i < 10; ++i) acc[i] = 0.f;
    for (int k = k0; k < k1; ++k) {
        float v = V[(size_t)k * HDIM + d];
        #pragma unroll
        for (int i = 0; i < 10; ++i)
            acc[i] = fmaf(__ldg(S + (size_t)(g * 10 + i) * LC + k), v, acc[i]);
    }
    #pragma unroll
    for (int i = 0; i < 10; ++i)
        atomicAdd(&g_o2[((size_t)h * NC + g * 10 + i) * HDIM + d], acc[i]);
}
__global__ void __launch_bounds__(256) o2_to_cc()
{
    int idx = blockIdx.x * 256 + threadIdx.x;
    if (idx >= NHEADS * NC * HDIM) return;
    int d = idx & 127;
    int i = (idx >> 7) % NC;
    int h = idx / (NC * HDIM);
    g_cch[(size_t)(LX + i) * CCW + h * HDIM + d] = __float2half_rn(g_o2[idx]);
}

// ---------------- convert fp32 -> fp16 -------------------------------------
__global__ void __launch_bounds__(256) convert_h(
    const float4* __restrict__ src, uint2* __restrict__ h, int n4)
{
    int idx = blockIdx.x * 256 + threadIdx.x;
    if (idx >= n4) return;
    float4 v = src[idx];
    uint2 r;
    r.x = pack2h(v.x, v.y);
    r.y = pack2h(v.z, v.w);
    h[idx] = r;
}

// ---------------- modulation: m = silu(vec) @ mod_w^T + mod_b --------------
// 8 warps/block, warp per output row, silu(vec) cached in smem.
__global__ void __launch_bounds__(256) mod_kernel(
    const float* __restrict__ vec, const float* __restrict__ mod_w,
    const float* __restrict__ mod_b)
{
    __shared__ float sv[HIDDEN];
    for (int i = threadIdx.x; i < HIDDEN; i += 256) {
        float xv = vec[i];
        sv[i] = xv / (1.f + __expf(-xv));
    }
    __syncthreads();
    int n = blockIdx.x * 8 + (threadIdx.x >> 5);
    int lane = threadIdx.x & 31;
    const float4* w4 = reinterpret_cast<const float4*>(mod_w + (size_t)n * HIDDEN);
    float acc = 0.f;
    #pragma unroll
    for (int i = 0; i < 12; ++i) {
        float4 w = w4[lane + 32 * i];
        int k = (lane + 32 * i) * 4;
        acc += w.x * sv[k] + w.y * sv[k + 1] + w.z * sv[k + 2] + w.w * sv[k + 3];
    }
    acc = warp_sum(acc);
    if (lane == 0) g_mod[n] = acc + mod_b[n];
}

// ---------------- layernorm + modulate -> fp16 (float4) ---------------------
__global__ void __launch_bounds__(128) ln_mod_kernel(
    const float* __restrict__ x, const float* __restrict__ concepts)
{
    __shared__ float sbuf[4];
    int row = blockIdx.x;
    const float4* src = (row < LX)
        ? reinterpret_cast<const float4*>(x + (size_t)row * HIDDEN)
        : reinterpret_cast<const float4*>(concepts + (size_t)(row - LX) * HIDDEN);
    int tid = threadIdx.x;
    float4 v[3];
    float s = 0.f;
    #pragma unroll
    for (int i = 0; i < 3; i++) {
        v[i] = src[tid + 128 * i];
        s += v[i].x + v[i].y + v[i].z + v[i].w;
    }
    s = block_sum<128>(s, sbuf);
    float mu = s * (1.0f / 1536.0f);
    float s2 = 0.f;
    #pragma unroll
    for (int i = 0; i < 3; i++) {
        float dx = v[i].x - mu, dy = v[i].y - mu, dz = v[i].z - mu, dw = v[i].w - mu;
        s2 = fmaf(dx, dx, s2); s2 = fmaf(dy, dy, s2);
        s2 = fmaf(dz, dz, s2); s2 = fmaf(dw, dw, s2);
    }
    s2 = block_sum<128>(s2, sbuf);
    float rstd = rsqrtf(s2 * (1.0f / 1536.0f) + 1e-6f);
    #pragma unroll
    for (int i = 0; i < 3; i++) {
        int j4 = tid + 128 * i;
        float4 sc = *reinterpret_cast<const float4*>(g_mod + HIDDEN + j4 * 4);
        float4 sh = *reinterpret_cast<const float4*>(g_mod + j4 * 4);
        float ox = (1.f + sc.x) * ((v[i].x - mu) * rstd) + sh.x;
        float oy = (1.f + sc.y) * ((v[i].y - mu) * rstd) + sh.y;
        float oz = (1.f + sc.z) * ((v[i].z - mu) * rstd) + sh.z;
        float ow = (1.f + sc.w) * ((v[i].w - mu) * rstd) + sh.w;
        uint2 r;
        r.x = pack2h(ox, oy);
        r.y = pack2h(oz, ow);
        *reinterpret_cast<uint2*>(g_xmh + (size_t)row * HIDDEN + j4 * 4) = r;
    }
}

// ---------------- attention prep (warp per token-head, float4) -------------
// pe/cpe layout: [tok][64][2][2] fp32.  d = lane*4 + {0..3}; pair indices
// i0 = lane*2, i1 = lane*2+1 are intra-thread.
__device__ __forceinline__ float4 rope4(float4 t, const float* __restrict__ pe,
                                        int tok, int lane)
{
    float4 p0 = *reinterpret_cast<const float4*>(pe + ((size_t)tok * 64 + lane * 2) * 4);
    float4 p1 = *reinterpret_cast<const float4*>(pe + ((size_t)tok * 64 + lane * 2 + 1) * 4);
    float4 r;
    r.x = p0.x * t.x + p0.y * t.y;
    r.y = p0.z * t.x + p0.w * t.y;
    r.z = p1.x * t.z + p1.y * t.w;
    r.w = p1.z * t.z + p1.w * t.w;
    return r;
}

__global__ void __launch_bounds__(384) attn_prep1(
    const float* __restrict__ pe, const float* __restrict__ cpe,
    const float* __restrict__ q_scale, const float* __restrict__ k_scale)
{
    int t = blockIdx.x;
    int h = threadIdx.x >> 5, lane = threadIdx.x & 31;
    const float* hrow = g_h + (size_t)t * QKVW;
    float4 q = *reinterpret_cast<const float4*>(hrow + h * HDIM + lane * 4);
    float4 k = *reinterpret_cast<const float4*>(hrow + HIDDEN + h * HDIM + lane * 4);
    float4 v = *reinterpret_cast<const float4*>(hrow + 2 * HIDDEN + h * HDIM + lane * 4);
    float sq = q.x * q.x + q.y * q.y + q.z * q.z + q.w * q.w;
    float sk = k.x * k.x + k.y * k.y + k.z * k.z + k.w * k.w;
    sq = warp_sum(sq); sk = warp_sum(sk);
    float rq = rsqrtf(sq * (1.f / 128.f) + 1e-6f);
    float rk = rsqrtf(sk * (1.f / 128.f) + 1e-6f);
    float4 qs = *reinterpret_cast<const float4*>(q_scale + lane * 4);
    float4 ks = *reinterpret_cast<const float4*>(k_scale + lane * 4);
    float4 qn = make_float4(q.x * rq * qs.x, q.y * rq * qs.y,
                            q.z * rq * qs.z, q.w * rq * qs.w);
    float4 kn = make_float4(k.x * rk * ks.x, k.y * rk * ks.y,
                            k.z * rk * ks.z, k.w * rk * ks.w);
    float4 qr = rope4(qn, pe, t, lane);
    float4 kr = rope4(kn, pe, t, lane);
    size_t qi = ((size_t)h * LX + t) * HDIM + lane * 4;
    uint2 r;
    r.x = pack2h(qr.x, qr.y); r.y = pack2h(qr.z, qr.w);
    *reinterpret_cast<uint2*>(g_q1h + qi) = r;
    r.x = pack2h(kr.x, kr.y); r.y = pack2h(kr.z, kr.w);
    *reinterpret_cast<uint2*>(g_k1h + qi) = r;
    r.x = pack2h(v.x, v.y); r.y = pack2h(v.z, v.w);
    *reinterpret_cast<uint2*>(g_v1h + qi) = r;
    if (t >= TXT) {
        int j = NC + (t - TXT);
        float4 kc = rope4(kn, cpe, j, lane);
        size_t ki = ((size_t)h * LC + j) * HDIM + lane * 4;
        *reinterpret_cast<float4*>(g_k2 + ki) = kc;
        *reinterpret_cast<float4*>(g_v2 + ki) = v;
    }
}

__global__ void __launch_bounds__(384) attn_prep2(
    const float* __restrict__ cpe,
    const float* __restrict__ q_scale, const float* __restrict__ k_scale)
{
    int i = blockIdx.x;
    int h = threadIdx.x >> 5, lane = threadIdx.x & 31;
    const float* hrow = g_h + (size_t)(LX + i) * QKVW;
    float4 q = *reinterpret_cast<const float4*>(hrow + h * HDIM + lane * 4);
    float4 k = *reinterpret_cast<const float4*>(hrow + HIDDEN + h * HDIM + lane * 4);
    float4 v = *reinterpret_cast<const float4*>(hrow + 2 * HIDDEN + h * HDIM + lane * 4);
    float sq = q.x * q.x + q.y * q.y + q.z * q.z + q.w * q.w;
    float sk = k.x * k.x + k.y * k.y + k.z * k.z + k.w * k.w;
    sq = warp_sum(sq); sk = warp_sum(sk);
    float rq = rsqrtf(sq * (1.f / 128.f) + 1e-6f);
    float rk = rsqrtf(sk * (1.f / 128.f) + 1e-6f);
    float4 qs = *reinterpret_cast<const float4*>(q_scale + lane * 4);
    float4 ks = *reinterpret_cast<const float4*>(k_scale + lane * 4);
    float4 qn = make_float4(q.x * rq * qs.x, q.y * rq * qs.y,
                            q.z * rq * qs.z, q.w * rq * qs.w);
    float4 kn = make_float4(k.x * rk * ks.x, k.y * rk * ks.y,
                            k.z * rk * ks.z, k.w * rk * ks.w);
    float4 qr = rope4(qn, cpe, i, lane);
    float4 kr = rope4(kn, cpe, i, lane);
    *reinterpret_cast<float4*>(g_q2 + ((size_t)h * NC + i) * HDIM + lane * 4) = qr;
    size_t ki = ((size_t)h * LC + i) * HDIM + lane * 4;
    *reinterpret_cast<float4*>(g_k2 + ki) = kr;
    *reinterpret_cast<float4*>(g_v2 + ki) = v;
}

// ---------------- row softmax (block-2 path) -------------------------------
__global__ void __launch_bounds__(256) softmax_rows(float* __restrict__ S, int ncol)
{
    __shared__ float sbuf[8];
    float* row = S + (size_t)blockIdx.x * ncol;
    int tid = threadIdx.x;
    float v[17];
    float mx = -1e30f;
    #pragma unroll
    for (int i = 0; i < 17; i++) {
        int c = tid + 256 * i;
        v[i] = (c < ncol) ? row[c] : -1e30f;
        mx = fmaxf(mx, v[i]);
    }
    mx = block_max<256>(mx, sbuf);
    float s = 0.f;
    #pragma unroll
    for (int i = 0; i < 17; i++) { v[i] = __expf(v[i] - mx); s += v[i]; }
    s = block_sum<256>(s, sbuf);
    float inv = 1.f / s;
    #pragma unroll
    for (int i = 0; i < 17; i++) {
        int c = tid + 256 * i;
        if (c < ncol) row[c] = v[i] * inv;
    }
}

// ---------------- residual: out = base + gate * block_out (float4) ---------
__global__ void __launch_bounds__(256) final_kernel(
    const float* __restrict__ x, const float* __restrict__ concepts,
    float* __restrict__ out)
{
    int idx = blockIdx.x * 256 + threadIdx.x;      // float4 index
    if (idx >= NROWS * (HIDDEN / 4)) return;
    int c4 = idx % (HIDDEN / 4);
    int r = idx / (HIDDEN / 4);
    float4 base = (r < LX)
        ? reinterpret_cast<const float4*>(x)[idx]
        : reinterpret_cast<const float4*>(concepts)[idx - LX * (HIDDEN / 4)];
    float4 g = *reinterpret_cast<const float4*>(g_mod + 2 * HIDDEN + c4 * 4);
    float4 o = reinterpret_cast<const float4*>(g_out)[idx];
    float4 rv;
    rv.x = fmaf(g.x, o.x, base.x);
    rv.y = fmaf(g.y, o.y, base.y);
    rv.z = fmaf(g.z, o.z, base.z);
    rv.w = fmaf(g.w, o.w, base.w);
    reinterpret_cast<float4*>(out)[idx] = rv;
}

// ---------------------------------------------------------------------------
extern "C" void kernel_launch(void* const* d_in, const int* in_sizes, int n_in,
                              void* d_out, int out_size)
{
    const float* x        = (const float*)d_in[0];
    const float* concepts = (const float*)d_in[1];
    const float* vec      = (const float*)d_in[2];
    const float* pe       = (const float*)d_in[3];
    const float* cpe      = (const float*)d_in[4];
    const float* w1       = (const float*)d_in[5];
    const float* b1       = (const float*)d_in[6];
    const float* w2       = (const float*)d_in[7];
    const float* b2       = (const float*)d_in[8];
    const float* q_scale  = (const float*)d_in[9];
    const float* k_scale  = (const float*)d_in[10];
    const float* mod_w    = (const float*)d_in[11];
    const float* mod_b    = (const float*)d_in[12];
    float* out = (float*)d_out;

    void* p;
    cudaGetSymbolAddress(&p, g_xmh);  f16* xmh = (f16*)p;
    cudaGetSymbolAddress(&p, g_w1h);  f16* w1h = (f16*)p;
    cudaGetSymbolAddress(&p, g_w2h);  f16* w2h = (f16*)p;
    cudaGetSymbolAddress(&p, g_h);    float* hbuf = (float*)p;
    cudaGetSymbolAddress(&p, g_q1h);  f16* q1h = (f16*)p;
    cudaGetSymbolAddress(&p, g_k1h);  f16* k1h = (f16*)p;
    cudaGetSymbolAddress(&p, g_v1h);  f16* v1h = (f16*)p;
    cudaGetSymbolAddress(&p, g_q2);   float* q2b  = (float*)p;
    cudaGetSymbolAddress(&p, g_k2);   float* k2b  = (float*)p;
    cudaGetSymbolAddress(&p, g_s2);   float* s2b  = (float*)p;
    cudaGetSymbolAddress(&p, g_cch);  f16* cch = (f16*)p;
    cudaGetSymbolAddress(&p, g_out);  float* outb = (float*)p;

    static cudaStream_t s1 = nullptr;
    static cudaEvent_t evFork = nullptr, evW1 = nullptr, evLN = nullptr,
                       evPrep = nullptr, evSide = nullptr;
    if (s1 == nullptr) {
        cudaStreamCreateWithFlags(&s1, cudaStreamNonBlocking);
        cudaEventCreateWithFlags(&evFork, cudaEventDisableTiming);
        cudaEventCreateWithFlags(&evW1, cudaEventDisableTiming);
        cudaEventCreateWithFlags(&evLN, cudaEventDisableTiming);
        cudaEventCreateWithFlags(&evPrep, cudaEventDisableTiming);
        cudaEventCreateWithFlags(&evSide, cudaEventDisableTiming);
        cudaFuncSetAttribute(gemm_f16,
                             cudaFuncAttributeMaxDynamicSharedMemorySize, HG_SMEM);
        cudaFuncSetAttribute(flash1,
                             cudaFuncAttributeMaxDynamicSharedMemorySize, FLASH_SMEM);
    }

    const float scl = 0.08838834764831845f;  // 1/sqrt(128)

    // fork: side stream converts weights
    cudaEventRecord(evFork, 0);
    cudaStreamWaitEvent(s1, evFork, 0);
    {
        int n4 = (W1OUT * HIDDEN) / 4;
        convert_h<<<(n4 + 255) / 256, 256, 0, s1>>>(
            (const float4*)w1, (uint2*)w1h, n4);
    }
    cudaEventRecord(evW1, s1);
    {
        int n4 = (HIDDEN * CCW) / 4;
        convert_h<<<(n4 + 255) / 256, 256, 0, s1>>>(
            (const float4*)w2, (uint2*)w2h, n4);
        zero_o2<<<(NHEADS * NC * HDIM + 255) / 256, 256, 0, s1>>>();
    }

    // main: modulation + layernorm
    mod_kernel<<<(3 * HIDDEN) / 8, 256>>>(vec, mod_w, mod_b);
    ln_mod_kernel<<<NROWS, 128>>>(x, concepts);
    cudaEventRecord(evLN, 0);

    // join w1, then qkv half of GEMM1 on main
    cudaStreamWaitEvent(0, evW1, 0);
    gemm_f16<<<dim3(QKVW / 128, (NROWS + 127) / 128), 256, HG_SMEM>>>(
        xmh, HIDDEN, w1h, HIDDEN,
        hbuf, QKVW, nullptr, QKVW,      // gelu_n0 = QKVW -> all cols fp32 C
        NROWS, QKVW, HIDDEN, b1);

    // side: mlp half of GEMM1 (needs ln + w1h; overlaps prep + flash)
    cudaStreamWaitEvent(s1, evLN, 0);
    gemm_f16<<<dim3(MLPH / 128, (NROWS + 127) / 128), 256, HG_SMEM, s1>>>(
        xmh, HIDDEN, w1h + (size_t)QKVW * HIDDEN, HIDDEN,
        nullptr, 0, cch, 0,             // gelu_n0 = 0 -> all cols gelu -> cc
        NROWS, MLPH, HIDDEN, b1 + QKVW);

    // main: prep (warp-per-row) then flash
    attn_prep1<<<LX, 384>>>(pe, cpe, q_scale, k_scale);
    attn_prep2<<<NC, 384>>>(cpe, q_scale, k_scale);
    cudaEventRecord(evPrep, 0);

    // side: block-2 chain after its GEMM1_mlp + prep
    cudaStreamWaitEvent(s1, evPrep, 0);
    sgemm_abt<<<dim3((LC + 127) / 128, 1, NHEADS), 256, 0, s1>>>(
        q2b, HDIM, (long long)NC * HDIM, k2b, HDIM, (long long)LC * HDIM,
        s2b, LC, (long long)NC * LC, NC, LC, HDIM, scl);
    softmax_rows<<<NHEADS * NC, 256, 0, s1>>>(s2b, LC);
    pv2_kernel<<<dim3(KSPLIT, NHEADS), 256, 0, s1>>>();
    o2_to_cc<<<(NHEADS * NC * HDIM + 255) / 256, 256, 0, s1>>>();
    cudaEventRecord(evSide, s1);

    // main: flash attention
    flash1<<<dim3(LX / 128, NHEADS), 256, FLASH_SMEM>>>(q1h, k1h, v1h, cch);

    // join side (covers GEMM1_mlp, w2 conversion, block-2) before GEMM2
    cudaStreamWaitEvent(0, evSide, 0);
    gemm_f16<<<dim3(HIDDEN / 128, (NROWS + 127) / 128), 256, HG_SMEM>>>(
        cch, CCW, w2h, CCW,
        outb, HIDDEN, nullptr, HIDDEN,
        NROWS, HIDDEN, CCW, b2);
    final_kernel<<<(NROWS * (HIDDEN / 4) + 255) / 256, 256>>>(x, concepts, out);
}